// round 10
// baseline (speedup 1.0000x reference)
#include <cuda_runtime.h>
#include <cuda_bf16.h>

#define BB   8
#define SS   2048
#define KIN  512
#define NIN  2048
#define NP   4096
#define HID  4096
#define DM   1024
#define KSEL 256
#define NC   512     // refine candidate count (int8 approx needs the wide margin)
#define NCP  512

typedef unsigned long long ull;
typedef unsigned int u32;

// ---------------- scratch ----------------
__device__ __align__(256) __nv_bfloat16 g_Asp[(size_t)BB * 2 * SS * KIN];
__device__ __align__(256) signed char   g_Ai8[(size_t)BB * SS * KIN];   // 8 MB
__device__ __align__(256) signed char   g_Bi8[(size_t)BB * NP * KIN];   // 16 MB
__device__ float g_sA[BB * SS];
__device__ float g_sB[BB * NP];
__device__ __align__(256) __nv_bfloat16 g_Bc [(size_t)BB * 2 * NC * KIN];
__device__ __align__(256) __nv_bfloat16 g_PC [(size_t)BB * 2 * SS * NC];
__device__ __align__(256) __nv_bfloat16 g_PA [(size_t)BB * 2 * SS * KSEL];
__device__ __align__(256) __nv_bfloat16 g_Pr [(size_t)BB * 2 * DM * KSEL];
__device__ float    g_mask[BB * NIN];
__device__ float    g_h[BB * HID];
__device__ float    g_sig[BB * NP];
__device__ unsigned g_scoreEnc[BB * NP];
__device__ unsigned g_scoreEnc2[BB * NC];
__device__ int      g_pidx512[BB * NC];
__device__ int      g_pidx[BB * KSEL];
__device__ int      g_cmap[BB * KSEL];

// ---------------- helpers ----------------
__device__ __forceinline__ unsigned fenc(float f) {
    unsigned u = __float_as_uint(f);
    return (u & 0x80000000u) ? ~u : (u | 0x80000000u);
}
__device__ __forceinline__ float fdec(unsigned u) {
    return __uint_as_float((u & 0x80000000u) ? (u & 0x7fffffffu) : ~u);
}
__device__ __forceinline__ float gelu_f(float x) {
    return 0.5f * x * (1.0f + erff(x * 0.70710678118654752f));
}
__device__ __forceinline__ u32 smem_u32(const void* p) {
    u32 a; asm("{ .reg .u64 t; cvta.to.shared.u64 t, %1; cvt.u32.u64 %0, t; }" : "=r"(a) : "l"(p));
    return a;
}
__device__ __forceinline__ void split2(float a, __nv_bfloat16& h, __nv_bfloat16& m) {
    h = __float2bfloat16(a);
    m = __float2bfloat16(a - __bfloat162float(h));
}

// ---------------- mma.sync / ldmatrix / cp.async ----------------
__device__ __forceinline__ void mma16816(float* d, const u32* a, u32 b0, u32 b1) {
    asm volatile("mma.sync.aligned.m16n8k16.row.col.f32.bf16.bf16.f32 "
        "{%0,%1,%2,%3}, {%4,%5,%6,%7}, {%8,%9}, {%0,%1,%2,%3};"
        : "+f"(d[0]), "+f"(d[1]), "+f"(d[2]), "+f"(d[3])
        : "r"(a[0]), "r"(a[1]), "r"(a[2]), "r"(a[3]), "r"(b0), "r"(b1));
}
__device__ __forceinline__ void mma16832s8(int* d, const u32* a, u32 b0, u32 b1) {
    asm volatile("mma.sync.aligned.m16n8k32.row.col.s32.s8.s8.s32 "
        "{%0,%1,%2,%3}, {%4,%5,%6,%7}, {%8,%9}, {%0,%1,%2,%3};"
        : "+r"(d[0]), "+r"(d[1]), "+r"(d[2]), "+r"(d[3])
        : "r"(a[0]), "r"(a[1]), "r"(a[2]), "r"(a[3]), "r"(b0), "r"(b1));
}
__device__ __forceinline__ void ldsm4(u32* r, u32 addr) {
    asm volatile("ldmatrix.sync.aligned.m8n8.x4.shared.b16 {%0,%1,%2,%3}, [%4];"
        : "=r"(r[0]), "=r"(r[1]), "=r"(r[2]), "=r"(r[3]) : "r"(addr));
}
__device__ __forceinline__ void cpasync16(u32 dst, const void* src) {
    asm volatile("cp.async.cg.shared.global [%0], [%1], 16;" :: "r"(dst), "l"(src));
}
#define CP_COMMIT() asm volatile("cp.async.commit_group;" ::: "memory")
#define CP_WAIT(n)  asm volatile("cp.async.wait_group %0;" :: "n"(n) : "memory")

#define RPAD   80
#define PLANE  (128 * RPAD)          // 10240
#define STGB4  (4 * PLANE)           // refine/gemm3t stage: 40960
#define GSMEM4 (2 * STGB4)           // 81920 -> 2 CTAs/SM
#define STG1   (2 * PLANE)           // gemm1q stage (A-i8 + B-i8): 20480
#define GSMEM1 (2 * STG1)            // 40960 -> 2 CTAs/SM

// ---------------- init kernels ----------------
__global__ void k_initMask() {
    int t = blockIdx.x * blockDim.x + threadIdx.x;
    if (t < BB * NIN) g_mask[t] = 0.0f;
}
__global__ void k_initScore() {
    int t = blockIdx.x * blockDim.x + threadIdx.x;
    if (t < BB * NP)  g_scoreEnc[t] = 0u;
    if (t < BB * NC)  g_scoreEnc2[t] = 0u;
}
__global__ void k_scatter(const int* __restrict__ sidx) {
    int t = blockIdx.x * blockDim.x + threadIdx.x;
    if (t < BB * KIN) {
        int b = t >> 9;
        g_mask[b * NIN + sidx[t]] = 1.0f;
    }
}

// ---------------- split A planes (bf16, for refine) ----------------
union B4U { __nv_bfloat16 h[4]; ull u; };
union B2U { __nv_bfloat16 h[2]; u32 u; };

__global__ void k_splitAh(const float* __restrict__ act) {
    size_t t = (size_t)blockIdx.x * 256 + threadIdx.x;
    size_t bs = t >> 7;
    int k4 = (int)(t & 127);
    int b = (int)(bs >> 11), s = (int)(bs & 2047);
    float4 v = ((const float4*)act)[t];
    float vv[4] = { v.x, v.y, v.z, v.w };
    B4U hh;
#pragma unroll
    for (int i = 0; i < 4; i++) hh.h[i] = __float2bfloat16(vv[i]);
    *(ull*)(g_Asp + ((size_t)(b * 2) * SS + s) * KIN + k4 * 4) = hh.u;
}

__global__ void k_splitAm(const float* __restrict__ act) {
    size_t t = (size_t)blockIdx.x * 256 + threadIdx.x;
    size_t bs = t >> 7;
    int k4 = (int)(t & 127);
    int b = (int)(bs >> 11), s = (int)(bs & 2047);
    float4 v = ((const float4*)act)[t];
    float vv[4] = { v.x, v.y, v.z, v.w };
    B4U mm;
#pragma unroll
    for (int i = 0; i < 4; i++) {
        __nv_bfloat16 h = __float2bfloat16(vv[i]);
        mm.h[i] = __float2bfloat16(vv[i] - __bfloat162float(h));
    }
    *(ull*)(g_Asp + ((size_t)(b * 2 + 1) * SS + s) * KIN + k4 * 4) = mm.u;
}

// ---------------- quantize A rows to int8 (warp per row) ----------------
__global__ void k_quantA(const float* __restrict__ act) {
    int warp = threadIdx.x >> 5, lane = threadIdx.x & 31;
    int rowid = blockIdx.x * 8 + warp;               // over BB*SS
    const float4* a = (const float4*)(act + (size_t)rowid * KIN + lane * 16);
    float4 v[4];
    float mx = 0.0f;
#pragma unroll
    for (int i = 0; i < 4; i++) {
        v[i] = a[i];
        mx = fmaxf(mx, fmaxf(fmaxf(fabsf(v[i].x), fabsf(v[i].y)),
                             fmaxf(fabsf(v[i].z), fabsf(v[i].w))));
    }
#pragma unroll
    for (int o = 16; o > 0; o >>= 1) mx = fmaxf(mx, __shfl_xor_sync(0xffffffffu, mx, o));
    float inv = mx > 0.0f ? 127.0f / mx : 0.0f;
    signed char q[16];
#pragma unroll
    for (int i = 0; i < 4; i++) {
        q[4 * i + 0] = (signed char)__float2int_rn(v[i].x * inv);
        q[4 * i + 1] = (signed char)__float2int_rn(v[i].y * inv);
        q[4 * i + 2] = (signed char)__float2int_rn(v[i].z * inv);
        q[4 * i + 3] = (signed char)__float2int_rn(v[i].w * inv);
    }
    *(int4*)(g_Ai8 + (size_t)rowid * KIN + lane * 16) = *(int4*)q;
    if (lane == 0) g_sA[rowid] = mx / 127.0f;
}

// ---------------- gather + quantize B rows (block per p) ----------------
__global__ void k_gatherBq(const float* __restrict__ cw, const int* __restrict__ sidx) {
    __shared__ float row[NIN];
    __shared__ float rmax[8];
    int p = blockIdx.x, tid = threadIdx.x;
    for (int i = tid; i < NIN; i += 256) row[i] = cw[(size_t)p * NIN + i];
    __syncthreads();
#pragma unroll 1
    for (int b = 0; b < BB; b++) {
        int k = tid * 2;
        int i0 = sidx[b * KIN + k], i1 = sidx[b * KIN + k + 1];
        float v0 = row[i0], v1 = row[i1];
        float m = fmaxf(fabsf(v0), fabsf(v1));
#pragma unroll
        for (int o = 16; o > 0; o >>= 1) m = fmaxf(m, __shfl_xor_sync(0xffffffffu, m, o));
        if ((tid & 31) == 0) rmax[tid >> 5] = m;
        __syncthreads();
        float mx = fmaxf(fmaxf(fmaxf(rmax[0], rmax[1]), fmaxf(rmax[2], rmax[3])),
                         fmaxf(fmaxf(rmax[4], rmax[5]), fmaxf(rmax[6], rmax[7])));
        float inv = mx > 0.0f ? 127.0f / mx : 0.0f;
        unsigned char q0 = (unsigned char)(signed char)__float2int_rn(v0 * inv);
        unsigned char q1 = (unsigned char)(signed char)__float2int_rn(v1 * inv);
        *(unsigned short*)(g_Bi8 + ((size_t)b * NP + p) * KIN + k) =
            (unsigned short)(q0 | ((unsigned)q1 << 8));
        if (tid == 0) g_sB[b * NP + p] = mx / 127.0f;
        __syncthreads();
    }
}

// ---------------- gather B splits (bf16 2-plane) for NC candidates ----------------
__global__ void k_gatherBc(const float* __restrict__ cw, const int* __restrict__ sidx) {
    __shared__ float row[NIN];
    int blk = blockIdx.x;              // b * NC + j
    int b = blk / NC, j = blk % NC;
    int tid = threadIdx.x;
    int p = g_pidx512[b * NC + j];
    for (int i = tid; i < NIN; i += 256) row[i] = cw[(size_t)p * NIN + i];
    __syncthreads();
    int k = tid * 2;
    int i0 = sidx[b * KIN + k], i1 = sidx[b * KIN + k + 1];
    B2U hh, mm;
    split2(row[i0], hh.h[0], mm.h[0]);
    split2(row[i1], hh.h[1], mm.h[1]);
    const size_t PL = (size_t)NC * KIN;
    size_t base = ((size_t)(b * 2) * NC + j) * KIN + k;
    *(u32*)(g_Bc + base)      = hh.u;
    *(u32*)(g_Bc + base + PL) = mm.u;
}

// ---------------- K1: approx score GEMM, int8 IMMA, 128x128 tile ----------------
__global__ __launch_bounds__(256, 2)
void k_gemm1q() {
    extern __shared__ char smem[];
    const u32 sbase = smem_u32(smem);
    const int tid = threadIdx.x;
    const int wid = tid >> 5, lid = tid & 31;
    const int wm = wid & 3, wn = wid >> 2;       // warp tile 32 x 64
    const int b  = blockIdx.z;
    const int p0 = blockIdx.x * 128;
    const int s0 = blockIdx.y * 128;

    int acc[2][8][4];
#pragma unroll
    for (int i = 0; i < 2; i++)
#pragma unroll
        for (int j = 0; j < 8; j++)
#pragma unroll
            for (int r = 0; r < 4; r++) acc[i][j][r] = 0;

    // stage: 128 rows x 64 int8 (one k-slab of 64) for A and B
    auto load_stage = [&](int ks, int buf) {
        const int k0 = ks * 64;
        u32 sgA = sbase + buf * STG1;
        u32 sgB = sgA + PLANE;
#pragma unroll
        for (int i = 0; i < 2; i++) {
            int idx = tid + i * 256;
            int r = idx >> 2, c = idx & 3;
            const signed char* g = g_Ai8 + ((size_t)b * SS + s0 + r) * KIN + k0 + c * 16;
            cpasync16(sgA + r * RPAD + c * 16, g);
        }
#pragma unroll
        for (int i = 0; i < 2; i++) {
            int idx = tid + i * 256;
            int r = idx >> 2, c = idx & 3;
            const signed char* g = g_Bi8 + ((size_t)b * NP + p0 + r) * KIN + k0 + c * 16;
            cpasync16(sgB + r * RPAD + c * 16, g);
        }
    };

    const u32 aoff = (u32)((wm * 32 + (lid & 15)) * RPAD + (lid >> 4) * 16);
    const u32 boff = (u32)((wn * 64 + (lid & 15)) * RPAD + (lid >> 4) * 16);

    load_stage(0, 0); CP_COMMIT();

#pragma unroll 1
    for (int ks = 0; ks < KIN / 64; ks++) {      // 8 slabs
        int buf = ks & 1;
        if (ks < KIN / 64 - 1) { load_stage(ks + 1, buf ^ 1); CP_COMMIT(); CP_WAIT(1); }
        else                   { CP_WAIT(0); }
        __syncthreads();
        u32 sA = sbase + buf * STG1;
        u32 sB = sA + PLANE;
#pragma unroll
        for (int kk = 0; kk < 2; kk++) {         // 2 x k32
            u32 ah[2][4];
#pragma unroll
            for (int mt = 0; mt < 2; mt++)
                ldsm4(ah[mt], sA + aoff + mt * (16 * RPAD) + kk * 32);
            u32 bh[4][4];
#pragma unroll
            for (int q = 0; q < 4; q++)
                ldsm4(bh[q], sB + boff + q * (16 * RPAD) + kk * 32);
#pragma unroll
            for (int mt = 0; mt < 2; mt++)
#pragma unroll
                for (int q = 0; q < 4; q++) {
                    mma16832s8(acc[mt][2 * q],     ah[mt], bh[q][0], bh[q][2]);
                    mma16832s8(acc[mt][2 * q + 1], ah[mt], bh[q][1], bh[q][3]);
                }
        }
        __syncthreads();
    }

    // epilogue: z = sA[row] * sB[col] * acc ; per-column max over 128 rows
    float* sAs = (float*)smem;
    float* sBs = (float*)(smem + 512);
    u32*   scol = (u32*)(smem + 1024);
    if (tid < 128) {
        sAs[tid] = g_sA[b * SS + s0 + tid];
        sBs[tid] = g_sB[b * NP + p0 + tid];
        scol[tid] = 0u;
    }
    __syncthreads();
    int r0 = wm * 32 + (lid >> 2);
    float a0 = sAs[r0], a8 = sAs[r0 + 8], a16 = sAs[r0 + 16], a24 = sAs[r0 + 24];
#pragma unroll
    for (int nt = 0; nt < 8; nt++) {
        int col = wn * 64 + nt * 8 + 2 * (lid & 3);
        float m0 = fmaxf(fmaxf(a0 * (float)acc[0][nt][0], a8 * (float)acc[0][nt][2]),
                         fmaxf(a16 * (float)acc[1][nt][0], a24 * (float)acc[1][nt][2]));
        float m1 = fmaxf(fmaxf(a0 * (float)acc[0][nt][1], a8 * (float)acc[0][nt][3]),
                         fmaxf(a16 * (float)acc[1][nt][1], a24 * (float)acc[1][nt][3]));
#pragma unroll
        for (int mk = 4; mk < 32; mk <<= 1) {
            m0 = fmaxf(m0, __shfl_xor_sync(0xffffffffu, m0, mk));
            m1 = fmaxf(m1, __shfl_xor_sync(0xffffffffu, m1, mk));
        }
        if (lid < 4) {
            atomicMax(&scol[col],     fenc(m0 * sBs[col]));
            atomicMax(&scol[col + 1], fenc(m1 * sBs[col + 1]));
        }
    }
    __syncthreads();
    if (tid < 128) atomicMax(&g_scoreEnc[b * NP + p0 + tid], scol[tid]);
}

// ---------------- K2: hidden MLP ----------------
__global__ void k_hidden(const float* __restrict__ w1, const float* __restrict__ b1) {
    int j = blockIdx.x;
    int tid = threadIdx.x;
    const float* wr = w1 + (size_t)j * NIN;
    float acc[BB];
#pragma unroll
    for (int b = 0; b < BB; b++) acc[b] = 0.0f;
    for (int n = tid; n < NIN; n += 256) {
        float w = wr[n];
#pragma unroll
        for (int b = 0; b < BB; b++) acc[b] += w * g_mask[b * NIN + n];
    }
    __shared__ float red[BB][256];
#pragma unroll
    for (int b = 0; b < BB; b++) red[b][tid] = acc[b];
    __syncthreads();
    for (int s1 = 128; s1 > 0; s1 >>= 1) {
        if (tid < s1) {
#pragma unroll
            for (int b = 0; b < BB; b++) red[b][tid] += red[b][tid + s1];
        }
        __syncthreads();
    }
    if (tid < BB) g_h[tid * HID + j] = gelu_f(red[tid][0] + b1[j]);
}

// ---------------- K3: relevance -> sigmoid ----------------
__global__ void k_relsig(const float* __restrict__ w2, const float* __restrict__ b2) {
    int warp = threadIdx.x >> 5, lane = threadIdx.x & 31;
    int p = blockIdx.x * 8 + warp;
    const float4* wr = (const float4*)(w2 + (size_t)p * HID);
    float acc[BB];
#pragma unroll
    for (int b = 0; b < BB; b++) acc[b] = 0.0f;
#pragma unroll 4
    for (int j = lane; j < HID / 4; j += 32) {
        float4 w = wr[j];
#pragma unroll
        for (int b = 0; b < BB; b++) {
            float4 h = ((const float4*)(g_h + b * HID))[j];
            acc[b] += w.x * h.x + w.y * h.y + w.z * h.z + w.w * h.w;
        }
    }
#pragma unroll
    for (int o = 16; o > 0; o >>= 1)
#pragma unroll
        for (int b = 0; b < BB; b++) acc[b] += __shfl_down_sync(0xffffffffu, acc[b], o);
    if (lane == 0) {
#pragma unroll
        for (int b = 0; b < BB; b++) {
            float rel = acc[b] + b2[p];
            g_sig[b * NP + p] = 1.0f / (1.0f + expf(-rel));
        }
    }
}

// ---------------- K4: approx top-NC ----------------
__global__ void k_topkc() {
    __shared__ ull key[NP];
    int b = blockIdx.x, tid = threadIdx.x;
    for (int i = tid; i < NP; i += 1024) {
        float sc = gelu_f(fdec(g_scoreEnc[b * NP + i])) * g_sig[b * NP + i];
        key[i] = ((ull)fenc(sc) << 32) | (unsigned)i;
    }
    __syncthreads();
    for (int k = 2; k <= NP; k <<= 1) {
        for (int j = k >> 1; j > 0; j >>= 1) {
            for (int i = tid; i < NP; i += 1024) {
                int ix = i ^ j;
                if (ix > i) {
                    ull x = key[i], y = key[ix];
                    bool desc = ((i & k) == 0);
                    if (desc ? (x < y) : (x > y)) { key[i] = y; key[ix] = x; }
                }
            }
            __syncthreads();
        }
    }
    if (tid < NC) g_pidx512[b * NC + tid] = (int)(key[tid] & 0xffffffffu);
}

// ---------------- K5: refine — exact 3-pass z for NC cands (bf16) ----------------
__global__ __launch_bounds__(256)
void k_refine() {
    extern __shared__ char smem[];
    const u32 sbase = smem_u32(smem);
    const int tid = threadIdx.x;
    const int wid = tid >> 5, lid = tid & 31;
    const int wm = wid & 3, wn = wid >> 2;
    const int b  = blockIdx.z;
    const int n0 = blockIdx.x * 128;
    const int s0 = blockIdx.y * 128;

    float acc[2][8][4];
#pragma unroll
    for (int i = 0; i < 2; i++)
#pragma unroll
        for (int j = 0; j < 8; j++)
#pragma unroll
            for (int r = 0; r < 4; r++) acc[i][j][r] = 0.0f;

    auto load_stage = [&](int ks, int buf) {
        const int k0 = ks * 32;
        u32 sg = sbase + buf * STGB4;
#pragma unroll
        for (int i = 0; i < 4; i++) {
            int idx = tid + i * 256;
            int sp = idx >> 9, rem = idx & 511;
            int r = rem >> 2, c = rem & 3;
            const __nv_bfloat16* g = g_Asp + ((size_t)(b * 2 + sp) * SS + s0 + r) * KIN + k0 + c * 8;
            cpasync16(sg + sp * PLANE + r * RPAD + c * 16, g);
        }
#pragma unroll
        for (int i = 0; i < 4; i++) {
            int idx = tid + i * 256;
            int sp = idx >> 9, rem = idx & 511;
            int r = rem >> 2, c = rem & 3;
            const __nv_bfloat16* g = g_Bc + ((size_t)(b * 2 + sp) * NC + n0 + r) * KIN + k0 + c * 8;
            cpasync16(sg + 2 * PLANE + sp * PLANE + r * RPAD + c * 16, g);
        }
    };

    const u32 aoff = (u32)((wm * 32 + (lid & 15)) * RPAD + (lid >> 4) * 16);
    const u32 boff = (u32)((wn * 64 + (lid & 15)) * RPAD + (lid >> 4) * 16);

    load_stage(0, 0); CP_COMMIT();

#pragma unroll 1
    for (int ks = 0; ks < KIN / 32; ks++) {
        int buf = ks & 1;
        if (ks < KIN / 32 - 1) { load_stage(ks + 1, buf ^ 1); CP_COMMIT(); CP_WAIT(1); }
        else                   { CP_WAIT(0); }
        __syncthreads();
        u32 sA = sbase + buf * STGB4;
        u32 sB = sA + 2 * PLANE;
#pragma unroll
        for (int kk = 0; kk < 2; kk++) {
            u32 ah[2][4], am[2][4];
#pragma unroll
            for (int mt = 0; mt < 2; mt++) {
                ldsm4(ah[mt], sA + aoff + mt * (16 * RPAD) + kk * 32);
                ldsm4(am[mt], sA + PLANE + aoff + mt * (16 * RPAD) + kk * 32);
            }
            u32 bh[4][4], bm[4][4];
#pragma unroll
            for (int nt2 = 0; nt2 < 4; nt2++) {
                ldsm4(bh[nt2], sB + boff + nt2 * (16 * RPAD) + kk * 32);
                ldsm4(bm[nt2], sB + PLANE + boff + nt2 * (16 * RPAD) + kk * 32);
            }
#pragma unroll
            for (int mt = 0; mt < 2; mt++)
#pragma unroll
                for (int nt2 = 0; nt2 < 4; nt2++) {
                    mma16816(acc[mt][2 * nt2],     ah[mt], bh[nt2][0], bh[nt2][2]);
                    mma16816(acc[mt][2 * nt2 + 1], ah[mt], bh[nt2][1], bh[nt2][3]);
                    mma16816(acc[mt][2 * nt2],     ah[mt], bm[nt2][0], bm[nt2][2]);
                    mma16816(acc[mt][2 * nt2 + 1], ah[mt], bm[nt2][1], bm[nt2][3]);
                    mma16816(acc[mt][2 * nt2],     am[mt], bh[nt2][0], bh[nt2][2]);
                    mma16816(acc[mt][2 * nt2 + 1], am[mt], bh[nt2][1], bh[nt2][3]);
                }
        }
        __syncthreads();
    }

    u32* scol = (u32*)smem;
    if (tid < 128) scol[tid] = 0u;
    __syncthreads();

    const size_t PL = (size_t)SS * NC;
#pragma unroll
    for (int mt = 0; mt < 2; mt++)
#pragma unroll
        for (int nt = 0; nt < 8; nt++) {
            int row = s0 + wm * 32 + mt * 16 + (lid >> 2);
            int col = n0 + wn * 64 + nt * 8 + 2 * (lid & 3);
            float g0 = gelu_f(acc[mt][nt][0]), g1 = gelu_f(acc[mt][nt][1]);
            float g2 = gelu_f(acc[mt][nt][2]), g3 = gelu_f(acc[mt][nt][3]);
            B2U h01, m01, h23, m23;
            split2(g0, h01.h[0], m01.h[0]); split2(g1, h01.h[1], m01.h[1]);
            split2(g2, h23.h[0], m23.h[0]); split2(g3, h23.h[1], m23.h[1]);
            size_t base = ((size_t)(b * 2) * SS + row) * NC + col;
            *(u32*)(g_PC + base)               = h01.u;
            *(u32*)(g_PC + base + PL)          = m01.u;
            *(u32*)(g_PC + base + 8 * NC)      = h23.u;
            *(u32*)(g_PC + base + PL + 8 * NC) = m23.u;
        }
#pragma unroll
    for (int nt = 0; nt < 8; nt++) {
        float m0 = fmaxf(fmaxf(acc[0][nt][0], acc[0][nt][2]), fmaxf(acc[1][nt][0], acc[1][nt][2]));
        float m1 = fmaxf(fmaxf(acc[0][nt][1], acc[0][nt][3]), fmaxf(acc[1][nt][1], acc[1][nt][3]));
#pragma unroll
        for (int mk = 4; mk < 32; mk <<= 1) {
            m0 = fmaxf(m0, __shfl_xor_sync(0xffffffffu, m0, mk));
            m1 = fmaxf(m1, __shfl_xor_sync(0xffffffffu, m1, mk));
        }
        if (lid < 4) {
            atomicMax(&scol[wn * 64 + nt * 8 + 2 * lid],     fenc(m0));
            atomicMax(&scol[wn * 64 + nt * 8 + 2 * lid + 1], fenc(m1));
        }
    }
    __syncthreads();
    if (tid < 128) atomicMax(&g_scoreEnc2[b * NC + n0 + tid], scol[tid]);
}

// ---------------- K6: exact rescore + top-256 ----------------
__global__ void k_rescore() {
    __shared__ ull key[NCP];
    int b = blockIdx.x, tid = threadIdx.x;   // 512 threads
    if (tid < NC) {
        float z = fdec(g_scoreEnc2[b * NC + tid]);
        int p = g_pidx512[b * NC + tid];
        float sc = gelu_f(z) * g_sig[b * NP + p];
        key[tid] = ((ull)fenc(sc) << 32) | (unsigned)tid;
    } else {
        key[tid] = 0ULL;
    }
    __syncthreads();
    for (int k = 2; k <= NCP; k <<= 1) {
        for (int j = k >> 1; j > 0; j >>= 1) {
            int i = tid;
            int ix = i ^ j;
            if (ix > i) {
                ull x = key[i], y = key[ix];
                bool desc = ((i & k) == 0);
                if (desc ? (x < y) : (x > y)) { key[i] = y; key[ix] = x; }
            }
            __syncthreads();
        }
    }
    if (tid < KSEL) {
        int slot = (int)(key[tid] & 0xffffffffu);
        g_cmap[b * KSEL + tid] = slot;
        g_pidx[b * KSEL + tid] = g_pidx512[b * NC + slot];
    }
}

// ---------------- K7: compact via smem staging ----------------
__global__ void k_compact() {
    __shared__ __nv_bfloat16 st[2][8][NC];   // 16 KB
    __shared__ int cm[KSEL];
    int blk = blockIdx.x;                    // BB * SS/8 blocks
    int b = blk / (SS / 8);
    int s8 = (blk % (SS / 8)) * 8;
    int tid = threadIdx.x;
    if (tid < KSEL) cm[tid] = g_cmap[b * KSEL + tid];
    const int4* src0 = (const int4*)(g_PC + ((size_t)(b * 2)     * SS + s8) * NC);
    const int4* src1 = (const int4*)(g_PC + ((size_t)(b * 2 + 1) * SS + s8) * NC);
    int4* d0 = (int4*)&st[0][0][0];
    int4* d1 = (int4*)&st[1][0][0];
    const int NI4 = 8 * NC / 8;
    for (int idx = tid; idx < NI4; idx += 256) {
        d0[idx] = src0[idx];
        d1[idx] = src1[idx];
    }
    __syncthreads();
    int j = tid;
    int c = cm[j];
    const size_t PLa = (size_t)SS * KSEL;
#pragma unroll
    for (int r = 0; r < 8; r++) {
        size_t dst = ((size_t)(b * 2) * SS + s8 + r) * KSEL + j;
        g_PA[dst]       = st[0][r][c];
        g_PA[dst + PLa] = st[1][r][c];
    }
}

// ---------------- K8: gather + transpose + split proj rows ----------------
__global__ void k_projsplit(const float* __restrict__ proj) {
    __shared__ float t[32][33];
    __shared__ int pj[32];
    int j0 = blockIdx.x * 32, d0 = blockIdx.y * 32, b = blockIdx.z;
    int tx = threadIdx.x, ty = threadIdx.y;
    if (ty == 0) pj[tx] = g_pidx[b * KSEL + j0 + tx];
    __syncthreads();
#pragma unroll
    for (int i = 0; i < 32; i += 8) {
        int p = pj[ty + i];
        t[ty + i][tx] = proj[(size_t)p * DM + d0 + tx];
    }
    __syncthreads();
    const size_t PL = (size_t)DM * KSEL;
#pragma unroll
    for (int i = 0; i < 32; i += 8) {
        float v = t[tx][ty + i];
        __nv_bfloat16 h, m;
        split2(v, h, m);
        size_t base = ((size_t)(b * 2) * DM + d0 + ty + i) * KSEL + j0 + tx;
        g_Pr[base]      = h;
        g_Pr[base + PL] = m;
    }
}

// ---------------- K9: final GEMM (HMMA 3-pass) ----------------
__global__ __launch_bounds__(256)
void k_gemm3t(float* __restrict__ out) {
    extern __shared__ char smem[];
    const u32 sbase = smem_u32(smem);
    const int tid = threadIdx.x;
    const int wid = tid >> 5, lid = tid & 31;
    const int wm = wid & 3, wn = wid >> 2;
    const int b  = blockIdx.z;
    const int d0 = blockIdx.x * 128;
    const int s0 = blockIdx.y * 128;

    float acc[2][8][4];
#pragma unroll
    for (int i = 0; i < 2; i++)
#pragma unroll
        for (int j = 0; j < 8; j++)
#pragma unroll
            for (int r = 0; r < 4; r++) acc[i][j][r] = 0.0f;

    auto load_stage = [&](int ks, int buf) {
        const int k0 = ks * 32;
        u32 sg = sbase + buf * STGB4;
#pragma unroll
        for (int i = 0; i < 4; i++) {
            int idx = tid + i * 256;
            int sp = idx >> 9, rem = idx & 511;
            int r = rem >> 2, c = rem & 3;
            const __nv_bfloat16* g = g_PA + ((size_t)(b * 2 + sp) * SS + s0 + r) * KSEL + k0 + c * 8;
            cpasync16(sg + sp * PLANE + r * RPAD + c * 16, g);
        }
#pragma unroll
        for (int i = 0; i < 4; i++) {
            int idx = tid + i * 256;
            int sp = idx >> 9, rem = idx & 511;
            int r = rem >> 2, c = rem & 3;
            const __nv_bfloat16* g = g_Pr + ((size_t)(b * 2 + sp) * DM + d0 + r) * KSEL + k0 + c * 8;
            cpasync16(sg + 2 * PLANE + sp * PLANE + r * RPAD + c * 16, g);
        }
    };

    const u32 aoff = (u32)((wm * 32 + (lid & 15)) * RPAD + (lid >> 4) * 16);
    const u32 boff = (u32)((wn * 64 + (lid & 15)) * RPAD + (lid >> 4) * 16);

    load_stage(0, 0); CP_COMMIT();

#pragma unroll 1
    for (int ks = 0; ks < KSEL / 32; ks++) {
        int buf = ks & 1;
        if (ks < KSEL / 32 - 1) { load_stage(ks + 1, buf ^ 1); CP_COMMIT(); CP_WAIT(1); }
        else                    { CP_WAIT(0); }
        __syncthreads();
        u32 sA = sbase + buf * STGB4;
        u32 sB = sA + 2 * PLANE;
#pragma unroll
        for (int kk = 0; kk < 2; kk++) {
            u32 ah[2][4], am[2][4];
#pragma unroll
            for (int mt = 0; mt < 2; mt++) {
                ldsm4(ah[mt], sA + aoff + mt * (16 * RPAD) + kk * 32);
                ldsm4(am[mt], sA + PLANE + aoff + mt * (16 * RPAD) + kk * 32);
            }
            u32 bh[4][4], bm[4][4];
#pragma unroll
            for (int nt2 = 0; nt2 < 4; nt2++) {
                ldsm4(bh[nt2], sB + boff + nt2 * (16 * RPAD) + kk * 32);
                ldsm4(bm[nt2], sB + PLANE + boff + nt2 * (16 * RPAD) + kk * 32);
            }
#pragma unroll
            for (int mt = 0; mt < 2; mt++)
#pragma unroll
                for (int nt2 = 0; nt2 < 4; nt2++) {
                    mma16816(acc[mt][2 * nt2],     ah[mt], bh[nt2][0], bh[nt2][2]);
                    mma16816(acc[mt][2 * nt2 + 1], ah[mt], bh[nt2][1], bh[nt2][3]);
                    mma16816(acc[mt][2 * nt2],     ah[mt], bm[nt2][0], bm[nt2][2]);
                    mma16816(acc[mt][2 * nt2 + 1], ah[mt], bm[nt2][1], bm[nt2][3]);
                    mma16816(acc[mt][2 * nt2],     am[mt], bh[nt2][0], bh[nt2][2]);
                    mma16816(acc[mt][2 * nt2 + 1], am[mt], bh[nt2][1], bh[nt2][3]);
                }
        }
        __syncthreads();
    }
#pragma unroll
    for (int mt = 0; mt < 2; mt++)
#pragma unroll
        for (int nt = 0; nt < 8; nt++) {
            int row = s0 + wm * 32 + mt * 16 + (lid >> 2);
            int col = d0 + wn * 64 + nt * 8 + 2 * (lid & 3);
            float* po = out + ((size_t)b * SS + row) * DM + col;
            *(float2*)po            = make_float2(acc[mt][nt][0], acc[mt][nt][1]);
            *(float2*)(po + 8 * DM) = make_float2(acc[mt][nt][2], acc[mt][nt][3]);
        }
}

// ---------------- entry (multi-stream fork/join) ----------------
extern "C" void kernel_launch(void* const* d_in, const int* in_sizes, int n_in,
                              void* d_out, int out_size) {
    const float* act  = (const float*)d_in[0];
    const int*   sidx = (const int*)d_in[1];
    int o = (n_in >= 9 && in_sizes[2] == 1) ? 3 : 2;
    const float* cw   = (const float*)d_in[o + 0];
    const float* proj = (const float*)d_in[o + 1];
    const float* w1   = (const float*)d_in[o + 2];
    const float* b1   = (const float*)d_in[o + 3];
    const float* w2   = (const float*)d_in[o + 4];
    const float* b2   = (const float*)d_in[o + 5];
    float* out = (float*)d_out;

    static cudaStream_t s1 = nullptr;
    static cudaEvent_t ev0 = nullptr, ev1 = nullptr, ev2 = nullptr, ev3 = nullptr;
    if (s1 == nullptr) {
        cudaStreamCreateWithFlags(&s1, cudaStreamNonBlocking);
        cudaEventCreateWithFlags(&ev0, cudaEventDisableTiming);
        cudaEventCreateWithFlags(&ev1, cudaEventDisableTiming);
        cudaEventCreateWithFlags(&ev2, cudaEventDisableTiming);
        cudaEventCreateWithFlags(&ev3, cudaEventDisableTiming);
        cudaFuncSetAttribute(k_gemm1q, cudaFuncAttributeMaxDynamicSharedMemorySize, GSMEM1);
        cudaFuncSetAttribute(k_refine, cudaFuncAttributeMaxDynamicSharedMemorySize, GSMEM4);
        cudaFuncSetAttribute(k_gemm3t, cudaFuncAttributeMaxDynamicSharedMemorySize, GSMEM4);
    }

    // fork: bf16 A splits (for refine) + MLP chain on s1
    cudaEventRecord(ev0, 0);
    cudaStreamWaitEvent(s1, ev0, 0);
    k_splitAh<<<(BB * SS * KIN / 4) / 256, 256, 0, s1>>>(act);
    k_splitAm<<<(BB * SS * KIN / 4) / 256, 256, 0, s1>>>(act);
    k_initMask<<<(BB * NIN + 255) / 256, 256, 0, s1>>>();
    k_scatter<<<(BB * KIN + 255) / 256, 256, 0, s1>>>(sidx);
    k_hidden<<<HID, 256, 0, s1>>>(w1, b1);
    k_relsig<<<NP / 8, 256, 0, s1>>>(w2, b2);
    cudaEventRecord(ev1, s1);

    // main chain: int8 approx scores
    k_initScore<<<(BB * NP + 255) / 256, 256>>>();
    k_quantA<<<BB * SS / 8, 256>>>(act);
    k_gatherBq<<<NP, 256>>>(cw, sidx);
    k_gemm1q<<<dim3(NP / 128, SS / 128, BB), 256, GSMEM1>>>();

    // join
    cudaStreamWaitEvent(0, ev1, 0);
    k_topkc<<<BB, 1024>>>();
    k_gatherBc<<<BB * NC, 256>>>(cw, sidx);
    k_refine<<<dim3(NC / 128, SS / 128, BB), 256, GSMEM4>>>();
    k_rescore<<<BB, NCP>>>();

    // fork: projsplit on s1, compact on main
    cudaEventRecord(ev2, 0);
    cudaStreamWaitEvent(s1, ev2, 0);
    k_projsplit<<<dim3(KSEL / 32, DM / 32, BB), dim3(32, 8), 0, s1>>>(proj);
    cudaEventRecord(ev3, s1);
    k_compact<<<BB * SS / 8, 256>>>();
    cudaStreamWaitEvent(0, ev3, 0);

    k_gemm3t<<<dim3(DM / 128, SS / 128, BB), 256, GSMEM4>>>(out);
}

// round 11
// speedup vs baseline: 1.4160x; 1.4160x over previous
#include <cuda_runtime.h>
#include <cuda_bf16.h>

#define BB   8
#define SS   2048
#define KIN  512
#define NIN  2048
#define NP   4096
#define HID  4096
#define DM   1024
#define KSEL 256
#define NC   384     // refine candidate count
#define NCP  512     // padded for bitonic

typedef unsigned long long ull;
typedef unsigned int u32;

// ---------------- scratch ----------------
__device__ __align__(256) __nv_bfloat16 g_Asp[(size_t)BB * 2 * SS * KIN];
__device__ __align__(256) __nv_bfloat16 g_Bh [(size_t)BB * NP * KIN];
__device__ __align__(256) __nv_bfloat16 g_Bc [(size_t)BB * 2 * NC * KIN];
__device__ __align__(256) __nv_bfloat16 g_PC [(size_t)BB * 2 * SS * NC];
__device__ __align__(256) __nv_bfloat16 g_PA [(size_t)BB * 2 * SS * KSEL];
__device__ __align__(256) __nv_bfloat16 g_Pr [(size_t)BB * 2 * DM * KSEL];
__device__ float    g_mask[BB * NIN];
__device__ float    g_h[BB * HID];
__device__ float    g_sig[BB * NP];
__device__ unsigned g_scoreEnc[BB * NP];
__device__ unsigned g_scoreEnc2[BB * NC];
__device__ int      g_pidx512[BB * NC];
__device__ int      g_pidx[BB * KSEL];
__device__ int      g_cmap[BB * KSEL];

// ---------------- helpers ----------------
__device__ __forceinline__ unsigned fenc(float f) {
    unsigned u = __float_as_uint(f);
    return (u & 0x80000000u) ? ~u : (u | 0x80000000u);
}
__device__ __forceinline__ float fdec(unsigned u) {
    return __uint_as_float((u & 0x80000000u) ? (u & 0x7fffffffu) : ~u);
}
__device__ __forceinline__ float gelu_f(float x) {
    return 0.5f * x * (1.0f + erff(x * 0.70710678118654752f));
}
__device__ __forceinline__ u32 smem_u32(const void* p) {
    u32 a; asm("{ .reg .u64 t; cvta.to.shared.u64 t, %1; cvt.u32.u64 %0, t; }" : "=r"(a) : "l"(p));
    return a;
}
__device__ __forceinline__ void split2(float a, __nv_bfloat16& h, __nv_bfloat16& m) {
    h = __float2bfloat16(a);
    m = __float2bfloat16(a - __bfloat162float(h));
}

// ---------------- mma.sync / ldmatrix / cp.async ----------------
__device__ __forceinline__ void mma16816(float* d, const u32* a, u32 b0, u32 b1) {
    asm volatile("mma.sync.aligned.m16n8k16.row.col.f32.bf16.bf16.f32 "
        "{%0,%1,%2,%3}, {%4,%5,%6,%7}, {%8,%9}, {%0,%1,%2,%3};"
        : "+f"(d[0]), "+f"(d[1]), "+f"(d[2]), "+f"(d[3])
        : "r"(a[0]), "r"(a[1]), "r"(a[2]), "r"(a[3]), "r"(b0), "r"(b1));
}
__device__ __forceinline__ void ldsm4(u32* r, u32 addr) {
    asm volatile("ldmatrix.sync.aligned.m8n8.x4.shared.b16 {%0,%1,%2,%3}, [%4];"
        : "=r"(r[0]), "=r"(r[1]), "=r"(r[2]), "=r"(r[3]) : "r"(addr));
}
__device__ __forceinline__ void cpasync16(u32 dst, const void* src) {
    asm volatile("cp.async.cg.shared.global [%0], [%1], 16;" :: "r"(dst), "l"(src));
}
#define CP_COMMIT() asm volatile("cp.async.commit_group;" ::: "memory")
#define CP_WAIT(n)  asm volatile("cp.async.wait_group %0;" :: "n"(n) : "memory")

#define RPAD   80
#define PLANE  (128 * RPAD)          // 10240
#define STGB4  (4 * PLANE)           // refine/gemm3t stage: 40960
#define GSMEM4 (2 * STGB4)           // 81920 -> 2 CTAs/SM
#define STG1   (2 * PLANE)           // gemm1a stage: 20480
#define GSMEM1 (2 * STG1)            // 40960 -> 2 CTAs/SM

// ---------------- init kernels ----------------
__global__ void k_initMask() {
    int t = blockIdx.x * blockDim.x + threadIdx.x;
    if (t < BB * NIN) g_mask[t] = 0.0f;
}
__global__ void k_initScore() {
    int t = blockIdx.x * blockDim.x + threadIdx.x;
    if (t < BB * NP)  g_scoreEnc[t] = 0u;
    if (t < BB * NC)  g_scoreEnc2[t] = 0u;
}
__global__ void k_scatter(const int* __restrict__ sidx) {
    int t = blockIdx.x * blockDim.x + threadIdx.x;
    if (t < BB * KIN) {
        int b = t >> 9;
        g_mask[b * NIN + sidx[t]] = 1.0f;
    }
}

// ---------------- split A planes ----------------
union B4U { __nv_bfloat16 h[4]; ull u; };
union B2U { __nv_bfloat16 h[2]; u32 u; };

__global__ void k_splitAh(const float* __restrict__ act) {
    size_t t = (size_t)blockIdx.x * 256 + threadIdx.x;
    size_t bs = t >> 7;
    int k4 = (int)(t & 127);
    int b = (int)(bs >> 11), s = (int)(bs & 2047);
    float4 v = ((const float4*)act)[t];
    float vv[4] = { v.x, v.y, v.z, v.w };
    B4U hh;
#pragma unroll
    for (int i = 0; i < 4; i++) hh.h[i] = __float2bfloat16(vv[i]);
    *(ull*)(g_Asp + ((size_t)(b * 2) * SS + s) * KIN + k4 * 4) = hh.u;
}

__global__ void k_splitAm(const float* __restrict__ act) {
    size_t t = (size_t)blockIdx.x * 256 + threadIdx.x;
    size_t bs = t >> 7;
    int k4 = (int)(t & 127);
    int b = (int)(bs >> 11), s = (int)(bs & 2047);
    float4 v = ((const float4*)act)[t];
    float vv[4] = { v.x, v.y, v.z, v.w };
    B4U mm;
#pragma unroll
    for (int i = 0; i < 4; i++) {
        __nv_bfloat16 h = __float2bfloat16(vv[i]);
        mm.h[i] = __float2bfloat16(vv[i] - __bfloat162float(h));
    }
    *(ull*)(g_Asp + ((size_t)(b * 2 + 1) * SS + s) * KIN + k4 * 4) = mm.u;
}

// ---------------- gather B h-plane ----------------
__global__ void k_gatherBh(const float* __restrict__ cw, const int* __restrict__ sidx) {
    __shared__ float row[NIN];
    __shared__ int sidxS[BB * KIN];
    int p = blockIdx.x, tid = threadIdx.x;
    for (int i = tid; i < NIN; i += 256) row[i] = cw[(size_t)p * NIN + i];
    for (int i = tid; i < BB * KIN / 4; i += 256)
        ((int4*)sidxS)[i] = ((const int4*)sidx)[i];
    __syncthreads();
    int k = tid * 2;
#pragma unroll 1
    for (int b = 0; b < BB; b++) {
        int i0 = sidxS[b * KIN + k], i1 = sidxS[b * KIN + k + 1];
        B2U hh;
        hh.h[0] = __float2bfloat16(row[i0]);
        hh.h[1] = __float2bfloat16(row[i1]);
        *(u32*)(g_Bh + ((size_t)b * NP + p) * KIN + k) = hh.u;
    }
}

// ---------------- gather B splits for NC candidates ----------------
__global__ void k_gatherBc(const float* __restrict__ cw, const int* __restrict__ sidx) {
    __shared__ float row[NIN];
    int blk = blockIdx.x;
    int b = blk / NC, j = blk % NC;
    int tid = threadIdx.x;
    int p = g_pidx512[b * NC + j];
    for (int i = tid; i < NIN; i += 256) row[i] = cw[(size_t)p * NIN + i];
    __syncthreads();
    int k = tid * 2;
    int i0 = sidx[b * KIN + k], i1 = sidx[b * KIN + k + 1];
    B2U hh, mm;
    split2(row[i0], hh.h[0], mm.h[0]);
    split2(row[i1], hh.h[1], mm.h[1]);
    const size_t PL = (size_t)NC * KIN;
    size_t base = ((size_t)(b * 2) * NC + j) * KIN + k;
    *(u32*)(g_Bc + base)      = hh.u;
    *(u32*)(g_Bc + base + PL) = mm.u;
}

// ---------------- K1a: approx score GEMM, 128x128 tile, 2 CTAs/SM ----------------
__global__ __launch_bounds__(256, 2)
void k_gemm1a() {
    extern __shared__ char smem[];
    const u32 sbase = smem_u32(smem);
    const int tid = threadIdx.x;
    const int wid = tid >> 5, lid = tid & 31;
    const int wm = wid & 3, wn = wid >> 2;
    const int b  = blockIdx.z;
    const int p0 = blockIdx.x * 128;
    const int s0 = blockIdx.y * 128;

    float acc[2][8][4];
#pragma unroll
    for (int i = 0; i < 2; i++)
#pragma unroll
        for (int j = 0; j < 8; j++)
#pragma unroll
            for (int r = 0; r < 4; r++) acc[i][j][r] = 0.0f;

    auto load_stage = [&](int ks, int buf) {
        const int k0 = ks * 32;
        u32 sgA = sbase + buf * STG1;
        u32 sgB = sgA + PLANE;
#pragma unroll
        for (int i = 0; i < 2; i++) {
            int idx = tid + i * 256;
            int r = idx >> 2, c = idx & 3;
            const __nv_bfloat16* g = g_Asp + ((size_t)(b * 2) * SS + s0 + r) * KIN + k0 + c * 8;
            cpasync16(sgA + r * RPAD + c * 16, g);
        }
#pragma unroll
        for (int i = 0; i < 2; i++) {
            int idx = tid + i * 256;
            int r = idx >> 2, c = idx & 3;
            const __nv_bfloat16* g = g_Bh + ((size_t)b * NP + p0 + r) * KIN + k0 + c * 8;
            cpasync16(sgB + r * RPAD + c * 16, g);
        }
    };

    const u32 aoff = (u32)((wm * 32 + (lid & 15)) * RPAD + (lid >> 4) * 16);
    const u32 boff = (u32)((wn * 64 + (lid & 15)) * RPAD + (lid >> 4) * 16);

    load_stage(0, 0); CP_COMMIT();

#pragma unroll 1
    for (int ks = 0; ks < KIN / 32; ks++) {
        int buf = ks & 1;
        if (ks < KIN / 32 - 1) { load_stage(ks + 1, buf ^ 1); CP_COMMIT(); CP_WAIT(1); }
        else                   { CP_WAIT(0); }
        __syncthreads();
        u32 sA = sbase + buf * STG1;
        u32 sB = sA + PLANE;
#pragma unroll
        for (int kk = 0; kk < 2; kk++) {
            u32 ah[2][4];
#pragma unroll
            for (int mt = 0; mt < 2; mt++)
                ldsm4(ah[mt], sA + aoff + mt * (16 * RPAD) + kk * 32);
            u32 bh[4][4];
#pragma unroll
            for (int q = 0; q < 4; q++)
                ldsm4(bh[q], sB + boff + q * (16 * RPAD) + kk * 32);
#pragma unroll
            for (int mt = 0; mt < 2; mt++)
#pragma unroll
                for (int q = 0; q < 4; q++) {
                    mma16816(acc[mt][2 * q],     ah[mt], bh[q][0], bh[q][2]);
                    mma16816(acc[mt][2 * q + 1], ah[mt], bh[q][1], bh[q][3]);
                }
        }
        __syncthreads();
    }

    u32* scol = (u32*)smem;
    if (tid < 128) scol[tid] = 0u;
    __syncthreads();
#pragma unroll
    for (int nt = 0; nt < 8; nt++) {
        float m0 = fmaxf(fmaxf(acc[0][nt][0], acc[0][nt][2]), fmaxf(acc[1][nt][0], acc[1][nt][2]));
        float m1 = fmaxf(fmaxf(acc[0][nt][1], acc[0][nt][3]), fmaxf(acc[1][nt][1], acc[1][nt][3]));
#pragma unroll
        for (int mk = 4; mk < 32; mk <<= 1) {
            m0 = fmaxf(m0, __shfl_xor_sync(0xffffffffu, m0, mk));
            m1 = fmaxf(m1, __shfl_xor_sync(0xffffffffu, m1, mk));
        }
        if (lid < 4) {
            atomicMax(&scol[wn * 64 + nt * 8 + 2 * lid],     fenc(m0));
            atomicMax(&scol[wn * 64 + nt * 8 + 2 * lid + 1], fenc(m1));
        }
    }
    __syncthreads();
    if (tid < 128) atomicMax(&g_scoreEnc[b * NP + p0 + tid], scol[tid]);
}

// ---------------- K2: hidden MLP ----------------
__global__ void k_hidden(const float* __restrict__ w1, const float* __restrict__ b1) {
    int j = blockIdx.x;
    int tid = threadIdx.x;
    const float* wr = w1 + (size_t)j * NIN;
    float acc[BB];
#pragma unroll
    for (int b = 0; b < BB; b++) acc[b] = 0.0f;
    for (int n = tid; n < NIN; n += 256) {
        float w = wr[n];
#pragma unroll
        for (int b = 0; b < BB; b++) acc[b] += w * g_mask[b * NIN + n];
    }
    __shared__ float red[BB][256];
#pragma unroll
    for (int b = 0; b < BB; b++) red[b][tid] = acc[b];
    __syncthreads();
    for (int s1 = 128; s1 > 0; s1 >>= 1) {
        if (tid < s1) {
#pragma unroll
            for (int b = 0; b < BB; b++) red[b][tid] += red[b][tid + s1];
        }
        __syncthreads();
    }
    if (tid < BB) g_h[tid * HID + j] = gelu_f(red[tid][0] + b1[j]);
}

// ---------------- K3a: relevance -> sigmoid ----------------
__global__ void k_relsig(const float* __restrict__ w2, const float* __restrict__ b2) {
    int warp = threadIdx.x >> 5, lane = threadIdx.x & 31;
    int p = blockIdx.x * 8 + warp;
    const float4* wr = (const float4*)(w2 + (size_t)p * HID);
    float acc[BB];
#pragma unroll
    for (int b = 0; b < BB; b++) acc[b] = 0.0f;
#pragma unroll 4
    for (int j = lane; j < HID / 4; j += 32) {
        float4 w = wr[j];
#pragma unroll
        for (int b = 0; b < BB; b++) {
            float4 h = ((const float4*)(g_h + b * HID))[j];
            acc[b] += w.x * h.x + w.y * h.y + w.z * h.z + w.w * h.w;
        }
    }
#pragma unroll
    for (int o = 16; o > 0; o >>= 1)
#pragma unroll
        for (int b = 0; b < BB; b++) acc[b] += __shfl_down_sync(0xffffffffu, acc[b], o);
    if (lane == 0) {
#pragma unroll
        for (int b = 0; b < BB; b++) {
            float rel = acc[b] + b2[p];
            g_sig[b * NP + p] = 1.0f / (1.0f + expf(-rel));
        }
    }
}

// ---------------- K4: approx top-NC ----------------
__global__ void k_topkc() {
    __shared__ ull key[NP];
    int b = blockIdx.x, tid = threadIdx.x;
    for (int i = tid; i < NP; i += 1024) {
        float sc = gelu_f(fdec(g_scoreEnc[b * NP + i])) * g_sig[b * NP + i];
        key[i] = ((ull)fenc(sc) << 32) | (unsigned)i;
    }
    __syncthreads();
    for (int k = 2; k <= NP; k <<= 1) {
        for (int j = k >> 1; j > 0; j >>= 1) {
            for (int i = tid; i < NP; i += 1024) {
                int ix = i ^ j;
                if (ix > i) {
                    ull x = key[i], y = key[ix];
                    bool desc = ((i & k) == 0);
                    if (desc ? (x < y) : (x > y)) { key[i] = y; key[ix] = x; }
                }
            }
            __syncthreads();
        }
    }
    if (tid < NC) g_pidx512[b * NC + tid] = (int)(key[tid] & 0xffffffffu);
}

// ---------------- K5: refine ----------------
__global__ __launch_bounds__(256)
void k_refine() {
    extern __shared__ char smem[];
    const u32 sbase = smem_u32(smem);
    const int tid = threadIdx.x;
    const int wid = tid >> 5, lid = tid & 31;
    const int wm = wid & 3, wn = wid >> 2;
    const int b  = blockIdx.z;
    const int n0 = blockIdx.x * 128;
    const int s0 = blockIdx.y * 128;

    float acc[2][8][4];
#pragma unroll
    for (int i = 0; i < 2; i++)
#pragma unroll
        for (int j = 0; j < 8; j++)
#pragma unroll
            for (int r = 0; r < 4; r++) acc[i][j][r] = 0.0f;

    auto load_stage = [&](int ks, int buf) {
        const int k0 = ks * 32;
        u32 sg = sbase + buf * STGB4;
#pragma unroll
        for (int i = 0; i < 4; i++) {
            int idx = tid + i * 256;
            int sp = idx >> 9, rem = idx & 511;
            int r = rem >> 2, c = rem & 3;
            const __nv_bfloat16* g = g_Asp + ((size_t)(b * 2 + sp) * SS + s0 + r) * KIN + k0 + c * 8;
            cpasync16(sg + sp * PLANE + r * RPAD + c * 16, g);
        }
#pragma unroll
        for (int i = 0; i < 4; i++) {
            int idx = tid + i * 256;
            int sp = idx >> 9, rem = idx & 511;
            int r = rem >> 2, c = rem & 3;
            const __nv_bfloat16* g = g_Bc + ((size_t)(b * 2 + sp) * NC + n0 + r) * KIN + k0 + c * 8;
            cpasync16(sg + 2 * PLANE + sp * PLANE + r * RPAD + c * 16, g);
        }
    };

    const u32 aoff = (u32)((wm * 32 + (lid & 15)) * RPAD + (lid >> 4) * 16);
    const u32 boff = (u32)((wn * 64 + (lid & 15)) * RPAD + (lid >> 4) * 16);

    load_stage(0, 0); CP_COMMIT();

#pragma unroll 1
    for (int ks = 0; ks < KIN / 32; ks++) {
        int buf = ks & 1;
        if (ks < KIN / 32 - 1) { load_stage(ks + 1, buf ^ 1); CP_COMMIT(); CP_WAIT(1); }
        else                   { CP_WAIT(0); }
        __syncthreads();
        u32 sA = sbase + buf * STGB4;
        u32 sB = sA + 2 * PLANE;
#pragma unroll
        for (int kk = 0; kk < 2; kk++) {
            u32 ah[2][4], am[2][4];
#pragma unroll
            for (int mt = 0; mt < 2; mt++) {
                ldsm4(ah[mt], sA + aoff + mt * (16 * RPAD) + kk * 32);
                ldsm4(am[mt], sA + PLANE + aoff + mt * (16 * RPAD) + kk * 32);
            }
            u32 bh[4][4], bm[4][4];
#pragma unroll
            for (int nt2 = 0; nt2 < 4; nt2++) {
                ldsm4(bh[nt2], sB + boff + nt2 * (16 * RPAD) + kk * 32);
                ldsm4(bm[nt2], sB + PLANE + boff + nt2 * (16 * RPAD) + kk * 32);
            }
#pragma unroll
            for (int mt = 0; mt < 2; mt++)
#pragma unroll
                for (int nt2 = 0; nt2 < 4; nt2++) {
                    mma16816(acc[mt][2 * nt2],     ah[mt], bh[nt2][0], bh[nt2][2]);
                    mma16816(acc[mt][2 * nt2 + 1], ah[mt], bh[nt2][1], bh[nt2][3]);
                    mma16816(acc[mt][2 * nt2],     ah[mt], bm[nt2][0], bm[nt2][2]);
                    mma16816(acc[mt][2 * nt2 + 1], ah[mt], bm[nt2][1], bm[nt2][3]);
                    mma16816(acc[mt][2 * nt2],     am[mt], bh[nt2][0], bh[nt2][2]);
                    mma16816(acc[mt][2 * nt2 + 1], am[mt], bh[nt2][1], bh[nt2][3]);
                }
        }
        __syncthreads();
    }

    u32* scol = (u32*)smem;
    if (tid < 128) scol[tid] = 0u;
    __syncthreads();

    const size_t PL = (size_t)SS * NC;
#pragma unroll
    for (int mt = 0; mt < 2; mt++)
#pragma unroll
        for (int nt = 0; nt < 8; nt++) {
            int row = s0 + wm * 32 + mt * 16 + (lid >> 2);
            int col = n0 + wn * 64 + nt * 8 + 2 * (lid & 3);
            float g0 = gelu_f(acc[mt][nt][0]), g1 = gelu_f(acc[mt][nt][1]);
            float g2 = gelu_f(acc[mt][nt][2]), g3 = gelu_f(acc[mt][nt][3]);
            B2U h01, m01, h23, m23;
            split2(g0, h01.h[0], m01.h[0]); split2(g1, h01.h[1], m01.h[1]);
            split2(g2, h23.h[0], m23.h[0]); split2(g3, h23.h[1], m23.h[1]);
            size_t base = ((size_t)(b * 2) * SS + row) * NC + col;
            *(u32*)(g_PC + base)               = h01.u;
            *(u32*)(g_PC + base + PL)          = m01.u;
            *(u32*)(g_PC + base + 8 * NC)      = h23.u;
            *(u32*)(g_PC + base + PL + 8 * NC) = m23.u;
        }
#pragma unroll
    for (int nt = 0; nt < 8; nt++) {
        float m0 = fmaxf(fmaxf(acc[0][nt][0], acc[0][nt][2]), fmaxf(acc[1][nt][0], acc[1][nt][2]));
        float m1 = fmaxf(fmaxf(acc[0][nt][1], acc[0][nt][3]), fmaxf(acc[1][nt][1], acc[1][nt][3]));
#pragma unroll
        for (int mk = 4; mk < 32; mk <<= 1) {
            m0 = fmaxf(m0, __shfl_xor_sync(0xffffffffu, m0, mk));
            m1 = fmaxf(m1, __shfl_xor_sync(0xffffffffu, m1, mk));
        }
        if (lid < 4) {
            atomicMax(&scol[wn * 64 + nt * 8 + 2 * lid],     fenc(m0));
            atomicMax(&scol[wn * 64 + nt * 8 + 2 * lid + 1], fenc(m1));
        }
    }
    __syncthreads();
    if (tid < 128) atomicMax(&g_scoreEnc2[b * NC + n0 + tid], scol[tid]);
}

// ---------------- K6: exact rescore + top-256 ----------------
__global__ void k_rescore() {
    __shared__ ull key[NCP];
    int b = blockIdx.x, tid = threadIdx.x;
    if (tid < NC) {
        float z = fdec(g_scoreEnc2[b * NC + tid]);
        int p = g_pidx512[b * NC + tid];
        float sc = gelu_f(z) * g_sig[b * NP + p];
        key[tid] = ((ull)fenc(sc) << 32) | (unsigned)tid;
    } else {
        key[tid] = 0ULL;
    }
    __syncthreads();
    for (int k = 2; k <= NCP; k <<= 1) {
        for (int j = k >> 1; j > 0; j >>= 1) {
            int i = tid;
            int ix = i ^ j;
            if (ix > i) {
                ull x = key[i], y = key[ix];
                bool desc = ((i & k) == 0);
                if (desc ? (x < y) : (x > y)) { key[i] = y; key[ix] = x; }
            }
            __syncthreads();
        }
    }
    if (tid < KSEL) {
        int slot = (int)(key[tid] & 0xffffffffu);
        g_cmap[b * KSEL + tid] = slot;
        g_pidx[b * KSEL + tid] = g_pidx512[b * NC + slot];
    }
}

// ---------------- K7: compact via smem staging ----------------
__global__ void k_compact() {
    __shared__ __nv_bfloat16 st[2][8][NC];
    __shared__ int cm[KSEL];
    int blk = blockIdx.x;
    int b = blk / (SS / 8);
    int s8 = (blk % (SS / 8)) * 8;
    int tid = threadIdx.x;
    if (tid < KSEL) cm[tid] = g_cmap[b * KSEL + tid];
    const int4* src0 = (const int4*)(g_PC + ((size_t)(b * 2)     * SS + s8) * NC);
    const int4* src1 = (const int4*)(g_PC + ((size_t)(b * 2 + 1) * SS + s8) * NC);
    int4* d0 = (int4*)&st[0][0][0];
    int4* d1 = (int4*)&st[1][0][0];
    const int NI4 = 8 * NC / 8;
    for (int idx = tid; idx < NI4; idx += 256) {
        d0[idx] = src0[idx];
        d1[idx] = src1[idx];
    }
    __syncthreads();
    int j = tid;
    int c = cm[j];
    const size_t PLa = (size_t)SS * KSEL;
#pragma unroll
    for (int r = 0; r < 8; r++) {
        size_t dst = ((size_t)(b * 2) * SS + s8 + r) * KSEL + j;
        g_PA[dst]       = st[0][r][c];
        g_PA[dst + PLa] = st[1][r][c];
    }
}

// ---------------- K8: gather + transpose + split proj rows ----------------
__global__ void k_projsplit(const float* __restrict__ proj) {
    __shared__ float t[32][33];
    __shared__ int pj[32];
    int j0 = blockIdx.x * 32, d0 = blockIdx.y * 32, b = blockIdx.z;
    int tx = threadIdx.x, ty = threadIdx.y;
    if (ty == 0) pj[tx] = g_pidx[b * KSEL + j0 + tx];
    __syncthreads();
#pragma unroll
    for (int i = 0; i < 32; i += 8) {
        int p = pj[ty + i];
        t[ty + i][tx] = proj[(size_t)p * DM + d0 + tx];
    }
    __syncthreads();
    const size_t PL = (size_t)DM * KSEL;
#pragma unroll
    for (int i = 0; i < 32; i += 8) {
        float v = t[tx][ty + i];
        __nv_bfloat16 h, m;
        split2(v, h, m);
        size_t base = ((size_t)(b * 2) * DM + d0 + ty + i) * KSEL + j0 + tx;
        g_Pr[base]      = h;
        g_Pr[base + PL] = m;
    }
}

// ---------------- K9: final GEMM ----------------
__global__ __launch_bounds__(256)
void k_gemm3t(float* __restrict__ out) {
    extern __shared__ char smem[];
    const u32 sbase = smem_u32(smem);
    const int tid = threadIdx.x;
    const int wid = tid >> 5, lid = tid & 31;
    const int wm = wid & 3, wn = wid >> 2;
    const int b  = blockIdx.z;
    const int d0 = blockIdx.x * 128;
    const int s0 = blockIdx.y * 128;

    float acc[2][8][4];
#pragma unroll
    for (int i = 0; i < 2; i++)
#pragma unroll
        for (int j = 0; j < 8; j++)
#pragma unroll
            for (int r = 0; r < 4; r++) acc[i][j][r] = 0.0f;

    auto load_stage = [&](int ks, int buf) {
        const int k0 = ks * 32;
        u32 sg = sbase + buf * STGB4;
#pragma unroll
        for (int i = 0; i < 4; i++) {
            int idx = tid + i * 256;
            int sp = idx >> 9, rem = idx & 511;
            int r = rem >> 2, c = rem & 3;
            const __nv_bfloat16* g = g_PA + ((size_t)(b * 2 + sp) * SS + s0 + r) * KSEL + k0 + c * 8;
            cpasync16(sg + sp * PLANE + r * RPAD + c * 16, g);
        }
#pragma unroll
        for (int i = 0; i < 4; i++) {
            int idx = tid + i * 256;
            int sp = idx >> 9, rem = idx & 511;
            int r = rem >> 2, c = rem & 3;
            const __nv_bfloat16* g = g_Pr + ((size_t)(b * 2 + sp) * DM + d0 + r) * KSEL + k0 + c * 8;
            cpasync16(sg + 2 * PLANE + sp * PLANE + r * RPAD + c * 16, g);
        }
    };

    const u32 aoff = (u32)((wm * 32 + (lid & 15)) * RPAD + (lid >> 4) * 16);
    const u32 boff = (u32)((wn * 64 + (lid & 15)) * RPAD + (lid >> 4) * 16);

    load_stage(0, 0); CP_COMMIT();

#pragma unroll 1
    for (int ks = 0; ks < KSEL / 32; ks++) {
        int buf = ks & 1;
        if (ks < KSEL / 32 - 1) { load_stage(ks + 1, buf ^ 1); CP_COMMIT(); CP_WAIT(1); }
        else                    { CP_WAIT(0); }
        __syncthreads();
        u32 sA = sbase + buf * STGB4;
        u32 sB = sA + 2 * PLANE;
#pragma unroll
        for (int kk = 0; kk < 2; kk++) {
            u32 ah[2][4], am[2][4];
#pragma unroll
            for (int mt = 0; mt < 2; mt++) {
                ldsm4(ah[mt], sA + aoff + mt * (16 * RPAD) + kk * 32);
                ldsm4(am[mt], sA + PLANE + aoff + mt * (16 * RPAD) + kk * 32);
            }
            u32 bh[4][4], bm[4][4];
#pragma unroll
            for (int nt2 = 0; nt2 < 4; nt2++) {
                ldsm4(bh[nt2], sB + boff + nt2 * (16 * RPAD) + kk * 32);
                ldsm4(bm[nt2], sB + PLANE + boff + nt2 * (16 * RPAD) + kk * 32);
            }
#pragma unroll
            for (int mt = 0; mt < 2; mt++)
#pragma unroll
                for (int nt2 = 0; nt2 < 4; nt2++) {
                    mma16816(acc[mt][2 * nt2],     ah[mt], bh[nt2][0], bh[nt2][2]);
                    mma16816(acc[mt][2 * nt2 + 1], ah[mt], bh[nt2][1], bh[nt2][3]);
                    mma16816(acc[mt][2 * nt2],     ah[mt], bm[nt2][0], bm[nt2][2]);
                    mma16816(acc[mt][2 * nt2 + 1], ah[mt], bm[nt2][1], bm[nt2][3]);
                    mma16816(acc[mt][2 * nt2],     am[mt], bh[nt2][0], bh[nt2][2]);
                    mma16816(acc[mt][2 * nt2 + 1], am[mt], bh[nt2][1], bh[nt2][3]);
                }
        }
        __syncthreads();
    }
#pragma unroll
    for (int mt = 0; mt < 2; mt++)
#pragma unroll
        for (int nt = 0; nt < 8; nt++) {
            int row = s0 + wm * 32 + mt * 16 + (lid >> 2);
            int col = d0 + wn * 64 + nt * 8 + 2 * (lid & 3);
            float* po = out + ((size_t)b * SS + row) * DM + col;
            *(float2*)po            = make_float2(acc[mt][nt][0], acc[mt][nt][1]);
            *(float2*)(po + 8 * DM) = make_float2(acc[mt][nt][2], acc[mt][nt][3]);
        }
}

// ---------------- entry (multi-stream fork/join) ----------------
extern "C" void kernel_launch(void* const* d_in, const int* in_sizes, int n_in,
                              void* d_out, int out_size) {
    const float* act  = (const float*)d_in[0];
    const int*   sidx = (const int*)d_in[1];
    int o = (n_in >= 9 && in_sizes[2] == 1) ? 3 : 2;
    const float* cw   = (const float*)d_in[o + 0];
    const float* proj = (const float*)d_in[o + 1];
    const float* w1   = (const float*)d_in[o + 2];
    const float* b1   = (const float*)d_in[o + 3];
    const float* w2   = (const float*)d_in[o + 4];
    const float* b2   = (const float*)d_in[o + 5];
    float* out = (float*)d_out;

    static cudaStream_t s1 = nullptr;
    static cudaEvent_t ev0 = nullptr, evA = nullptr, ev1 = nullptr, ev2 = nullptr, ev3 = nullptr;
    if (s1 == nullptr) {
        cudaStreamCreateWithFlags(&s1, cudaStreamNonBlocking);
        cudaEventCreateWithFlags(&ev0, cudaEventDisableTiming);
        cudaEventCreateWithFlags(&evA, cudaEventDisableTiming);
        cudaEventCreateWithFlags(&ev1, cudaEventDisableTiming);
        cudaEventCreateWithFlags(&ev2, cudaEventDisableTiming);
        cudaEventCreateWithFlags(&ev3, cudaEventDisableTiming);
        cudaFuncSetAttribute(k_gemm1a, cudaFuncAttributeMaxDynamicSharedMemorySize, GSMEM1);
        cudaFuncSetAttribute(k_refine, cudaFuncAttributeMaxDynamicSharedMemorySize, GSMEM4);
        cudaFuncSetAttribute(k_gemm3t, cudaFuncAttributeMaxDynamicSharedMemorySize, GSMEM4);
    }

    // fork: A plane splits + MLP chain on s1
    cudaEventRecord(ev0, 0);
    cudaStreamWaitEvent(s1, ev0, 0);
    k_splitAh<<<(BB * SS * KIN / 4) / 256, 256, 0, s1>>>(act);
    cudaEventRecord(evA, s1);                        // h-plane ready (gemm1a dep)
    k_splitAm<<<(BB * SS * KIN / 4) / 256, 256, 0, s1>>>(act);
    k_initMask<<<(BB * NIN + 255) / 256, 256, 0, s1>>>();
    k_scatter<<<(BB * KIN + 255) / 256, 256, 0, s1>>>(sidx);
    k_hidden<<<HID, 256, 0, s1>>>(w1, b1);
    k_relsig<<<NP / 8, 256, 0, s1>>>(w2, b2);
    cudaEventRecord(ev1, s1);

    // main chain
    k_initScore<<<(BB * NP + 255) / 256, 256>>>();
    k_gatherBh<<<NP, 256>>>(cw, sidx);
    cudaStreamWaitEvent(0, evA, 0);                  // gemm1a needs h-plane
    k_gemm1a<<<dim3(NP / 128, SS / 128, BB), 256, GSMEM1>>>();

    // join
    cudaStreamWaitEvent(0, ev1, 0);
    k_topkc<<<BB, 1024>>>();
    k_gatherBc<<<BB * NC, 256>>>(cw, sidx);
    k_refine<<<dim3(NC / 128, SS / 128, BB), 256, GSMEM4>>>();
    k_rescore<<<BB, NCP>>>();

    // fork: projsplit on s1, compact on main
    cudaEventRecord(ev2, 0);
    cudaStreamWaitEvent(s1, ev2, 0);
    k_projsplit<<<dim3(KSEL / 32, DM / 32, BB), dim3(32, 8), 0, s1>>>(proj);
    cudaEventRecord(ev3, s1);
    k_compact<<<BB * SS / 8, 256>>>();
    cudaStreamWaitEvent(0, ev3, 0);

    k_gemm3t<<<dim3(DM / 128, SS / 128, BB), 256, GSMEM4>>>(out);
}

// round 12
// speedup vs baseline: 1.4805x; 1.0456x over previous
#include <cuda_runtime.h>
#include <cuda_bf16.h>
#include <cuda_fp16.h>

#define BB   8
#define SS   2048
#define KIN  512
#define NIN  2048
#define NP   4096
#define HID  4096
#define DM   1024
#define KSEL 256
#define NC   384     // refine candidate count
#define NCP  512     // padded for bitonic

typedef unsigned long long ull;
typedef unsigned int u32;

// ---------------- scratch ----------------
__device__ __align__(256) __nv_bfloat16 g_Asp[(size_t)BB * 2 * SS * KIN];  // bf16 planes (refine)
__device__ __align__(256) __half        g_Ah16[(size_t)BB * SS * KIN];     // f16 A (approx)
__device__ __align__(256) __half        g_Bh [(size_t)BB * NP * KIN];      // f16 B (approx)
__device__ __align__(256) __nv_bfloat16 g_Bc [(size_t)BB * 2 * NC * KIN];
__device__ __align__(256) __nv_bfloat16 g_PC [(size_t)BB * 2 * SS * NC];
__device__ __align__(256) __nv_bfloat16 g_PA [(size_t)BB * 2 * SS * KSEL];
__device__ __align__(256) __nv_bfloat16 g_Pr [(size_t)BB * 2 * DM * KSEL];
__device__ float    g_mask[BB * NIN];
__device__ float    g_h[BB * HID];
__device__ float    g_sig[BB * NP];
__device__ unsigned g_scoreEnc[BB * NP];
__device__ unsigned g_scoreEnc2[BB * NC];
__device__ int      g_pidx512[BB * NC];
__device__ int      g_pidx[BB * KSEL];
__device__ int      g_cmap[BB * KSEL];

// ---------------- helpers ----------------
__device__ __forceinline__ unsigned fenc(float f) {
    unsigned u = __float_as_uint(f);
    return (u & 0x80000000u) ? ~u : (u | 0x80000000u);
}
__device__ __forceinline__ float fdec(unsigned u) {
    return __uint_as_float((u & 0x80000000u) ? (u & 0x7fffffffu) : ~u);
}
__device__ __forceinline__ float gelu_f(float x) {
    return 0.5f * x * (1.0f + erff(x * 0.70710678118654752f));
}
__device__ __forceinline__ u32 smem_u32(const void* p) {
    u32 a; asm("{ .reg .u64 t; cvta.to.shared.u64 t, %1; cvt.u32.u64 %0, t; }" : "=r"(a) : "l"(p));
    return a;
}
__device__ __forceinline__ void split2(float a, __nv_bfloat16& h, __nv_bfloat16& m) {
    h = __float2bfloat16(a);
    m = __float2bfloat16(a - __bfloat162float(h));
}

// ---------------- mma.sync / ldmatrix / cp.async ----------------
__device__ __forceinline__ void mma16816(float* d, const u32* a, u32 b0, u32 b1) {
    asm volatile("mma.sync.aligned.m16n8k16.row.col.f32.bf16.bf16.f32 "
        "{%0,%1,%2,%3}, {%4,%5,%6,%7}, {%8,%9}, {%0,%1,%2,%3};"
        : "+f"(d[0]), "+f"(d[1]), "+f"(d[2]), "+f"(d[3])
        : "r"(a[0]), "r"(a[1]), "r"(a[2]), "r"(a[3]), "r"(b0), "r"(b1));
}
// f16-accumulate variant (approx pass): potentially 2x rate
__device__ __forceinline__ void mma16816h(u32* d, const u32* a, u32 b0, u32 b1) {
    asm volatile("mma.sync.aligned.m16n8k16.row.col.f16.f16.f16.f16 "
        "{%0,%1}, {%2,%3,%4,%5}, {%6,%7}, {%0,%1};"
        : "+r"(d[0]), "+r"(d[1])
        : "r"(a[0]), "r"(a[1]), "r"(a[2]), "r"(a[3]), "r"(b0), "r"(b1));
}
__device__ __forceinline__ void ldsm4(u32* r, u32 addr) {
    asm volatile("ldmatrix.sync.aligned.m8n8.x4.shared.b16 {%0,%1,%2,%3}, [%4];"
        : "=r"(r[0]), "=r"(r[1]), "=r"(r[2]), "=r"(r[3]) : "r"(addr));
}
__device__ __forceinline__ void cpasync16(u32 dst, const void* src) {
    asm volatile("cp.async.cg.shared.global [%0], [%1], 16;" :: "r"(dst), "l"(src));
}
#define CP_COMMIT() asm volatile("cp.async.commit_group;" ::: "memory")
#define CP_WAIT(n)  asm volatile("cp.async.wait_group %0;" :: "n"(n) : "memory")

#define RPAD   80
#define PLANE  (128 * RPAD)          // 10240
#define STGB4  (4 * PLANE)           // refine/gemm3t stage: 40960
#define GSMEM4 (2 * STGB4)           // 81920 -> 2 CTAs/SM
#define STG1   (2 * PLANE)           // gemm1a stage: 20480
#define GSMEM1 (2 * STG1)            // 40960 -> 2 CTAs/SM

// ---------------- init kernels ----------------
__global__ void k_initMask() {
    int t = blockIdx.x * blockDim.x + threadIdx.x;
    if (t < BB * NIN) g_mask[t] = 0.0f;
}
__global__ void k_initScore() {
    int t = blockIdx.x * blockDim.x + threadIdx.x;
    if (t < BB * NP)  g_scoreEnc[t] = 0u;
    if (t < BB * NC)  g_scoreEnc2[t] = 0u;
}
__global__ void k_scatter(const int* __restrict__ sidx) {
    int t = blockIdx.x * blockDim.x + threadIdx.x;
    if (t < BB * KIN) {
        int b = t >> 9;
        g_mask[b * NIN + sidx[t]] = 1.0f;
    }
}

// ---------------- split A planes ----------------
union B4U { __nv_bfloat16 h[4]; ull u; };
union B2U { __nv_bfloat16 h[2]; u32 u; };
union H4U { __half h[4]; ull u; };
union H2U { __half h[2]; u32 u; };

__global__ void k_splitAf16(const float* __restrict__ act) {
    size_t t = (size_t)blockIdx.x * 256 + threadIdx.x;
    float4 v = ((const float4*)act)[t];
    H4U hh;
    hh.h[0] = __float2half(v.x); hh.h[1] = __float2half(v.y);
    hh.h[2] = __float2half(v.z); hh.h[3] = __float2half(v.w);
    *(ull*)(g_Ah16 + t * 4) = hh.u;
}

__global__ void k_splitAh(const float* __restrict__ act) {
    size_t t = (size_t)blockIdx.x * 256 + threadIdx.x;
    size_t bs = t >> 7;
    int k4 = (int)(t & 127);
    int b = (int)(bs >> 11), s = (int)(bs & 2047);
    float4 v = ((const float4*)act)[t];
    float vv[4] = { v.x, v.y, v.z, v.w };
    B4U hh;
#pragma unroll
    for (int i = 0; i < 4; i++) hh.h[i] = __float2bfloat16(vv[i]);
    *(ull*)(g_Asp + ((size_t)(b * 2) * SS + s) * KIN + k4 * 4) = hh.u;
}

__global__ void k_splitAm(const float* __restrict__ act) {
    size_t t = (size_t)blockIdx.x * 256 + threadIdx.x;
    size_t bs = t >> 7;
    int k4 = (int)(t & 127);
    int b = (int)(bs >> 11), s = (int)(bs & 2047);
    float4 v = ((const float4*)act)[t];
    float vv[4] = { v.x, v.y, v.z, v.w };
    B4U mm;
#pragma unroll
    for (int i = 0; i < 4; i++) {
        __nv_bfloat16 h = __float2bfloat16(vv[i]);
        mm.h[i] = __float2bfloat16(vv[i] - __bfloat162float(h));
    }
    *(ull*)(g_Asp + ((size_t)(b * 2 + 1) * SS + s) * KIN + k4 * 4) = mm.u;
}

// ---------------- gather B f16 (full 4096 rows) ----------------
__global__ void k_gatherBh(const float* __restrict__ cw, const int* __restrict__ sidx) {
    __shared__ float row[NIN];
    __shared__ int sidxS[BB * KIN];
    int p = blockIdx.x, tid = threadIdx.x;
    for (int i = tid; i < NIN; i += 256) row[i] = cw[(size_t)p * NIN + i];
    for (int i = tid; i < BB * KIN / 4; i += 256)
        ((int4*)sidxS)[i] = ((const int4*)sidx)[i];
    __syncthreads();
    int k = tid * 2;
#pragma unroll 1
    for (int b = 0; b < BB; b++) {
        int i0 = sidxS[b * KIN + k], i1 = sidxS[b * KIN + k + 1];
        H2U hh;
        hh.h[0] = __float2half(row[i0]);
        hh.h[1] = __float2half(row[i1]);
        *(u32*)(g_Bh + ((size_t)b * NP + p) * KIN + k) = hh.u;
    }
}

// ---------------- gather B splits for NC candidates ----------------
__global__ void k_gatherBc(const float* __restrict__ cw, const int* __restrict__ sidx) {
    __shared__ float row[NIN];
    int blk = blockIdx.x;
    int b = blk / NC, j = blk % NC;
    int tid = threadIdx.x;
    int p = g_pidx512[b * NC + j];
    for (int i = tid; i < NIN; i += 256) row[i] = cw[(size_t)p * NIN + i];
    __syncthreads();
    int k = tid * 2;
    int i0 = sidx[b * KIN + k], i1 = sidx[b * KIN + k + 1];
    B2U hh, mm;
    split2(row[i0], hh.h[0], mm.h[0]);
    split2(row[i1], hh.h[1], mm.h[1]);
    const size_t PL = (size_t)NC * KIN;
    size_t base = ((size_t)(b * 2) * NC + j) * KIN + k;
    *(u32*)(g_Bc + base)      = hh.u;
    *(u32*)(g_Bc + base + PL) = mm.u;
}

// ---------------- K1a: approx score GEMM, f16 acc, 128x128 tile ----------------
__global__ __launch_bounds__(256, 2)
void k_gemm1a() {
    extern __shared__ char smem[];
    const u32 sbase = smem_u32(smem);
    const int tid = threadIdx.x;
    const int wid = tid >> 5, lid = tid & 31;
    const int wm = wid & 3, wn = wid >> 2;
    const int b  = blockIdx.z;
    const int p0 = blockIdx.x * 128;
    const int s0 = blockIdx.y * 128;

    u32 acc[2][8][2];
#pragma unroll
    for (int i = 0; i < 2; i++)
#pragma unroll
        for (int j = 0; j < 8; j++) { acc[i][j][0] = 0u; acc[i][j][1] = 0u; }

    auto load_stage = [&](int ks, int buf) {
        const int k0 = ks * 32;
        u32 sgA = sbase + buf * STG1;
        u32 sgB = sgA + PLANE;
#pragma unroll
        for (int i = 0; i < 2; i++) {
            int idx = tid + i * 256;
            int r = idx >> 2, c = idx & 3;
            const __half* g = g_Ah16 + ((size_t)b * SS + s0 + r) * KIN + k0 + c * 8;
            cpasync16(sgA + r * RPAD + c * 16, g);
        }
#pragma unroll
        for (int i = 0; i < 2; i++) {
            int idx = tid + i * 256;
            int r = idx >> 2, c = idx & 3;
            const __half* g = g_Bh + ((size_t)b * NP + p0 + r) * KIN + k0 + c * 8;
            cpasync16(sgB + r * RPAD + c * 16, g);
        }
    };

    const u32 aoff = (u32)((wm * 32 + (lid & 15)) * RPAD + (lid >> 4) * 16);
    const u32 boff = (u32)((wn * 64 + (lid & 15)) * RPAD + (lid >> 4) * 16);

    load_stage(0, 0); CP_COMMIT();

#pragma unroll 1
    for (int ks = 0; ks < KIN / 32; ks++) {
        int buf = ks & 1;
        if (ks < KIN / 32 - 1) { load_stage(ks + 1, buf ^ 1); CP_COMMIT(); CP_WAIT(1); }
        else                   { CP_WAIT(0); }
        __syncthreads();
        u32 sA = sbase + buf * STG1;
        u32 sB = sA + PLANE;
#pragma unroll
        for (int kk = 0; kk < 2; kk++) {
            u32 ah[2][4];
#pragma unroll
            for (int mt = 0; mt < 2; mt++)
                ldsm4(ah[mt], sA + aoff + mt * (16 * RPAD) + kk * 32);
            u32 bh[4][4];
#pragma unroll
            for (int q = 0; q < 4; q++)
                ldsm4(bh[q], sB + boff + q * (16 * RPAD) + kk * 32);
#pragma unroll
            for (int mt = 0; mt < 2; mt++)
#pragma unroll
                for (int q = 0; q < 4; q++) {
                    mma16816h(acc[mt][2 * q],     ah[mt], bh[q][0], bh[q][2]);
                    mma16816h(acc[mt][2 * q + 1], ah[mt], bh[q][1], bh[q][3]);
                }
        }
        __syncthreads();
    }

    // epilogue: per-column max of z over 128 rows (f16 acc -> float)
    u32* scol = (u32*)smem;
    if (tid < 128) scol[tid] = 0u;
    __syncthreads();
#pragma unroll
    for (int nt = 0; nt < 8; nt++) {
        float m0 = -1e30f, m1 = -1e30f;
#pragma unroll
        for (int mt = 0; mt < 2; mt++) {
            float2 lo = __half22float2(*(const __half2*)&acc[mt][nt][0]);  // row r
            float2 hi = __half22float2(*(const __half2*)&acc[mt][nt][1]);  // row r+8
            m0 = fmaxf(m0, fmaxf(lo.x, hi.x));
            m1 = fmaxf(m1, fmaxf(lo.y, hi.y));
        }
#pragma unroll
        for (int mk = 4; mk < 32; mk <<= 1) {
            m0 = fmaxf(m0, __shfl_xor_sync(0xffffffffu, m0, mk));
            m1 = fmaxf(m1, __shfl_xor_sync(0xffffffffu, m1, mk));
        }
        if (lid < 4) {
            atomicMax(&scol[wn * 64 + nt * 8 + 2 * lid],     fenc(m0));
            atomicMax(&scol[wn * 64 + nt * 8 + 2 * lid + 1], fenc(m1));
        }
    }
    __syncthreads();
    if (tid < 128) atomicMax(&g_scoreEnc[b * NP + p0 + tid], scol[tid]);
}

// ---------------- K2: hidden MLP ----------------
__global__ void k_hidden(const float* __restrict__ w1, const float* __restrict__ b1) {
    int j = blockIdx.x;
    int tid = threadIdx.x;
    const float* wr = w1 + (size_t)j * NIN;
    float acc[BB];
#pragma unroll
    for (int b = 0; b < BB; b++) acc[b] = 0.0f;
    for (int n = tid; n < NIN; n += 256) {
        float w = wr[n];
#pragma unroll
        for (int b = 0; b < BB; b++) acc[b] += w * g_mask[b * NIN + n];
    }
    __shared__ float red[BB][256];
#pragma unroll
    for (int b = 0; b < BB; b++) red[b][tid] = acc[b];
    __syncthreads();
    for (int s1 = 128; s1 > 0; s1 >>= 1) {
        if (tid < s1) {
#pragma unroll
            for (int b = 0; b < BB; b++) red[b][tid] += red[b][tid + s1];
        }
        __syncthreads();
    }
    if (tid < BB) g_h[tid * HID + j] = gelu_f(red[tid][0] + b1[j]);
}

// ---------------- K3a: relevance -> sigmoid ----------------
__global__ void k_relsig(const float* __restrict__ w2, const float* __restrict__ b2) {
    int warp = threadIdx.x >> 5, lane = threadIdx.x & 31;
    int p = blockIdx.x * 8 + warp;
    const float4* wr = (const float4*)(w2 + (size_t)p * HID);
    float acc[BB];
#pragma unroll
    for (int b = 0; b < BB; b++) acc[b] = 0.0f;
#pragma unroll 4
    for (int j = lane; j < HID / 4; j += 32) {
        float4 w = wr[j];
#pragma unroll
        for (int b = 0; b < BB; b++) {
            float4 h = ((const float4*)(g_h + b * HID))[j];
            acc[b] += w.x * h.x + w.y * h.y + w.z * h.z + w.w * h.w;
        }
    }
#pragma unroll
    for (int o = 16; o > 0; o >>= 1)
#pragma unroll
        for (int b = 0; b < BB; b++) acc[b] += __shfl_down_sync(0xffffffffu, acc[b], o);
    if (lane == 0) {
#pragma unroll
        for (int b = 0; b < BB; b++) {
            float rel = acc[b] + b2[p];
            g_sig[b * NP + p] = 1.0f / (1.0f + expf(-rel));
        }
    }
}

// ---------------- K4: approx top-NC ----------------
__global__ void k_topkc() {
    __shared__ ull key[NP];
    int b = blockIdx.x, tid = threadIdx.x;
    for (int i = tid; i < NP; i += 1024) {
        float sc = gelu_f(fdec(g_scoreEnc[b * NP + i])) * g_sig[b * NP + i];
        key[i] = ((ull)fenc(sc) << 32) | (unsigned)i;
    }
    __syncthreads();
    for (int k = 2; k <= NP; k <<= 1) {
        for (int j = k >> 1; j > 0; j >>= 1) {
            for (int i = tid; i < NP; i += 1024) {
                int ix = i ^ j;
                if (ix > i) {
                    ull x = key[i], y = key[ix];
                    bool desc = ((i & k) == 0);
                    if (desc ? (x < y) : (x > y)) { key[i] = y; key[ix] = x; }
                }
            }
            __syncthreads();
        }
    }
    if (tid < NC) g_pidx512[b * NC + tid] = (int)(key[tid] & 0xffffffffu);
}

// ---------------- K5: refine — exact 3-pass z for NC cands ----------------
__global__ __launch_bounds__(256)
void k_refine() {
    extern __shared__ char smem[];
    const u32 sbase = smem_u32(smem);
    const int tid = threadIdx.x;
    const int wid = tid >> 5, lid = tid & 31;
    const int wm = wid & 3, wn = wid >> 2;
    const int b  = blockIdx.z;
    const int n0 = blockIdx.x * 128;
    const int s0 = blockIdx.y * 128;

    float acc[2][8][4];
#pragma unroll
    for (int i = 0; i < 2; i++)
#pragma unroll
        for (int j = 0; j < 8; j++)
#pragma unroll
            for (int r = 0; r < 4; r++) acc[i][j][r] = 0.0f;

    auto load_stage = [&](int ks, int buf) {
        const int k0 = ks * 32;
        u32 sg = sbase + buf * STGB4;
#pragma unroll
        for (int i = 0; i < 4; i++) {
            int idx = tid + i * 256;
            int sp = idx >> 9, rem = idx & 511;
            int r = rem >> 2, c = rem & 3;
            const __nv_bfloat16* g = g_Asp + ((size_t)(b * 2 + sp) * SS + s0 + r) * KIN + k0 + c * 8;
            cpasync16(sg + sp * PLANE + r * RPAD + c * 16, g);
        }
#pragma unroll
        for (int i = 0; i < 4; i++) {
            int idx = tid + i * 256;
            int sp = idx >> 9, rem = idx & 511;
            int r = rem >> 2, c = rem & 3;
            const __nv_bfloat16* g = g_Bc + ((size_t)(b * 2 + sp) * NC + n0 + r) * KIN + k0 + c * 8;
            cpasync16(sg + 2 * PLANE + sp * PLANE + r * RPAD + c * 16, g);
        }
    };

    const u32 aoff = (u32)((wm * 32 + (lid & 15)) * RPAD + (lid >> 4) * 16);
    const u32 boff = (u32)((wn * 64 + (lid & 15)) * RPAD + (lid >> 4) * 16);

    load_stage(0, 0); CP_COMMIT();

#pragma unroll 1
    for (int ks = 0; ks < KIN / 32; ks++) {
        int buf = ks & 1;
        if (ks < KIN / 32 - 1) { load_stage(ks + 1, buf ^ 1); CP_COMMIT(); CP_WAIT(1); }
        else                   { CP_WAIT(0); }
        __syncthreads();
        u32 sA = sbase + buf * STGB4;
        u32 sB = sA + 2 * PLANE;
#pragma unroll
        for (int kk = 0; kk < 2; kk++) {
            u32 ah[2][4], am[2][4];
#pragma unroll
            for (int mt = 0; mt < 2; mt++) {
                ldsm4(ah[mt], sA + aoff + mt * (16 * RPAD) + kk * 32);
                ldsm4(am[mt], sA + PLANE + aoff + mt * (16 * RPAD) + kk * 32);
            }
            u32 bh[4][4], bm[4][4];
#pragma unroll
            for (int nt2 = 0; nt2 < 4; nt2++) {
                ldsm4(bh[nt2], sB + boff + nt2 * (16 * RPAD) + kk * 32);
                ldsm4(bm[nt2], sB + PLANE + boff + nt2 * (16 * RPAD) + kk * 32);
            }
#pragma unroll
            for (int mt = 0; mt < 2; mt++)
#pragma unroll
                for (int nt2 = 0; nt2 < 4; nt2++) {
                    mma16816(acc[mt][2 * nt2],     ah[mt], bh[nt2][0], bh[nt2][2]);
                    mma16816(acc[mt][2 * nt2 + 1], ah[mt], bh[nt2][1], bh[nt2][3]);
                    mma16816(acc[mt][2 * nt2],     ah[mt], bm[nt2][0], bm[nt2][2]);
                    mma16816(acc[mt][2 * nt2 + 1], ah[mt], bm[nt2][1], bm[nt2][3]);
                    mma16816(acc[mt][2 * nt2],     am[mt], bh[nt2][0], bh[nt2][2]);
                    mma16816(acc[mt][2 * nt2 + 1], am[mt], bh[nt2][1], bh[nt2][3]);
                }
        }
        __syncthreads();
    }

    u32* scol = (u32*)smem;
    if (tid < 128) scol[tid] = 0u;
    __syncthreads();

    const size_t PL = (size_t)SS * NC;
#pragma unroll
    for (int mt = 0; mt < 2; mt++)
#pragma unroll
        for (int nt = 0; nt < 8; nt++) {
            int row = s0 + wm * 32 + mt * 16 + (lid >> 2);
            int col = n0 + wn * 64 + nt * 8 + 2 * (lid & 3);
            float g0 = gelu_f(acc[mt][nt][0]), g1 = gelu_f(acc[mt][nt][1]);
            float g2 = gelu_f(acc[mt][nt][2]), g3 = gelu_f(acc[mt][nt][3]);
            B2U h01, m01, h23, m23;
            split2(g0, h01.h[0], m01.h[0]); split2(g1, h01.h[1], m01.h[1]);
            split2(g2, h23.h[0], m23.h[0]); split2(g3, h23.h[1], m23.h[1]);
            size_t base = ((size_t)(b * 2) * SS + row) * NC + col;
            *(u32*)(g_PC + base)               = h01.u;
            *(u32*)(g_PC + base + PL)          = m01.u;
            *(u32*)(g_PC + base + 8 * NC)      = h23.u;
            *(u32*)(g_PC + base + PL + 8 * NC) = m23.u;
        }
#pragma unroll
    for (int nt = 0; nt < 8; nt++) {
        float m0 = fmaxf(fmaxf(acc[0][nt][0], acc[0][nt][2]), fmaxf(acc[1][nt][0], acc[1][nt][2]));
        float m1 = fmaxf(fmaxf(acc[0][nt][1], acc[0][nt][3]), fmaxf(acc[1][nt][1], acc[1][nt][3]));
#pragma unroll
        for (int mk = 4; mk < 32; mk <<= 1) {
            m0 = fmaxf(m0, __shfl_xor_sync(0xffffffffu, m0, mk));
            m1 = fmaxf(m1, __shfl_xor_sync(0xffffffffu, m1, mk));
        }
        if (lid < 4) {
            atomicMax(&scol[wn * 64 + nt * 8 + 2 * lid],     fenc(m0));
            atomicMax(&scol[wn * 64 + nt * 8 + 2 * lid + 1], fenc(m1));
        }
    }
    __syncthreads();
    if (tid < 128) atomicMax(&g_scoreEnc2[b * NC + n0 + tid], scol[tid]);
}

// ---------------- K6: exact rescore + top-256 ----------------
__global__ void k_rescore() {
    __shared__ ull key[NCP];
    int b = blockIdx.x, tid = threadIdx.x;
    if (tid < NC) {
        float z = fdec(g_scoreEnc2[b * NC + tid]);
        int p = g_pidx512[b * NC + tid];
        float sc = gelu_f(z) * g_sig[b * NP + p];
        key[tid] = ((ull)fenc(sc) << 32) | (unsigned)tid;
    } else {
        key[tid] = 0ULL;
    }
    __syncthreads();
    for (int k = 2; k <= NCP; k <<= 1) {
        for (int j = k >> 1; j > 0; j >>= 1) {
            int i = tid;
            int ix = i ^ j;
            if (ix > i) {
                ull x = key[i], y = key[ix];
                bool desc = ((i & k) == 0);
                if (desc ? (x < y) : (x > y)) { key[i] = y; key[ix] = x; }
            }
            __syncthreads();
        }
    }
    if (tid < KSEL) {
        int slot = (int)(key[tid] & 0xffffffffu);
        g_cmap[b * KSEL + tid] = slot;
        g_pidx[b * KSEL + tid] = g_pidx512[b * NC + slot];
    }
}

// ---------------- K7: compact via smem staging ----------------
__global__ void k_compact() {
    __shared__ __nv_bfloat16 st[2][8][NC];
    __shared__ int cm[KSEL];
    int blk = blockIdx.x;
    int b = blk / (SS / 8);
    int s8 = (blk % (SS / 8)) * 8;
    int tid = threadIdx.x;
    if (tid < KSEL) cm[tid] = g_cmap[b * KSEL + tid];
    const int4* src0 = (const int4*)(g_PC + ((size_t)(b * 2)     * SS + s8) * NC);
    const int4* src1 = (const int4*)(g_PC + ((size_t)(b * 2 + 1) * SS + s8) * NC);
    int4* d0 = (int4*)&st[0][0][0];
    int4* d1 = (int4*)&st[1][0][0];
    const int NI4 = 8 * NC / 8;
    for (int idx = tid; idx < NI4; idx += 256) {
        d0[idx] = src0[idx];
        d1[idx] = src1[idx];
    }
    __syncthreads();
    int j = tid;
    int c = cm[j];
    const size_t PLa = (size_t)SS * KSEL;
#pragma unroll
    for (int r = 0; r < 8; r++) {
        size_t dst = ((size_t)(b * 2) * SS + s8 + r) * KSEL + j;
        g_PA[dst]       = st[0][r][c];
        g_PA[dst + PLa] = st[1][r][c];
    }
}

// ---------------- K8: gather + transpose + split proj rows ----------------
__global__ void k_projsplit(const float* __restrict__ proj) {
    __shared__ float t[32][33];
    __shared__ int pj[32];
    int j0 = blockIdx.x * 32, d0 = blockIdx.y * 32, b = blockIdx.z;
    int tx = threadIdx.x, ty = threadIdx.y;
    if (ty == 0) pj[tx] = g_pidx[b * KSEL + j0 + tx];
    __syncthreads();
#pragma unroll
    for (int i = 0; i < 32; i += 8) {
        int p = pj[ty + i];
        t[ty + i][tx] = proj[(size_t)p * DM + d0 + tx];
    }
    __syncthreads();
    const size_t PL = (size_t)DM * KSEL;
#pragma unroll
    for (int i = 0; i < 32; i += 8) {
        float v = t[tx][ty + i];
        __nv_bfloat16 h, m;
        split2(v, h, m);
        size_t base = ((size_t)(b * 2) * DM + d0 + ty + i) * KSEL + j0 + tx;
        g_Pr[base]      = h;
        g_Pr[base + PL] = m;
    }
}

// ---------------- K9: final GEMM (HMMA 3-pass) ----------------
__global__ __launch_bounds__(256)
void k_gemm3t(float* __restrict__ out) {
    extern __shared__ char smem[];
    const u32 sbase = smem_u32(smem);
    const int tid = threadIdx.x;
    const int wid = tid >> 5, lid = tid & 31;
    const int wm = wid & 3, wn = wid >> 2;
    const int b  = blockIdx.z;
    const int d0 = blockIdx.x * 128;
    const int s0 = blockIdx.y * 128;

    float acc[2][8][4];
#pragma unroll
    for (int i = 0; i < 2; i++)
#pragma unroll
        for (int j = 0; j < 8; j++)
#pragma unroll
            for (int r = 0; r < 4; r++) acc[i][j][r] = 0.0f;

    auto load_stage = [&](int ks, int buf) {
        const int k0 = ks * 32;
        u32 sg = sbase + buf * STGB4;
#pragma unroll
        for (int i = 0; i < 4; i++) {
            int idx = tid + i * 256;
            int sp = idx >> 9, rem = idx & 511;
            int r = rem >> 2, c = rem & 3;
            const __nv_bfloat16* g = g_PA + ((size_t)(b * 2 + sp) * SS + s0 + r) * KSEL + k0 + c * 8;
            cpasync16(sg + sp * PLANE + r * RPAD + c * 16, g);
        }
#pragma unroll
        for (int i = 0; i < 4; i++) {
            int idx = tid + i * 256;
            int sp = idx >> 9, rem = idx & 511;
            int r = rem >> 2, c = rem & 3;
            const __nv_bfloat16* g = g_Pr + ((size_t)(b * 2 + sp) * DM + d0 + r) * KSEL + k0 + c * 8;
            cpasync16(sg + 2 * PLANE + sp * PLANE + r * RPAD + c * 16, g);
        }
    };

    const u32 aoff = (u32)((wm * 32 + (lid & 15)) * RPAD + (lid >> 4) * 16);
    const u32 boff = (u32)((wn * 64 + (lid & 15)) * RPAD + (lid >> 4) * 16);

    load_stage(0, 0); CP_COMMIT();

#pragma unroll 1
    for (int ks = 0; ks < KSEL / 32; ks++) {
        int buf = ks & 1;
        if (ks < KSEL / 32 - 1) { load_stage(ks + 1, buf ^ 1); CP_COMMIT(); CP_WAIT(1); }
        else                    { CP_WAIT(0); }
        __syncthreads();
        u32 sA = sbase + buf * STGB4;
        u32 sB = sA + 2 * PLANE;
#pragma unroll
        for (int kk = 0; kk < 2; kk++) {
            u32 ah[2][4], am[2][4];
#pragma unroll
            for (int mt = 0; mt < 2; mt++) {
                ldsm4(ah[mt], sA + aoff + mt * (16 * RPAD) + kk * 32);
                ldsm4(am[mt], sA + PLANE + aoff + mt * (16 * RPAD) + kk * 32);
            }
            u32 bh[4][4], bm[4][4];
#pragma unroll
            for (int nt2 = 0; nt2 < 4; nt2++) {
                ldsm4(bh[nt2], sB + boff + nt2 * (16 * RPAD) + kk * 32);
                ldsm4(bm[nt2], sB + PLANE + boff + nt2 * (16 * RPAD) + kk * 32);
            }
#pragma unroll
            for (int mt = 0; mt < 2; mt++)
#pragma unroll
                for (int nt2 = 0; nt2 < 4; nt2++) {
                    mma16816(acc[mt][2 * nt2],     ah[mt], bh[nt2][0], bh[nt2][2]);
                    mma16816(acc[mt][2 * nt2 + 1], ah[mt], bh[nt2][1], bh[nt2][3]);
                    mma16816(acc[mt][2 * nt2],     ah[mt], bm[nt2][0], bm[nt2][2]);
                    mma16816(acc[mt][2 * nt2 + 1], ah[mt], bm[nt2][1], bm[nt2][3]);
                    mma16816(acc[mt][2 * nt2],     am[mt], bh[nt2][0], bh[nt2][2]);
                    mma16816(acc[mt][2 * nt2 + 1], am[mt], bh[nt2][1], bh[nt2][3]);
                }
        }
        __syncthreads();
    }
#pragma unroll
    for (int mt = 0; mt < 2; mt++)
#pragma unroll
        for (int nt = 0; nt < 8; nt++) {
            int row = s0 + wm * 32 + mt * 16 + (lid >> 2);
            int col = d0 + wn * 64 + nt * 8 + 2 * (lid & 3);
            float* po = out + ((size_t)b * SS + row) * DM + col;
            *(float2*)po            = make_float2(acc[mt][nt][0], acc[mt][nt][1]);
            *(float2*)(po + 8 * DM) = make_float2(acc[mt][nt][2], acc[mt][nt][3]);
        }
}

// ---------------- entry (multi-stream fork/join) ----------------
extern "C" void kernel_launch(void* const* d_in, const int* in_sizes, int n_in,
                              void* d_out, int out_size) {
    const float* act  = (const float*)d_in[0];
    const int*   sidx = (const int*)d_in[1];
    int o = (n_in >= 9 && in_sizes[2] == 1) ? 3 : 2;
    const float* cw   = (const float*)d_in[o + 0];
    const float* proj = (const float*)d_in[o + 1];
    const float* w1   = (const float*)d_in[o + 2];
    const float* b1   = (const float*)d_in[o + 3];
    const float* w2   = (const float*)d_in[o + 4];
    const float* b2   = (const float*)d_in[o + 5];
    float* out = (float*)d_out;

    static cudaStream_t s1 = nullptr;
    static cudaEvent_t ev0 = nullptr, evA = nullptr, ev1 = nullptr, ev2 = nullptr, ev3 = nullptr;
    if (s1 == nullptr) {
        cudaStreamCreateWithFlags(&s1, cudaStreamNonBlocking);
        cudaEventCreateWithFlags(&ev0, cudaEventDisableTiming);
        cudaEventCreateWithFlags(&evA, cudaEventDisableTiming);
        cudaEventCreateWithFlags(&ev1, cudaEventDisableTiming);
        cudaEventCreateWithFlags(&ev2, cudaEventDisableTiming);
        cudaEventCreateWithFlags(&ev3, cudaEventDisableTiming);
        cudaFuncSetAttribute(k_gemm1a, cudaFuncAttributeMaxDynamicSharedMemorySize, GSMEM1);
        cudaFuncSetAttribute(k_refine, cudaFuncAttributeMaxDynamicSharedMemorySize, GSMEM4);
        cudaFuncSetAttribute(k_gemm3t, cudaFuncAttributeMaxDynamicSharedMemorySize, GSMEM4);
    }

    // fork: f16 A (gemm1a dep), bf16 A planes (refine) + MLP chain on s1
    cudaEventRecord(ev0, 0);
    cudaStreamWaitEvent(s1, ev0, 0);
    k_splitAf16<<<(BB * SS * KIN / 4) / 256, 256, 0, s1>>>(act);
    cudaEventRecord(evA, s1);                        // f16 A ready (gemm1a dep)
    k_splitAh<<<(BB * SS * KIN / 4) / 256, 256, 0, s1>>>(act);
    k_splitAm<<<(BB * SS * KIN / 4) / 256, 256, 0, s1>>>(act);
    k_initMask<<<(BB * NIN + 255) / 256, 256, 0, s1>>>();
    k_scatter<<<(BB * KIN + 255) / 256, 256, 0, s1>>>(sidx);
    k_hidden<<<HID, 256, 0, s1>>>(w1, b1);
    k_relsig<<<NP / 8, 256, 0, s1>>>(w2, b2);
    cudaEventRecord(ev1, s1);

    // main chain
    k_initScore<<<(BB * NP + 255) / 256, 256>>>();
    k_gatherBh<<<NP, 256>>>(cw, sidx);
    cudaStreamWaitEvent(0, evA, 0);                  // gemm1a needs f16 A
    k_gemm1a<<<dim3(NP / 128, SS / 128, BB), 256, GSMEM1>>>();

    // join
    cudaStreamWaitEvent(0, ev1, 0);
    k_topkc<<<BB, 1024>>>();
    k_gatherBc<<<BB * NC, 256>>>(cw, sidx);
    k_refine<<<dim3(NC / 128, SS / 128, BB), 256, GSMEM4>>>();
    k_rescore<<<BB, NCP>>>();

    // fork: projsplit on s1, compact on main
    cudaEventRecord(ev2, 0);
    cudaStreamWaitEvent(s1, ev2, 0);
    k_projsplit<<<dim3(KSEL / 32, DM / 32, BB), dim3(32, 8), 0, s1>>>(proj);
    cudaEventRecord(ev3, s1);
    k_compact<<<BB * SS / 8, 256>>>();
    cudaStreamWaitEvent(0, ev3, 0);

    k_gemm3t<<<dim3(DM / 128, SS / 128, BB), 256, GSMEM4>>>(out);
}

// round 13
// speedup vs baseline: 1.5466x; 1.0446x over previous
#include <cuda_runtime.h>
#include <cuda_bf16.h>
#include <cuda_fp16.h>

#define BB   8
#define SS   2048
#define KIN  512
#define NIN  2048
#define NP   4096
#define HID  4096
#define DM   1024
#define KSEL 256
#define NC   384     // refine candidate count
#define NCP  512     // padded for bitonic

typedef unsigned long long ull;
typedef unsigned int u32;

// ---------------- scratch ----------------
__device__ __align__(256) __nv_bfloat16 g_Asp[(size_t)BB * 2 * SS * KIN];  // bf16 planes (refine)
__device__ __align__(256) __half        g_Ah16[(size_t)BB * SS * KIN];     // f16 A (approx)
__device__ __align__(256) __half        g_Bh [(size_t)BB * NP * KIN];      // f16 B (approx)
__device__ __align__(256) __nv_bfloat16 g_Bc [(size_t)BB * 2 * NC * KIN];  // bf16 planes (refine)
__device__ __align__(256) __half        g_PC [(size_t)BB * 2 * SS * NC];   // f16 gelu splits
__device__ __align__(256) __half        g_PA [(size_t)BB * 2 * SS * KSEL]; // f16 compacted
__device__ __align__(256) __half        g_Pr [(size_t)BB * DM * KSEL];     // f16 proj^T (single plane)
__device__ float    g_mask[BB * NIN];
__device__ float    g_h[BB * HID];
__device__ float    g_sig[BB * NP];
__device__ unsigned g_scoreEnc[BB * NP];
__device__ unsigned g_scoreEnc2[BB * NC];
__device__ int      g_pidx512[BB * NC];
__device__ int      g_pidx[BB * KSEL];
__device__ int      g_cmap[BB * KSEL];

// ---------------- helpers ----------------
__device__ __forceinline__ unsigned fenc(float f) {
    unsigned u = __float_as_uint(f);
    return (u & 0x80000000u) ? ~u : (u | 0x80000000u);
}
__device__ __forceinline__ float fdec(unsigned u) {
    return __uint_as_float((u & 0x80000000u) ? (u & 0x7fffffffu) : ~u);
}
__device__ __forceinline__ float gelu_f(float x) {
    return 0.5f * x * (1.0f + erff(x * 0.70710678118654752f));
}
__device__ __forceinline__ u32 smem_u32(const void* p) {
    u32 a; asm("{ .reg .u64 t; cvta.to.shared.u64 t, %1; cvt.u32.u64 %0, t; }" : "=r"(a) : "l"(p));
    return a;
}
__device__ __forceinline__ void split2(float a, __nv_bfloat16& h, __nv_bfloat16& m) {
    h = __float2bfloat16(a);
    m = __float2bfloat16(a - __bfloat162float(h));
}
__device__ __forceinline__ void split2h(float a, __half& h, __half& m) {
    h = __float2half(a);
    m = __float2half(a - __half2float(h));
}

// ---------------- mma.sync / ldmatrix / cp.async ----------------
__device__ __forceinline__ void mma16816(float* d, const u32* a, u32 b0, u32 b1) {
    asm volatile("mma.sync.aligned.m16n8k16.row.col.f32.bf16.bf16.f32 "
        "{%0,%1,%2,%3}, {%4,%5,%6,%7}, {%8,%9}, {%0,%1,%2,%3};"
        : "+f"(d[0]), "+f"(d[1]), "+f"(d[2]), "+f"(d[3])
        : "r"(a[0]), "r"(a[1]), "r"(a[2]), "r"(a[3]), "r"(b0), "r"(b1));
}
// f16 inputs, f32 accumulate
__device__ __forceinline__ void mma16816f(float* d, const u32* a, u32 b0, u32 b1) {
    asm volatile("mma.sync.aligned.m16n8k16.row.col.f32.f16.f16.f32 "
        "{%0,%1,%2,%3}, {%4,%5,%6,%7}, {%8,%9}, {%0,%1,%2,%3};"
        : "+f"(d[0]), "+f"(d[1]), "+f"(d[2]), "+f"(d[3])
        : "r"(a[0]), "r"(a[1]), "r"(a[2]), "r"(a[3]), "r"(b0), "r"(b1));
}
// f16 accumulate (approx pass)
__device__ __forceinline__ void mma16816h(u32* d, const u32* a, u32 b0, u32 b1) {
    asm volatile("mma.sync.aligned.m16n8k16.row.col.f16.f16.f16.f16 "
        "{%0,%1}, {%2,%3,%4,%5}, {%6,%7}, {%0,%1};"
        : "+r"(d[0]), "+r"(d[1])
        : "r"(a[0]), "r"(a[1]), "r"(a[2]), "r"(a[3]), "r"(b0), "r"(b1));
}
__device__ __forceinline__ void ldsm4(u32* r, u32 addr) {
    asm volatile("ldmatrix.sync.aligned.m8n8.x4.shared.b16 {%0,%1,%2,%3}, [%4];"
        : "=r"(r[0]), "=r"(r[1]), "=r"(r[2]), "=r"(r[3]) : "r"(addr));
}
__device__ __forceinline__ void cpasync16(u32 dst, const void* src) {
    asm volatile("cp.async.cg.shared.global [%0], [%1], 16;" :: "r"(dst), "l"(src));
}
#define CP_COMMIT() asm volatile("cp.async.commit_group;" ::: "memory")
#define CP_WAIT(n)  asm volatile("cp.async.wait_group %0;" :: "n"(n) : "memory")

#define RPAD   80
#define PLANE  (128 * RPAD)          // 10240
#define STGB4  (4 * PLANE)           // refine stage: 40960
#define GSMEM4 (2 * STGB4)           // 81920 -> 2 CTAs/SM
#define STG1   (2 * PLANE)           // gemm1a stage: 20480
#define GSMEM1 (2 * STG1)            // 40960 -> 2 CTAs/SM
#define STG3   (3 * PLANE)           // gemm3t stage (PAh,PAm,Pr): 30720
#define GSMEM3 (2 * STG3)            // 61440 -> 2 CTAs/SM

// ---------------- init kernels ----------------
__global__ void k_initMask() {
    int t = blockIdx.x * blockDim.x + threadIdx.x;
    if (t < BB * NIN) g_mask[t] = 0.0f;
}
__global__ void k_initScore() {
    int t = blockIdx.x * blockDim.x + threadIdx.x;
    if (t < BB * NP)  g_scoreEnc[t] = 0u;
    if (t < BB * NC)  g_scoreEnc2[t] = 0u;
}
__global__ void k_scatter(const int* __restrict__ sidx) {
    int t = blockIdx.x * blockDim.x + threadIdx.x;
    if (t < BB * KIN) {
        int b = t >> 9;
        g_mask[b * NIN + sidx[t]] = 1.0f;
    }
}

// ---------------- split A planes ----------------
union B4U { __nv_bfloat16 h[4]; ull u; };
union B2U { __nv_bfloat16 h[2]; u32 u; };
union H4U { __half h[4]; ull u; };
union H2U { __half h[2]; u32 u; };

__global__ void k_splitAf16(const float* __restrict__ act) {
    size_t t = (size_t)blockIdx.x * 256 + threadIdx.x;
    float4 v = ((const float4*)act)[t];
    H4U hh;
    hh.h[0] = __float2half(v.x); hh.h[1] = __float2half(v.y);
    hh.h[2] = __float2half(v.z); hh.h[3] = __float2half(v.w);
    *(ull*)(g_Ah16 + t * 4) = hh.u;
}

__global__ void k_splitAh(const float* __restrict__ act) {
    size_t t = (size_t)blockIdx.x * 256 + threadIdx.x;
    size_t bs = t >> 7;
    int k4 = (int)(t & 127);
    int b = (int)(bs >> 11), s = (int)(bs & 2047);
    float4 v = ((const float4*)act)[t];
    float vv[4] = { v.x, v.y, v.z, v.w };
    B4U hh;
#pragma unroll
    for (int i = 0; i < 4; i++) hh.h[i] = __float2bfloat16(vv[i]);
    *(ull*)(g_Asp + ((size_t)(b * 2) * SS + s) * KIN + k4 * 4) = hh.u;
}

__global__ void k_splitAm(const float* __restrict__ act) {
    size_t t = (size_t)blockIdx.x * 256 + threadIdx.x;
    size_t bs = t >> 7;
    int k4 = (int)(t & 127);
    int b = (int)(bs >> 11), s = (int)(bs & 2047);
    float4 v = ((const float4*)act)[t];
    float vv[4] = { v.x, v.y, v.z, v.w };
    B4U mm;
#pragma unroll
    for (int i = 0; i < 4; i++) {
        __nv_bfloat16 h = __float2bfloat16(vv[i]);
        mm.h[i] = __float2bfloat16(vv[i] - __bfloat162float(h));
    }
    *(ull*)(g_Asp + ((size_t)(b * 2 + 1) * SS + s) * KIN + k4 * 4) = mm.u;
}

// ---------------- gather B f16 (full 4096 rows) ----------------
__global__ void k_gatherBh(const float* __restrict__ cw, const int* __restrict__ sidx) {
    __shared__ float row[NIN];
    __shared__ int sidxS[BB * KIN];
    int p = blockIdx.x, tid = threadIdx.x;
    for (int i = tid; i < NIN; i += 256) row[i] = cw[(size_t)p * NIN + i];
    for (int i = tid; i < BB * KIN / 4; i += 256)
        ((int4*)sidxS)[i] = ((const int4*)sidx)[i];
    __syncthreads();
    int k = tid * 2;
#pragma unroll 1
    for (int b = 0; b < BB; b++) {
        int i0 = sidxS[b * KIN + k], i1 = sidxS[b * KIN + k + 1];
        H2U hh;
        hh.h[0] = __float2half(row[i0]);
        hh.h[1] = __float2half(row[i1]);
        *(u32*)(g_Bh + ((size_t)b * NP + p) * KIN + k) = hh.u;
    }
}

// ---------------- gather B splits for NC candidates ----------------
__global__ void k_gatherBc(const float* __restrict__ cw, const int* __restrict__ sidx) {
    __shared__ float row[NIN];
    int blk = blockIdx.x;
    int b = blk / NC, j = blk % NC;
    int tid = threadIdx.x;
    int p = g_pidx512[b * NC + j];
    for (int i = tid; i < NIN; i += 256) row[i] = cw[(size_t)p * NIN + i];
    __syncthreads();
    int k = tid * 2;
    int i0 = sidx[b * KIN + k], i1 = sidx[b * KIN + k + 1];
    B2U hh, mm;
    split2(row[i0], hh.h[0], mm.h[0]);
    split2(row[i1], hh.h[1], mm.h[1]);
    const size_t PL = (size_t)NC * KIN;
    size_t base = ((size_t)(b * 2) * NC + j) * KIN + k;
    *(u32*)(g_Bc + base)      = hh.u;
    *(u32*)(g_Bc + base + PL) = mm.u;
}

// ---------------- K1a: approx score GEMM, f16 acc, 128x128 tile ----------------
__global__ __launch_bounds__(256, 2)
void k_gemm1a() {
    extern __shared__ char smem[];
    const u32 sbase = smem_u32(smem);
    const int tid = threadIdx.x;
    const int wid = tid >> 5, lid = tid & 31;
    const int wm = wid & 3, wn = wid >> 2;
    const int b  = blockIdx.z;
    const int p0 = blockIdx.x * 128;
    const int s0 = blockIdx.y * 128;

    u32 acc[2][8][2];
#pragma unroll
    for (int i = 0; i < 2; i++)
#pragma unroll
        for (int j = 0; j < 8; j++) { acc[i][j][0] = 0u; acc[i][j][1] = 0u; }

    auto load_stage = [&](int ks, int buf) {
        const int k0 = ks * 32;
        u32 sgA = sbase + buf * STG1;
        u32 sgB = sgA + PLANE;
#pragma unroll
        for (int i = 0; i < 2; i++) {
            int idx = tid + i * 256;
            int r = idx >> 2, c = idx & 3;
            const __half* g = g_Ah16 + ((size_t)b * SS + s0 + r) * KIN + k0 + c * 8;
            cpasync16(sgA + r * RPAD + c * 16, g);
        }
#pragma unroll
        for (int i = 0; i < 2; i++) {
            int idx = tid + i * 256;
            int r = idx >> 2, c = idx & 3;
            const __half* g = g_Bh + ((size_t)b * NP + p0 + r) * KIN + k0 + c * 8;
            cpasync16(sgB + r * RPAD + c * 16, g);
        }
    };

    const u32 aoff = (u32)((wm * 32 + (lid & 15)) * RPAD + (lid >> 4) * 16);
    const u32 boff = (u32)((wn * 64 + (lid & 15)) * RPAD + (lid >> 4) * 16);

    load_stage(0, 0); CP_COMMIT();

#pragma unroll 1
    for (int ks = 0; ks < KIN / 32; ks++) {
        int buf = ks & 1;
        if (ks < KIN / 32 - 1) { load_stage(ks + 1, buf ^ 1); CP_COMMIT(); CP_WAIT(1); }
        else                   { CP_WAIT(0); }
        __syncthreads();
        u32 sA = sbase + buf * STG1;
        u32 sB = sA + PLANE;
#pragma unroll
        for (int kk = 0; kk < 2; kk++) {
            u32 ah[2][4];
#pragma unroll
            for (int mt = 0; mt < 2; mt++)
                ldsm4(ah[mt], sA + aoff + mt * (16 * RPAD) + kk * 32);
            u32 bh[4][4];
#pragma unroll
            for (int q = 0; q < 4; q++)
                ldsm4(bh[q], sB + boff + q * (16 * RPAD) + kk * 32);
#pragma unroll
            for (int mt = 0; mt < 2; mt++)
#pragma unroll
                for (int q = 0; q < 4; q++) {
                    mma16816h(acc[mt][2 * q],     ah[mt], bh[q][0], bh[q][2]);
                    mma16816h(acc[mt][2 * q + 1], ah[mt], bh[q][1], bh[q][3]);
                }
        }
        __syncthreads();
    }

    u32* scol = (u32*)smem;
    if (tid < 128) scol[tid] = 0u;
    __syncthreads();
#pragma unroll
    for (int nt = 0; nt < 8; nt++) {
        float m0 = -1e30f, m1 = -1e30f;
#pragma unroll
        for (int mt = 0; mt < 2; mt++) {
            float2 lo = __half22float2(*(const __half2*)&acc[mt][nt][0]);
            float2 hi = __half22float2(*(const __half2*)&acc[mt][nt][1]);
            m0 = fmaxf(m0, fmaxf(lo.x, hi.x));
            m1 = fmaxf(m1, fmaxf(lo.y, hi.y));
        }
#pragma unroll
        for (int mk = 4; mk < 32; mk <<= 1) {
            m0 = fmaxf(m0, __shfl_xor_sync(0xffffffffu, m0, mk));
            m1 = fmaxf(m1, __shfl_xor_sync(0xffffffffu, m1, mk));
        }
        if (lid < 4) {
            atomicMax(&scol[wn * 64 + nt * 8 + 2 * lid],     fenc(m0));
            atomicMax(&scol[wn * 64 + nt * 8 + 2 * lid + 1], fenc(m1));
        }
    }
    __syncthreads();
    if (tid < 128) atomicMax(&g_scoreEnc[b * NP + p0 + tid], scol[tid]);
}

// ---------------- K2: hidden MLP ----------------
__global__ void k_hidden(const float* __restrict__ w1, const float* __restrict__ b1) {
    int j = blockIdx.x;
    int tid = threadIdx.x;
    const float* wr = w1 + (size_t)j * NIN;
    float acc[BB];
#pragma unroll
    for (int b = 0; b < BB; b++) acc[b] = 0.0f;
    for (int n = tid; n < NIN; n += 256) {
        float w = wr[n];
#pragma unroll
        for (int b = 0; b < BB; b++) acc[b] += w * g_mask[b * NIN + n];
    }
    __shared__ float red[BB][256];
#pragma unroll
    for (int b = 0; b < BB; b++) red[b][tid] = acc[b];
    __syncthreads();
    for (int s1 = 128; s1 > 0; s1 >>= 1) {
        if (tid < s1) {
#pragma unroll
            for (int b = 0; b < BB; b++) red[b][tid] += red[b][tid + s1];
        }
        __syncthreads();
    }
    if (tid < BB) g_h[tid * HID + j] = gelu_f(red[tid][0] + b1[j]);
}

// ---------------- K3a: relevance -> sigmoid ----------------
__global__ void k_relsig(const float* __restrict__ w2, const float* __restrict__ b2) {
    int warp = threadIdx.x >> 5, lane = threadIdx.x & 31;
    int p = blockIdx.x * 8 + warp;
    const float4* wr = (const float4*)(w2 + (size_t)p * HID);
    float acc[BB];
#pragma unroll
    for (int b = 0; b < BB; b++) acc[b] = 0.0f;
#pragma unroll 4
    for (int j = lane; j < HID / 4; j += 32) {
        float4 w = wr[j];
#pragma unroll
        for (int b = 0; b < BB; b++) {
            float4 h = ((const float4*)(g_h + b * HID))[j];
            acc[b] += w.x * h.x + w.y * h.y + w.z * h.z + w.w * h.w;
        }
    }
#pragma unroll
    for (int o = 16; o > 0; o >>= 1)
#pragma unroll
        for (int b = 0; b < BB; b++) acc[b] += __shfl_down_sync(0xffffffffu, acc[b], o);
    if (lane == 0) {
#pragma unroll
        for (int b = 0; b < BB; b++) {
            float rel = acc[b] + b2[p];
            g_sig[b * NP + p] = 1.0f / (1.0f + expf(-rel));
        }
    }
}

// ---------------- K4: approx top-NC ----------------
__global__ void k_topkc() {
    __shared__ ull key[NP];
    int b = blockIdx.x, tid = threadIdx.x;
    for (int i = tid; i < NP; i += 1024) {
        float sc = gelu_f(fdec(g_scoreEnc[b * NP + i])) * g_sig[b * NP + i];
        key[i] = ((ull)fenc(sc) << 32) | (unsigned)i;
    }
    __syncthreads();
    for (int k = 2; k <= NP; k <<= 1) {
        for (int j = k >> 1; j > 0; j >>= 1) {
            for (int i = tid; i < NP; i += 1024) {
                int ix = i ^ j;
                if (ix > i) {
                    ull x = key[i], y = key[ix];
                    bool desc = ((i & k) == 0);
                    if (desc ? (x < y) : (x > y)) { key[i] = y; key[ix] = x; }
                }
            }
            __syncthreads();
        }
    }
    if (tid < NC) g_pidx512[b * NC + tid] = (int)(key[tid] & 0xffffffffu);
}

// ---------------- K5: refine — exact 3-pass bf16 z for NC cands ----------------
__global__ __launch_bounds__(256)
void k_refine() {
    extern __shared__ char smem[];
    const u32 sbase = smem_u32(smem);
    const int tid = threadIdx.x;
    const int wid = tid >> 5, lid = tid & 31;
    const int wm = wid & 3, wn = wid >> 2;
    const int b  = blockIdx.z;
    const int n0 = blockIdx.x * 128;
    const int s0 = blockIdx.y * 128;

    float acc[2][8][4];
#pragma unroll
    for (int i = 0; i < 2; i++)
#pragma unroll
        for (int j = 0; j < 8; j++)
#pragma unroll
            for (int r = 0; r < 4; r++) acc[i][j][r] = 0.0f;

    auto load_stage = [&](int ks, int buf) {
        const int k0 = ks * 32;
        u32 sg = sbase + buf * STGB4;
#pragma unroll
        for (int i = 0; i < 4; i++) {
            int idx = tid + i * 256;
            int sp = idx >> 9, rem = idx & 511;
            int r = rem >> 2, c = rem & 3;
            const __nv_bfloat16* g = g_Asp + ((size_t)(b * 2 + sp) * SS + s0 + r) * KIN + k0 + c * 8;
            cpasync16(sg + sp * PLANE + r * RPAD + c * 16, g);
        }
#pragma unroll
        for (int i = 0; i < 4; i++) {
            int idx = tid + i * 256;
            int sp = idx >> 9, rem = idx & 511;
            int r = rem >> 2, c = rem & 3;
            const __nv_bfloat16* g = g_Bc + ((size_t)(b * 2 + sp) * NC + n0 + r) * KIN + k0 + c * 8;
            cpasync16(sg + 2 * PLANE + sp * PLANE + r * RPAD + c * 16, g);
        }
    };

    const u32 aoff = (u32)((wm * 32 + (lid & 15)) * RPAD + (lid >> 4) * 16);
    const u32 boff = (u32)((wn * 64 + (lid & 15)) * RPAD + (lid >> 4) * 16);

    load_stage(0, 0); CP_COMMIT();

#pragma unroll 1
    for (int ks = 0; ks < KIN / 32; ks++) {
        int buf = ks & 1;
        if (ks < KIN / 32 - 1) { load_stage(ks + 1, buf ^ 1); CP_COMMIT(); CP_WAIT(1); }
        else                   { CP_WAIT(0); }
        __syncthreads();
        u32 sA = sbase + buf * STGB4;
        u32 sB = sA + 2 * PLANE;
#pragma unroll
        for (int kk = 0; kk < 2; kk++) {
            u32 ah[2][4], am[2][4];
#pragma unroll
            for (int mt = 0; mt < 2; mt++) {
                ldsm4(ah[mt], sA + aoff + mt * (16 * RPAD) + kk * 32);
                ldsm4(am[mt], sA + PLANE + aoff + mt * (16 * RPAD) + kk * 32);
            }
            u32 bh[4][4], bm[4][4];
#pragma unroll
            for (int nt2 = 0; nt2 < 4; nt2++) {
                ldsm4(bh[nt2], sB + boff + nt2 * (16 * RPAD) + kk * 32);
                ldsm4(bm[nt2], sB + PLANE + boff + nt2 * (16 * RPAD) + kk * 32);
            }
#pragma unroll
            for (int mt = 0; mt < 2; mt++)
#pragma unroll
                for (int nt2 = 0; nt2 < 4; nt2++) {
                    mma16816(acc[mt][2 * nt2],     ah[mt], bh[nt2][0], bh[nt2][2]);
                    mma16816(acc[mt][2 * nt2 + 1], ah[mt], bh[nt2][1], bh[nt2][3]);
                    mma16816(acc[mt][2 * nt2],     ah[mt], bm[nt2][0], bm[nt2][2]);
                    mma16816(acc[mt][2 * nt2 + 1], ah[mt], bm[nt2][1], bm[nt2][3]);
                    mma16816(acc[mt][2 * nt2],     am[mt], bh[nt2][0], bh[nt2][2]);
                    mma16816(acc[mt][2 * nt2 + 1], am[mt], bh[nt2][1], bh[nt2][3]);
                }
        }
        __syncthreads();
    }

    u32* scol = (u32*)smem;
    if (tid < 128) scol[tid] = 0u;
    __syncthreads();

    // epilogue: store gelu(z) as TWO f16 planes (exact to 2^-22); max-z per cand
    const size_t PL = (size_t)SS * NC;
#pragma unroll
    for (int mt = 0; mt < 2; mt++)
#pragma unroll
        for (int nt = 0; nt < 8; nt++) {
            int row = s0 + wm * 32 + mt * 16 + (lid >> 2);
            int col = n0 + wn * 64 + nt * 8 + 2 * (lid & 3);
            float g0 = gelu_f(acc[mt][nt][0]), g1 = gelu_f(acc[mt][nt][1]);
            float g2 = gelu_f(acc[mt][nt][2]), g3 = gelu_f(acc[mt][nt][3]);
            H2U h01, m01, h23, m23;
            split2h(g0, h01.h[0], m01.h[0]); split2h(g1, h01.h[1], m01.h[1]);
            split2h(g2, h23.h[0], m23.h[0]); split2h(g3, h23.h[1], m23.h[1]);
            size_t base = ((size_t)(b * 2) * SS + row) * NC + col;
            *(u32*)(g_PC + base)               = h01.u;
            *(u32*)(g_PC + base + PL)          = m01.u;
            *(u32*)(g_PC + base + 8 * NC)      = h23.u;
            *(u32*)(g_PC + base + PL + 8 * NC) = m23.u;
        }
#pragma unroll
    for (int nt = 0; nt < 8; nt++) {
        float m0 = fmaxf(fmaxf(acc[0][nt][0], acc[0][nt][2]), fmaxf(acc[1][nt][0], acc[1][nt][2]));
        float m1 = fmaxf(fmaxf(acc[0][nt][1], acc[0][nt][3]), fmaxf(acc[1][nt][1], acc[1][nt][3]));
#pragma unroll
        for (int mk = 4; mk < 32; mk <<= 1) {
            m0 = fmaxf(m0, __shfl_xor_sync(0xffffffffu, m0, mk));
            m1 = fmaxf(m1, __shfl_xor_sync(0xffffffffu, m1, mk));
        }
        if (lid < 4) {
            atomicMax(&scol[wn * 64 + nt * 8 + 2 * lid],     fenc(m0));
            atomicMax(&scol[wn * 64 + nt * 8 + 2 * lid + 1], fenc(m1));
        }
    }
    __syncthreads();
    if (tid < 128) atomicMax(&g_scoreEnc2[b * NC + n0 + tid], scol[tid]);
}

// ---------------- K6: exact rescore + top-256 ----------------
__global__ void k_rescore() {
    __shared__ ull key[NCP];
    int b = blockIdx.x, tid = threadIdx.x;
    if (tid < NC) {
        float z = fdec(g_scoreEnc2[b * NC + tid]);
        int p = g_pidx512[b * NC + tid];
        float sc = gelu_f(z) * g_sig[b * NP + p];
        key[tid] = ((ull)fenc(sc) << 32) | (unsigned)tid;
    } else {
        key[tid] = 0ULL;
    }
    __syncthreads();
    for (int k = 2; k <= NCP; k <<= 1) {
        for (int j = k >> 1; j > 0; j >>= 1) {
            int i = tid;
            int ix = i ^ j;
            if (ix > i) {
                ull x = key[i], y = key[ix];
                bool desc = ((i & k) == 0);
                if (desc ? (x < y) : (x > y)) { key[i] = y; key[ix] = x; }
            }
            __syncthreads();
        }
    }
    if (tid < KSEL) {
        int slot = (int)(key[tid] & 0xffffffffu);
        g_cmap[b * KSEL + tid] = slot;
        g_pidx[b * KSEL + tid] = g_pidx512[b * NC + slot];
    }
}

// ---------------- K7: compact via smem staging ----------------
__global__ void k_compact() {
    __shared__ __half st[2][8][NC];
    __shared__ int cm[KSEL];
    int blk = blockIdx.x;
    int b = blk / (SS / 8);
    int s8 = (blk % (SS / 8)) * 8;
    int tid = threadIdx.x;
    if (tid < KSEL) cm[tid] = g_cmap[b * KSEL + tid];
    const int4* src0 = (const int4*)(g_PC + ((size_t)(b * 2)     * SS + s8) * NC);
    const int4* src1 = (const int4*)(g_PC + ((size_t)(b * 2 + 1) * SS + s8) * NC);
    int4* d0 = (int4*)&st[0][0][0];
    int4* d1 = (int4*)&st[1][0][0];
    const int NI4 = 8 * NC / 8;
    for (int idx = tid; idx < NI4; idx += 256) {
        d0[idx] = src0[idx];
        d1[idx] = src1[idx];
    }
    __syncthreads();
    int j = tid;
    int c = cm[j];
    const size_t PLa = (size_t)SS * KSEL;
#pragma unroll
    for (int r = 0; r < 8; r++) {
        size_t dst = ((size_t)(b * 2) * SS + s8 + r) * KSEL + j;
        g_PA[dst]       = st[0][r][c];
        g_PA[dst + PLa] = st[1][r][c];
    }
}

// ---------------- K8: gather + transpose proj rows -> f16 single plane ----------------
__global__ void k_projsplit(const float* __restrict__ proj) {
    __shared__ float t[32][33];
    __shared__ int pj[32];
    int j0 = blockIdx.x * 32, d0 = blockIdx.y * 32, b = blockIdx.z;
    int tx = threadIdx.x, ty = threadIdx.y;
    if (ty == 0) pj[tx] = g_pidx[b * KSEL + j0 + tx];
    __syncthreads();
#pragma unroll
    for (int i = 0; i < 32; i += 8) {
        int p = pj[ty + i];
        t[ty + i][tx] = proj[(size_t)p * DM + d0 + tx];
    }
    __syncthreads();
#pragma unroll
    for (int i = 0; i < 32; i += 8) {
        float v = t[tx][ty + i];
        g_Pr[((size_t)b * DM + d0 + ty + i) * KSEL + j0 + tx] = __float2half(v);
    }
}

// ---------------- K9: final GEMM (f16 2-pass: PAh*Pr + PAm*Pr) ----------------
__global__ __launch_bounds__(256)
void k_gemm3t(float* __restrict__ out) {
    extern __shared__ char smem[];
    const u32 sbase = smem_u32(smem);
    const int tid = threadIdx.x;
    const int wid = tid >> 5, lid = tid & 31;
    const int wm = wid & 3, wn = wid >> 2;
    const int b  = blockIdx.z;
    const int d0 = blockIdx.x * 128;
    const int s0 = blockIdx.y * 128;

    float acc[2][8][4];
#pragma unroll
    for (int i = 0; i < 2; i++)
#pragma unroll
        for (int j = 0; j < 8; j++)
#pragma unroll
            for (int r = 0; r < 4; r++) acc[i][j][r] = 0.0f;

    auto load_stage = [&](int ks, int buf) {
        const int k0 = ks * 32;
        u32 sg = sbase + buf * STG3;
#pragma unroll
        for (int i = 0; i < 4; i++) {   // PA: 2 planes, 1024 chunks
            int idx = tid + i * 256;
            int sp = idx >> 9, rem = idx & 511;
            int r = rem >> 2, c = rem & 3;
            const __half* g = g_PA + ((size_t)(b * 2 + sp) * SS + s0 + r) * KSEL + k0 + c * 8;
            cpasync16(sg + sp * PLANE + r * RPAD + c * 16, g);
        }
#pragma unroll
        for (int i = 0; i < 2; i++) {   // Pr: 1 plane, 512 chunks
            int idx = tid + i * 256;
            int r = idx >> 2, c = idx & 3;
            const __half* g = g_Pr + ((size_t)b * DM + d0 + r) * KSEL + k0 + c * 8;
            cpasync16(sg + 2 * PLANE + r * RPAD + c * 16, g);
        }
    };

    const u32 aoff = (u32)((wm * 32 + (lid & 15)) * RPAD + (lid >> 4) * 16);
    const u32 boff = (u32)((wn * 64 + (lid & 15)) * RPAD + (lid >> 4) * 16);

    load_stage(0, 0); CP_COMMIT();

#pragma unroll 1
    for (int ks = 0; ks < KSEL / 32; ks++) {
        int buf = ks & 1;
        if (ks < KSEL / 32 - 1) { load_stage(ks + 1, buf ^ 1); CP_COMMIT(); CP_WAIT(1); }
        else                    { CP_WAIT(0); }
        __syncthreads();
        u32 sA = sbase + buf * STG3;
        u32 sB = sA + 2 * PLANE;
#pragma unroll
        for (int kk = 0; kk < 2; kk++) {
            u32 ah[2][4], am[2][4];
#pragma unroll
            for (int mt = 0; mt < 2; mt++) {
                ldsm4(ah[mt], sA + aoff + mt * (16 * RPAD) + kk * 32);
                ldsm4(am[mt], sA + PLANE + aoff + mt * (16 * RPAD) + kk * 32);
            }
            u32 bh[4][4];
#pragma unroll
            for (int nt2 = 0; nt2 < 4; nt2++)
                ldsm4(bh[nt2], sB + boff + nt2 * (16 * RPAD) + kk * 32);
#pragma unroll
            for (int mt = 0; mt < 2; mt++)
#pragma unroll
                for (int nt2 = 0; nt2 < 4; nt2++) {
                    mma16816f(acc[mt][2 * nt2],     ah[mt], bh[nt2][0], bh[nt2][2]);
                    mma16816f(acc[mt][2 * nt2 + 1], ah[mt], bh[nt2][1], bh[nt2][3]);
                    mma16816f(acc[mt][2 * nt2],     am[mt], bh[nt2][0], bh[nt2][2]);
                    mma16816f(acc[mt][2 * nt2 + 1], am[mt], bh[nt2][1], bh[nt2][3]);
                }
        }
        __syncthreads();
    }
#pragma unroll
    for (int mt = 0; mt < 2; mt++)
#pragma unroll
        for (int nt = 0; nt < 8; nt++) {
            int row = s0 + wm * 32 + mt * 16 + (lid >> 2);
            int col = d0 + wn * 64 + nt * 8 + 2 * (lid & 3);
            float* po = out + ((size_t)b * SS + row) * DM + col;
            *(float2*)po            = make_float2(acc[mt][nt][0], acc[mt][nt][1]);
            *(float2*)(po + 8 * DM) = make_float2(acc[mt][nt][2], acc[mt][nt][3]);
        }
}

// ---------------- entry (multi-stream fork/join) ----------------
extern "C" void kernel_launch(void* const* d_in, const int* in_sizes, int n_in,
                              void* d_out, int out_size) {
    const float* act  = (const float*)d_in[0];
    const int*   sidx = (const int*)d_in[1];
    int o = (n_in >= 9 && in_sizes[2] == 1) ? 3 : 2;
    const float* cw   = (const float*)d_in[o + 0];
    const float* proj = (const float*)d_in[o + 1];
    const float* w1   = (const float*)d_in[o + 2];
    const float* b1   = (const float*)d_in[o + 3];
    const float* w2   = (const float*)d_in[o + 4];
    const float* b2   = (const float*)d_in[o + 5];
    float* out = (float*)d_out;

    static cudaStream_t s1 = nullptr;
    static cudaEvent_t ev0 = nullptr, evA = nullptr, ev1 = nullptr, ev2 = nullptr, ev3 = nullptr;
    if (s1 == nullptr) {
        cudaStreamCreateWithFlags(&s1, cudaStreamNonBlocking);
        cudaEventCreateWithFlags(&ev0, cudaEventDisableTiming);
        cudaEventCreateWithFlags(&evA, cudaEventDisableTiming);
        cudaEventCreateWithFlags(&ev1, cudaEventDisableTiming);
        cudaEventCreateWithFlags(&ev2, cudaEventDisableTiming);
        cudaEventCreateWithFlags(&ev3, cudaEventDisableTiming);
        cudaFuncSetAttribute(k_gemm1a, cudaFuncAttributeMaxDynamicSharedMemorySize, GSMEM1);
        cudaFuncSetAttribute(k_refine, cudaFuncAttributeMaxDynamicSharedMemorySize, GSMEM4);
        cudaFuncSetAttribute(k_gemm3t, cudaFuncAttributeMaxDynamicSharedMemorySize, GSMEM3);
    }

    // fork: f16 A (gemm1a dep), bf16 A planes (refine) + MLP chain on s1
    cudaEventRecord(ev0, 0);
    cudaStreamWaitEvent(s1, ev0, 0);
    k_splitAf16<<<(BB * SS * KIN / 4) / 256, 256, 0, s1>>>(act);
    cudaEventRecord(evA, s1);
    k_splitAh<<<(BB * SS * KIN / 4) / 256, 256, 0, s1>>>(act);
    k_splitAm<<<(BB * SS * KIN / 4) / 256, 256, 0, s1>>>(act);
    k_initMask<<<(BB * NIN + 255) / 256, 256, 0, s1>>>();
    k_scatter<<<(BB * KIN + 255) / 256, 256, 0, s1>>>(sidx);
    k_hidden<<<HID, 256, 0, s1>>>(w1, b1);
    k_relsig<<<NP / 8, 256, 0, s1>>>(w2, b2);
    cudaEventRecord(ev1, s1);

    // main chain
    k_initScore<<<(BB * NP + 255) / 256, 256>>>();
    k_gatherBh<<<NP, 256>>>(cw, sidx);
    cudaStreamWaitEvent(0, evA, 0);
    k_gemm1a<<<dim3(NP / 128, SS / 128, BB), 256, GSMEM1>>>();

    // join
    cudaStreamWaitEvent(0, ev1, 0);
    k_topkc<<<BB, 1024>>>();
    k_gatherBc<<<BB * NC, 256>>>(cw, sidx);
    k_refine<<<dim3(NC / 128, SS / 128, BB), 256, GSMEM4>>>();
    k_rescore<<<BB, NCP>>>();

    // fork: projsplit on s1, compact on main
    cudaEventRecord(ev2, 0);
    cudaStreamWaitEvent(s1, ev2, 0);
    k_projsplit<<<dim3(KSEL / 32, DM / 32, BB), dim3(32, 8), 0, s1>>>(proj);
    cudaEventRecord(ev3, s1);
    k_compact<<<BB * SS / 8, 256>>>();
    cudaStreamWaitEvent(0, ev3, 0);

    k_gemm3t<<<dim3(DM / 128, SS / 128, BB), 256, GSMEM3>>>(out);
}

// round 14
// speedup vs baseline: 1.6125x; 1.0426x over previous
#include <cuda_runtime.h>
#include <cuda_bf16.h>
#include <cuda_fp16.h>

#define BB   8
#define SS   2048
#define KIN  512
#define NIN  2048
#define NP   4096
#define HID  4096
#define DM   1024
#define KSEL 256
#define NC   384
#define NCP  512

typedef unsigned long long ull;
typedef unsigned int u32;

// ---------------- scratch ----------------
__device__ __align__(256) __nv_bfloat16 g_Asp[(size_t)BB * 2 * SS * KIN];
__device__ __align__(256) __half        g_Ah16[(size_t)BB * SS * KIN];
__device__ __align__(256) __half        g_Bh [(size_t)BB * NP * KIN];
__device__ __align__(256) __nv_bfloat16 g_Bc [(size_t)BB * 2 * NC * KIN];
__device__ __align__(256) __half        g_PC [(size_t)BB * 2 * SS * NC];
__device__ __align__(256) __half        g_PA [(size_t)BB * 2 * SS * KSEL];
__device__ __align__(256) __half        g_Pr [(size_t)BB * DM * KSEL];
__device__ float    g_mask[BB * NIN];
__device__ float    g_h[BB * HID];
__device__ float    g_sig[BB * NP];
__device__ unsigned g_scoreEnc[BB * NP];
__device__ unsigned g_scoreEnc2[BB * NC];
__device__ int      g_pidx512[BB * NC];
__device__ int      g_pidx[BB * KSEL];
__device__ int      g_cmap[BB * KSEL];

// ---------------- helpers ----------------
__device__ __forceinline__ unsigned fenc(float f) {
    unsigned u = __float_as_uint(f);
    return (u & 0x80000000u) ? ~u : (u | 0x80000000u);
}
__device__ __forceinline__ float fdec(unsigned u) {
    return __uint_as_float((u & 0x80000000u) ? (u & 0x7fffffffu) : ~u);
}
__device__ __forceinline__ float gelu_f(float x) {
    return 0.5f * x * (1.0f + erff(x * 0.70710678118654752f));
}
__device__ __forceinline__ u32 smem_u32(const void* p) {
    u32 a; asm("{ .reg .u64 t; cvta.to.shared.u64 t, %1; cvt.u32.u64 %0, t; }" : "=r"(a) : "l"(p));
    return a;
}
__device__ __forceinline__ void split2(float a, __nv_bfloat16& h, __nv_bfloat16& m) {
    h = __float2bfloat16(a);
    m = __float2bfloat16(a - __bfloat162float(h));
}
__device__ __forceinline__ void split2h(float a, __half& h, __half& m) {
    h = __float2half(a);
    m = __float2half(a - __half2float(h));
}

// ---------------- mma.sync / ldmatrix / cp.async ----------------
__device__ __forceinline__ void mma16816(float* d, const u32* a, u32 b0, u32 b1) {
    asm volatile("mma.sync.aligned.m16n8k16.row.col.f32.bf16.bf16.f32 "
        "{%0,%1,%2,%3}, {%4,%5,%6,%7}, {%8,%9}, {%0,%1,%2,%3};"
        : "+f"(d[0]), "+f"(d[1]), "+f"(d[2]), "+f"(d[3])
        : "r"(a[0]), "r"(a[1]), "r"(a[2]), "r"(a[3]), "r"(b0), "r"(b1));
}
__device__ __forceinline__ void mma16816f(float* d, const u32* a, u32 b0, u32 b1) {
    asm volatile("mma.sync.aligned.m16n8k16.row.col.f32.f16.f16.f32 "
        "{%0,%1,%2,%3}, {%4,%5,%6,%7}, {%8,%9}, {%0,%1,%2,%3};"
        : "+f"(d[0]), "+f"(d[1]), "+f"(d[2]), "+f"(d[3])
        : "r"(a[0]), "r"(a[1]), "r"(a[2]), "r"(a[3]), "r"(b0), "r"(b1));
}
__device__ __forceinline__ void mma16816h(u32* d, const u32* a, u32 b0, u32 b1) {
    asm volatile("mma.sync.aligned.m16n8k16.row.col.f16.f16.f16.f16 "
        "{%0,%1}, {%2,%3,%4,%5}, {%6,%7}, {%0,%1};"
        : "+r"(d[0]), "+r"(d[1])
        : "r"(a[0]), "r"(a[1]), "r"(a[2]), "r"(a[3]), "r"(b0), "r"(b1));
}
__device__ __forceinline__ void ldsm4(u32* r, u32 addr) {
    asm volatile("ldmatrix.sync.aligned.m8n8.x4.shared.b16 {%0,%1,%2,%3}, [%4];"
        : "=r"(r[0]), "=r"(r[1]), "=r"(r[2]), "=r"(r[3]) : "r"(addr));
}
__device__ __forceinline__ void cpasync16(u32 dst, const void* src) {
    asm volatile("cp.async.cg.shared.global [%0], [%1], 16;" :: "r"(dst), "l"(src));
}
#define CP_COMMIT() asm volatile("cp.async.commit_group;" ::: "memory")
#define CP_WAIT(n)  asm volatile("cp.async.wait_group %0;" :: "n"(n) : "memory")

#define RPAD   80
#define PLANE  (128 * RPAD)
#define STGB4  (4 * PLANE)
#define GSMEM4 (2 * STGB4)           // 81920 -> 2 CTAs/SM
#define STG1   (2 * PLANE)
#define GSMEM1 (2 * STG1)            // 40960
#define STG3   (3 * PLANE)
#define GSMEM3 (2 * STG3)            // 61440

// ---------------- init kernels ----------------
__global__ void k_initMask() {
    int t = blockIdx.x * blockDim.x + threadIdx.x;
    if (t < BB * NIN) g_mask[t] = 0.0f;
}
__global__ void k_initScore() {
    int t = blockIdx.x * blockDim.x + threadIdx.x;
    if (t < BB * NP)  g_scoreEnc[t] = 0u;
    if (t < BB * NC)  g_scoreEnc2[t] = 0u;
}
__global__ void k_scatter(const int* __restrict__ sidx) {
    int t = blockIdx.x * blockDim.x + threadIdx.x;
    if (t < BB * KIN) {
        int b = t >> 9;
        g_mask[b * NIN + sidx[t]] = 1.0f;
    }
}

// ---------------- merged A split: one read of act, three writes ----------------
union B4U { __nv_bfloat16 h[4]; ull u; };
union B2U { __nv_bfloat16 h[2]; u32 u; };
union H4U { __half h[4]; ull u; };
union H2U { __half h[2]; u32 u; };

__global__ void k_splitA(const float* __restrict__ act) {
    size_t t = (size_t)blockIdx.x * 256 + threadIdx.x;
    size_t bs = t >> 7;
    int k4 = (int)(t & 127);
    int b = (int)(bs >> 11), s = (int)(bs & 2047);
    float4 v = ((const float4*)act)[t];
    float vv[4] = { v.x, v.y, v.z, v.w };
    H4U f16; B4U hh, mm;
#pragma unroll
    for (int i = 0; i < 4; i++) {
        f16.h[i] = __float2half(vv[i]);
        hh.h[i] = __float2bfloat16(vv[i]);
        mm.h[i] = __float2bfloat16(vv[i] - __bfloat162float(hh.h[i]));
    }
    *(ull*)(g_Ah16 + t * 4) = f16.u;
    size_t base = ((size_t)(b * 2) * SS + s) * KIN + k4 * 4;
    const size_t PL = (size_t)SS * KIN;
    *(ull*)(g_Asp + base)      = hh.u;
    *(ull*)(g_Asp + base + PL) = mm.u;
}

// ---------------- gather B f16 (full 4096 rows) ----------------
__global__ void k_gatherBh(const float* __restrict__ cw, const int* __restrict__ sidx) {
    __shared__ float row[NIN];
    __shared__ int sidxS[BB * KIN];
    int p = blockIdx.x, tid = threadIdx.x;
    for (int i = tid; i < NIN; i += 256) row[i] = cw[(size_t)p * NIN + i];
    for (int i = tid; i < BB * KIN / 4; i += 256)
        ((int4*)sidxS)[i] = ((const int4*)sidx)[i];
    __syncthreads();
    int k = tid * 2;
#pragma unroll 1
    for (int b = 0; b < BB; b++) {
        int i0 = sidxS[b * KIN + k], i1 = sidxS[b * KIN + k + 1];
        H2U hh;
        hh.h[0] = __float2half(row[i0]);
        hh.h[1] = __float2half(row[i1]);
        *(u32*)(g_Bh + ((size_t)b * NP + p) * KIN + k) = hh.u;
    }
}

// ---------------- gather B splits for NC candidates ----------------
__global__ void k_gatherBc(const float* __restrict__ cw, const int* __restrict__ sidx) {
    __shared__ float row[NIN];
    int blk = blockIdx.x;
    int b = blk / NC, j = blk % NC;
    int tid = threadIdx.x;
    int p = g_pidx512[b * NC + j];
    for (int i = tid; i < NIN; i += 256) row[i] = cw[(size_t)p * NIN + i];
    __syncthreads();
    int k = tid * 2;
    int i0 = sidx[b * KIN + k], i1 = sidx[b * KIN + k + 1];
    B2U hh, mm;
    split2(row[i0], hh.h[0], mm.h[0]);
    split2(row[i1], hh.h[1], mm.h[1]);
    const size_t PL = (size_t)NC * KIN;
    size_t base = ((size_t)(b * 2) * NC + j) * KIN + k;
    *(u32*)(g_Bc + base)      = hh.u;
    *(u32*)(g_Bc + base + PL) = mm.u;
}

// ---------------- K1a: approx score GEMM, f16 acc, 128x128 tile ----------------
__global__ __launch_bounds__(256, 2)
void k_gemm1a() {
    extern __shared__ char smem[];
    const u32 sbase = smem_u32(smem);
    const int tid = threadIdx.x;
    const int wid = tid >> 5, lid = tid & 31;
    const int wm = wid & 3, wn = wid >> 2;
    const int b  = blockIdx.z;
    const int p0 = blockIdx.x * 128;
    const int s0 = blockIdx.y * 128;

    u32 acc[2][8][2];
#pragma unroll
    for (int i = 0; i < 2; i++)
#pragma unroll
        for (int j = 0; j < 8; j++) { acc[i][j][0] = 0u; acc[i][j][1] = 0u; }

    auto load_stage = [&](int ks, int buf) {
        const int k0 = ks * 32;
        u32 sgA = sbase + buf * STG1;
        u32 sgB = sgA + PLANE;
#pragma unroll
        for (int i = 0; i < 2; i++) {
            int idx = tid + i * 256;
            int r = idx >> 2, c = idx & 3;
            const __half* g = g_Ah16 + ((size_t)b * SS + s0 + r) * KIN + k0 + c * 8;
            cpasync16(sgA + r * RPAD + c * 16, g);
        }
#pragma unroll
        for (int i = 0; i < 2; i++) {
            int idx = tid + i * 256;
            int r = idx >> 2, c = idx & 3;
            const __half* g = g_Bh + ((size_t)b * NP + p0 + r) * KIN + k0 + c * 8;
            cpasync16(sgB + r * RPAD + c * 16, g);
        }
    };

    const u32 aoff = (u32)((wm * 32 + (lid & 15)) * RPAD + (lid >> 4) * 16);
    const u32 boff = (u32)((wn * 64 + (lid & 15)) * RPAD + (lid >> 4) * 16);

    load_stage(0, 0); CP_COMMIT();

#pragma unroll 1
    for (int ks = 0; ks < KIN / 32; ks++) {
        int buf = ks & 1;
        if (ks < KIN / 32 - 1) { load_stage(ks + 1, buf ^ 1); CP_COMMIT(); CP_WAIT(1); }
        else                   { CP_WAIT(0); }
        __syncthreads();
        u32 sA = sbase + buf * STG1;
        u32 sB = sA + PLANE;
#pragma unroll
        for (int kk = 0; kk < 2; kk++) {
            u32 ah[2][4];
#pragma unroll
            for (int mt = 0; mt < 2; mt++)
                ldsm4(ah[mt], sA + aoff + mt * (16 * RPAD) + kk * 32);
            u32 bh[4][4];
#pragma unroll
            for (int q = 0; q < 4; q++)
                ldsm4(bh[q], sB + boff + q * (16 * RPAD) + kk * 32);
#pragma unroll
            for (int mt = 0; mt < 2; mt++)
#pragma unroll
                for (int q = 0; q < 4; q++) {
                    mma16816h(acc[mt][2 * q],     ah[mt], bh[q][0], bh[q][2]);
                    mma16816h(acc[mt][2 * q + 1], ah[mt], bh[q][1], bh[q][3]);
                }
        }
        __syncthreads();
    }

    u32* scol = (u32*)smem;
    if (tid < 128) scol[tid] = 0u;
    __syncthreads();
#pragma unroll
    for (int nt = 0; nt < 8; nt++) {
        float m0 = -1e30f, m1 = -1e30f;
#pragma unroll
        for (int mt = 0; mt < 2; mt++) {
            float2 lo = __half22float2(*(const __half2*)&acc[mt][nt][0]);
            float2 hi = __half22float2(*(const __half2*)&acc[mt][nt][1]);
            m0 = fmaxf(m0, fmaxf(lo.x, hi.x));
            m1 = fmaxf(m1, fmaxf(lo.y, hi.y));
        }
#pragma unroll
        for (int mk = 4; mk < 32; mk <<= 1) {
            m0 = fmaxf(m0, __shfl_xor_sync(0xffffffffu, m0, mk));
            m1 = fmaxf(m1, __shfl_xor_sync(0xffffffffu, m1, mk));
        }
        if (lid < 4) {
            atomicMax(&scol[wn * 64 + nt * 8 + 2 * lid],     fenc(m0));
            atomicMax(&scol[wn * 64 + nt * 8 + 2 * lid + 1], fenc(m1));
        }
    }
    __syncthreads();
    if (tid < 128) atomicMax(&g_scoreEnc[b * NP + p0 + tid], scol[tid]);
}

// ---------------- K2: hidden MLP — mask staged in smem, warp per j-row ----------------
__global__ __launch_bounds__(256)
void k_hidden(const float* __restrict__ w1, const float* __restrict__ b1) {
    extern __shared__ float ms[];             // [BB][NIN] = 64 KB
    int tid = threadIdx.x, warp = tid >> 5, lane = tid & 31;
    // stage mask (16384 floats = 4096 float4)
    for (int i = tid; i < BB * NIN / 4; i += 256)
        ((float4*)ms)[i] = ((const float4*)g_mask)[i];
    __syncthreads();
    int j = blockIdx.x * 8 + warp;
    const float4* wr = (const float4*)(w1 + (size_t)j * NIN);
    float acc[BB];
#pragma unroll
    for (int b = 0; b < BB; b++) acc[b] = 0.0f;
#pragma unroll
    for (int it = 0; it < NIN / 128; it++) {  // 16 iters
        int q = lane + it * 32;
        float4 w = wr[q];
#pragma unroll
        for (int b = 0; b < BB; b++) {
            float4 m = ((const float4*)(ms + b * NIN))[q];
            acc[b] += w.x * m.x + w.y * m.y + w.z * m.z + w.w * m.w;
        }
    }
#pragma unroll
    for (int o = 16; o > 0; o >>= 1)
#pragma unroll
        for (int b = 0; b < BB; b++) acc[b] += __shfl_down_sync(0xffffffffu, acc[b], o);
    if (lane < BB) {
        float v = __shfl_sync(0xffffffffu, acc[lane], 0);
        // broadcast trick fails for array; do simple: lane 0 writes all
    }
    if (lane == 0) {
        float bj = b1[j];
#pragma unroll
        for (int b = 0; b < BB; b++) g_h[b * HID + j] = gelu_f(acc[b] + bj);
    }
}

// ---------------- K3a: relevance -> sigmoid — h staged in smem ----------------
__global__ __launch_bounds__(256)
void k_relsig(const float* __restrict__ w2, const float* __restrict__ b2) {
    __shared__ float hs[BB][1024];            // 32 KB per chunk
    int tid = threadIdx.x, warp = tid >> 5, lane = tid & 31;
    int pbase = blockIdx.x * 32;              // 128 blocks x 32 p
    float acc[4][BB];
#pragma unroll
    for (int pp = 0; pp < 4; pp++)
#pragma unroll
        for (int b = 0; b < BB; b++) acc[pp][b] = 0.0f;

#pragma unroll 1
    for (int ch = 0; ch < HID / 1024; ch++) { // 4 chunks
        int n0 = ch * 1024;
        // stage h chunk: 8 b x 1024 = 2048 float4
        for (int i = tid; i < BB * 1024 / 4; i += 256) {
            int b = i >> 8, q = i & 255;
            ((float4*)(hs[b]))[q] = ((const float4*)(g_h + b * HID + n0))[q];
        }
        __syncthreads();
#pragma unroll
        for (int pp = 0; pp < 4; pp++) {
            int p = pbase + warp * 4 + pp;
            const float4* wr = (const float4*)(w2 + (size_t)p * HID + n0);
#pragma unroll
            for (int it = 0; it < 8; it++) {  // 1024/4/32
                int q = lane + it * 32;
                float4 w = wr[q];
#pragma unroll
                for (int b = 0; b < BB; b++) {
                    float4 h = ((const float4*)(hs[b]))[q];
                    acc[pp][b] += w.x * h.x + w.y * h.y + w.z * h.z + w.w * h.w;
                }
            }
        }
        __syncthreads();
    }
#pragma unroll
    for (int o = 16; o > 0; o >>= 1)
#pragma unroll
        for (int pp = 0; pp < 4; pp++)
#pragma unroll
            for (int b = 0; b < BB; b++)
                acc[pp][b] += __shfl_down_sync(0xffffffffu, acc[pp][b], o);
    if (lane == 0) {
#pragma unroll
        for (int pp = 0; pp < 4; pp++) {
            int p = pbase + warp * 4 + pp;
            float bp = b2[p];
#pragma unroll
            for (int b = 0; b < BB; b++) {
                float rel = acc[pp][b] + bp;
                g_sig[b * NP + p] = 1.0f / (1.0f + expf(-rel));
            }
        }
    }
}

// ---------------- K4: approx top-NC ----------------
__global__ void k_topkc() {
    __shared__ ull key[NP];
    int b = blockIdx.x, tid = threadIdx.x;
    for (int i = tid; i < NP; i += 1024) {
        float sc = gelu_f(fdec(g_scoreEnc[b * NP + i])) * g_sig[b * NP + i];
        key[i] = ((ull)fenc(sc) << 32) | (unsigned)i;
    }
    __syncthreads();
    for (int k = 2; k <= NP; k <<= 1) {
        for (int j = k >> 1; j > 0; j >>= 1) {
            for (int i = tid; i < NP; i += 1024) {
                int ix = i ^ j;
                if (ix > i) {
                    ull x = key[i], y = key[ix];
                    bool desc = ((i & k) == 0);
                    if (desc ? (x < y) : (x > y)) { key[i] = y; key[ix] = x; }
                }
            }
            __syncthreads();
        }
    }
    if (tid < NC) g_pidx512[b * NC + tid] = (int)(key[tid] & 0xffffffffu);
}

// ---------------- K5: refine — exact 3-pass bf16 z for NC cands ----------------
__global__ __launch_bounds__(256)
void k_refine() {
    extern __shared__ char smem[];
    const u32 sbase = smem_u32(smem);
    const int tid = threadIdx.x;
    const int wid = tid >> 5, lid = tid & 31;
    const int wm = wid & 3, wn = wid >> 2;
    const int b  = blockIdx.z;
    const int n0 = blockIdx.x * 128;
    const int s0 = blockIdx.y * 128;

    float acc[2][8][4];
#pragma unroll
    for (int i = 0; i < 2; i++)
#pragma unroll
        for (int j = 0; j < 8; j++)
#pragma unroll
            for (int r = 0; r < 4; r++) acc[i][j][r] = 0.0f;

    auto load_stage = [&](int ks, int buf) {
        const int k0 = ks * 32;
        u32 sg = sbase + buf * STGB4;
#pragma unroll
        for (int i = 0; i < 4; i++) {
            int idx = tid + i * 256;
            int sp = idx >> 9, rem = idx & 511;
            int r = rem >> 2, c = rem & 3;
            const __nv_bfloat16* g = g_Asp + ((size_t)(b * 2 + sp) * SS + s0 + r) * KIN + k0 + c * 8;
            cpasync16(sg + sp * PLANE + r * RPAD + c * 16, g);
        }
#pragma unroll
        for (int i = 0; i < 4; i++) {
            int idx = tid + i * 256;
            int sp = idx >> 9, rem = idx & 511;
            int r = rem >> 2, c = rem & 3;
            const __nv_bfloat16* g = g_Bc + ((size_t)(b * 2 + sp) * NC + n0 + r) * KIN + k0 + c * 8;
            cpasync16(sg + 2 * PLANE + sp * PLANE + r * RPAD + c * 16, g);
        }
    };

    const u32 aoff = (u32)((wm * 32 + (lid & 15)) * RPAD + (lid >> 4) * 16);
    const u32 boff = (u32)((wn * 64 + (lid & 15)) * RPAD + (lid >> 4) * 16);

    load_stage(0, 0); CP_COMMIT();

#pragma unroll 1
    for (int ks = 0; ks < KIN / 32; ks++) {
        int buf = ks & 1;
        if (ks < KIN / 32 - 1) { load_stage(ks + 1, buf ^ 1); CP_COMMIT(); CP_WAIT(1); }
        else                   { CP_WAIT(0); }
        __syncthreads();
        u32 sA = sbase + buf * STGB4;
        u32 sB = sA + 2 * PLANE;
#pragma unroll
        for (int kk = 0; kk < 2; kk++) {
            u32 ah[2][4], am[2][4];
#pragma unroll
            for (int mt = 0; mt < 2; mt++) {
                ldsm4(ah[mt], sA + aoff + mt * (16 * RPAD) + kk * 32);
                ldsm4(am[mt], sA + PLANE + aoff + mt * (16 * RPAD) + kk * 32);
            }
            u32 bh[4][4], bm[4][4];
#pragma unroll
            for (int nt2 = 0; nt2 < 4; nt2++) {
                ldsm4(bh[nt2], sB + boff + nt2 * (16 * RPAD) + kk * 32);
                ldsm4(bm[nt2], sB + PLANE + boff + nt2 * (16 * RPAD) + kk * 32);
            }
#pragma unroll
            for (int mt = 0; mt < 2; mt++)
#pragma unroll
                for (int nt2 = 0; nt2 < 4; nt2++) {
                    mma16816(acc[mt][2 * nt2],     ah[mt], bh[nt2][0], bh[nt2][2]);
                    mma16816(acc[mt][2 * nt2 + 1], ah[mt], bh[nt2][1], bh[nt2][3]);
                    mma16816(acc[mt][2 * nt2],     ah[mt], bm[nt2][0], bm[nt2][2]);
                    mma16816(acc[mt][2 * nt2 + 1], ah[mt], bm[nt2][1], bm[nt2][3]);
                    mma16816(acc[mt][2 * nt2],     am[mt], bh[nt2][0], bh[nt2][2]);
                    mma16816(acc[mt][2 * nt2 + 1], am[mt], bh[nt2][1], bh[nt2][3]);
                }
        }
        __syncthreads();
    }

    u32* scol = (u32*)smem;
    if (tid < 128) scol[tid] = 0u;
    __syncthreads();

    const size_t PL = (size_t)SS * NC;
#pragma unroll
    for (int mt = 0; mt < 2; mt++)
#pragma unroll
        for (int nt = 0; nt < 8; nt++) {
            int row = s0 + wm * 32 + mt * 16 + (lid >> 2);
            int col = n0 + wn * 64 + nt * 8 + 2 * (lid & 3);
            float g0 = gelu_f(acc[mt][nt][0]), g1 = gelu_f(acc[mt][nt][1]);
            float g2 = gelu_f(acc[mt][nt][2]), g3 = gelu_f(acc[mt][nt][3]);
            H2U h01, m01, h23, m23;
            split2h(g0, h01.h[0], m01.h[0]); split2h(g1, h01.h[1], m01.h[1]);
            split2h(g2, h23.h[0], m23.h[0]); split2h(g3, h23.h[1], m23.h[1]);
            size_t base = ((size_t)(b * 2) * SS + row) * NC + col;
            *(u32*)(g_PC + base)               = h01.u;
            *(u32*)(g_PC + base + PL)          = m01.u;
            *(u32*)(g_PC + base + 8 * NC)      = h23.u;
            *(u32*)(g_PC + base + PL + 8 * NC) = m23.u;
        }
#pragma unroll
    for (int nt = 0; nt < 8; nt++) {
        float m0 = fmaxf(fmaxf(acc[0][nt][0], acc[0][nt][2]), fmaxf(acc[1][nt][0], acc[1][nt][2]));
        float m1 = fmaxf(fmaxf(acc[0][nt][1], acc[0][nt][3]), fmaxf(acc[1][nt][1], acc[1][nt][3]));
#pragma unroll
        for (int mk = 4; mk < 32; mk <<= 1) {
            m0 = fmaxf(m0, __shfl_xor_sync(0xffffffffu, m0, mk));
            m1 = fmaxf(m1, __shfl_xor_sync(0xffffffffu, m1, mk));
        }
        if (lid < 4) {
            atomicMax(&scol[wn * 64 + nt * 8 + 2 * lid],     fenc(m0));
            atomicMax(&scol[wn * 64 + nt * 8 + 2 * lid + 1], fenc(m1));
        }
    }
    __syncthreads();
    if (tid < 128) atomicMax(&g_scoreEnc2[b * NC + n0 + tid], scol[tid]);
}

// ---------------- K6: exact rescore + top-256 ----------------
__global__ void k_rescore() {
    __shared__ ull key[NCP];
    int b = blockIdx.x, tid = threadIdx.x;
    if (tid < NC) {
        float z = fdec(g_scoreEnc2[b * NC + tid]);
        int p = g_pidx512[b * NC + tid];
        float sc = gelu_f(z) * g_sig[b * NP + p];
        key[tid] = ((ull)fenc(sc) << 32) | (unsigned)tid;
    } else {
        key[tid] = 0ULL;
    }
    __syncthreads();
    for (int k = 2; k <= NCP; k <<= 1) {
        for (int j = k >> 1; j > 0; j >>= 1) {
            int i = tid;
            int ix = i ^ j;
            if (ix > i) {
                ull x = key[i], y = key[ix];
                bool desc = ((i & k) == 0);
                if (desc ? (x < y) : (x > y)) { key[i] = y; key[ix] = x; }
            }
            __syncthreads();
        }
    }
    if (tid < KSEL) {
        int slot = (int)(key[tid] & 0xffffffffu);
        g_cmap[b * KSEL + tid] = slot;
        g_pidx[b * KSEL + tid] = g_pidx512[b * NC + slot];
    }
}

// ---------------- K7: compact via smem staging ----------------
__global__ void k_compact() {
    __shared__ __half st[2][8][NC];
    __shared__ int cm[KSEL];
    int blk = blockIdx.x;
    int b = blk / (SS / 8);
    int s8 = (blk % (SS / 8)) * 8;
    int tid = threadIdx.x;
    if (tid < KSEL) cm[tid] = g_cmap[b * KSEL + tid];
    const int4* src0 = (const int4*)(g_PC + ((size_t)(b * 2)     * SS + s8) * NC);
    const int4* src1 = (const int4*)(g_PC + ((size_t)(b * 2 + 1) * SS + s8) * NC);
    int4* d0 = (int4*)&st[0][0][0];
    int4* d1 = (int4*)&st[1][0][0];
    const int NI4 = 8 * NC / 8;
    for (int idx = tid; idx < NI4; idx += 256) {
        d0[idx] = src0[idx];
        d1[idx] = src1[idx];
    }
    __syncthreads();
    int j = tid;
    int c = cm[j];
    const size_t PLa = (size_t)SS * KSEL;
#pragma unroll
    for (int r = 0; r < 8; r++) {
        size_t dst = ((size_t)(b * 2) * SS + s8 + r) * KSEL + j;
        g_PA[dst]       = st[0][r][c];
        g_PA[dst + PLa] = st[1][r][c];
    }
}

// ---------------- K8: gather + transpose proj rows -> f16 single plane ----------------
__global__ void k_projsplit(const float* __restrict__ proj) {
    __shared__ float t[32][33];
    __shared__ int pj[32];
    int j0 = blockIdx.x * 32, d0 = blockIdx.y * 32, b = blockIdx.z;
    int tx = threadIdx.x, ty = threadIdx.y;
    if (ty == 0) pj[tx] = g_pidx[b * KSEL + j0 + tx];
    __syncthreads();
#pragma unroll
    for (int i = 0; i < 32; i += 8) {
        int p = pj[ty + i];
        t[ty + i][tx] = proj[(size_t)p * DM + d0 + tx];
    }
    __syncthreads();
#pragma unroll
    for (int i = 0; i < 32; i += 8) {
        float v = t[tx][ty + i];
        g_Pr[((size_t)b * DM + d0 + ty + i) * KSEL + j0 + tx] = __float2half(v);
    }
}

// ---------------- K9: final GEMM (f16 2-pass) ----------------
__global__ __launch_bounds__(256)
void k_gemm3t(float* __restrict__ out) {
    extern __shared__ char smem[];
    const u32 sbase = smem_u32(smem);
    const int tid = threadIdx.x;
    const int wid = tid >> 5, lid = tid & 31;
    const int wm = wid & 3, wn = wid >> 2;
    const int b  = blockIdx.z;
    const int d0 = blockIdx.x * 128;
    const int s0 = blockIdx.y * 128;

    float acc[2][8][4];
#pragma unroll
    for (int i = 0; i < 2; i++)
#pragma unroll
        for (int j = 0; j < 8; j++)
#pragma unroll
            for (int r = 0; r < 4; r++) acc[i][j][r] = 0.0f;

    auto load_stage = [&](int ks, int buf) {
        const int k0 = ks * 32;
        u32 sg = sbase + buf * STG3;
#pragma unroll
        for (int i = 0; i < 4; i++) {
            int idx = tid + i * 256;
            int sp = idx >> 9, rem = idx & 511;
            int r = rem >> 2, c = rem & 3;
            const __half* g = g_PA + ((size_t)(b * 2 + sp) * SS + s0 + r) * KSEL + k0 + c * 8;
            cpasync16(sg + sp * PLANE + r * RPAD + c * 16, g);
        }
#pragma unroll
        for (int i = 0; i < 2; i++) {
            int idx = tid + i * 256;
            int r = idx >> 2, c = idx & 3;
            const __half* g = g_Pr + ((size_t)b * DM + d0 + r) * KSEL + k0 + c * 8;
            cpasync16(sg + 2 * PLANE + r * RPAD + c * 16, g);
        }
    };

    const u32 aoff = (u32)((wm * 32 + (lid & 15)) * RPAD + (lid >> 4) * 16);
    const u32 boff = (u32)((wn * 64 + (lid & 15)) * RPAD + (lid >> 4) * 16);

    load_stage(0, 0); CP_COMMIT();

#pragma unroll 1
    for (int ks = 0; ks < KSEL / 32; ks++) {
        int buf = ks & 1;
        if (ks < KSEL / 32 - 1) { load_stage(ks + 1, buf ^ 1); CP_COMMIT(); CP_WAIT(1); }
        else                    { CP_WAIT(0); }
        __syncthreads();
        u32 sA = sbase + buf * STG3;
        u32 sB = sA + 2 * PLANE;
#pragma unroll
        for (int kk = 0; kk < 2; kk++) {
            u32 ah[2][4], am[2][4];
#pragma unroll
            for (int mt = 0; mt < 2; mt++) {
                ldsm4(ah[mt], sA + aoff + mt * (16 * RPAD) + kk * 32);
                ldsm4(am[mt], sA + PLANE + aoff + mt * (16 * RPAD) + kk * 32);
            }
            u32 bh[4][4];
#pragma unroll
            for (int nt2 = 0; nt2 < 4; nt2++)
                ldsm4(bh[nt2], sB + boff + nt2 * (16 * RPAD) + kk * 32);
#pragma unroll
            for (int mt = 0; mt < 2; mt++)
#pragma unroll
                for (int nt2 = 0; nt2 < 4; nt2++) {
                    mma16816f(acc[mt][2 * nt2],     ah[mt], bh[nt2][0], bh[nt2][2]);
                    mma16816f(acc[mt][2 * nt2 + 1], ah[mt], bh[nt2][1], bh[nt2][3]);
                    mma16816f(acc[mt][2 * nt2],     am[mt], bh[nt2][0], bh[nt2][2]);
                    mma16816f(acc[mt][2 * nt2 + 1], am[mt], bh[nt2][1], bh[nt2][3]);
                }
        }
        __syncthreads();
    }
#pragma unroll
    for (int mt = 0; mt < 2; mt++)
#pragma unroll
        for (int nt = 0; nt < 8; nt++) {
            int row = s0 + wm * 32 + mt * 16 + (lid >> 2);
            int col = d0 + wn * 64 + nt * 8 + 2 * (lid & 3);
            float* po = out + ((size_t)b * SS + row) * DM + col;
            *(float2*)po            = make_float2(acc[mt][nt][0], acc[mt][nt][1]);
            *(float2*)(po + 8 * DM) = make_float2(acc[mt][nt][2], acc[mt][nt][3]);
        }
}

// ---------------- entry (multi-stream fork/join) ----------------
extern "C" void kernel_launch(void* const* d_in, const int* in_sizes, int n_in,
                              void* d_out, int out_size) {
    const float* act  = (const float*)d_in[0];
    const int*   sidx = (const int*)d_in[1];
    int o = (n_in >= 9 && in_sizes[2] == 1) ? 3 : 2;
    const float* cw   = (const float*)d_in[o + 0];
    const float* proj = (const float*)d_in[o + 1];
    const float* w1   = (const float*)d_in[o + 2];
    const float* b1   = (const float*)d_in[o + 3];
    const float* w2   = (const float*)d_in[o + 4];
    const float* b2   = (const float*)d_in[o + 5];
    float* out = (float*)d_out;

    static cudaStream_t s1 = nullptr;
    static cudaEvent_t ev0 = nullptr, evA = nullptr, ev1 = nullptr, ev2 = nullptr, ev3 = nullptr;
    if (s1 == nullptr) {
        cudaStreamCreateWithFlags(&s1, cudaStreamNonBlocking);
        cudaEventCreateWithFlags(&ev0, cudaEventDisableTiming);
        cudaEventCreateWithFlags(&evA, cudaEventDisableTiming);
        cudaEventCreateWithFlags(&ev1, cudaEventDisableTiming);
        cudaEventCreateWithFlags(&ev2, cudaEventDisableTiming);
        cudaEventCreateWithFlags(&ev3, cudaEventDisableTiming);
        cudaFuncSetAttribute(k_gemm1a, cudaFuncAttributeMaxDynamicSharedMemorySize, GSMEM1);
        cudaFuncSetAttribute(k_refine, cudaFuncAttributeMaxDynamicSharedMemorySize, GSMEM4);
        cudaFuncSetAttribute(k_gemm3t, cudaFuncAttributeMaxDynamicSharedMemorySize, GSMEM3);
        cudaFuncSetAttribute(k_hidden, cudaFuncAttributeMaxDynamicSharedMemorySize, BB * NIN * 4);
    }

    // fork: merged A split + MLP chain on s1
    cudaEventRecord(ev0, 0);
    cudaStreamWaitEvent(s1, ev0, 0);
    k_splitA<<<(BB * SS * KIN / 4) / 256, 256, 0, s1>>>(act);
    cudaEventRecord(evA, s1);
    k_initMask<<<(BB * NIN + 255) / 256, 256, 0, s1>>>();
    k_scatter<<<(BB * KIN + 255) / 256, 256, 0, s1>>>(sidx);
    k_hidden<<<HID / 8, 256, BB * NIN * 4, s1>>>(w1, b1);
    k_relsig<<<NP / 32, 256, 0, s1>>>(w2, b2);
    cudaEventRecord(ev1, s1);

    // main chain
    k_initScore<<<(BB * NP + 255) / 256, 256>>>();
    k_gatherBh<<<NP, 256>>>(cw, sidx);
    cudaStreamWaitEvent(0, evA, 0);
    k_gemm1a<<<dim3(NP / 128, SS / 128, BB), 256, GSMEM1>>>();

    // join
    cudaStreamWaitEvent(0, ev1, 0);
    k_topkc<<<BB, 1024>>>();
    k_gatherBc<<<BB * NC, 256>>>(cw, sidx);
    k_refine<<<dim3(NC / 128, SS / 128, BB), 256, GSMEM4>>>();
    k_rescore<<<BB, NCP>>>();

    // fork: projsplit on s1, compact on main
    cudaEventRecord(ev2, 0);
    cudaStreamWaitEvent(s1, ev2, 0);
    k_projsplit<<<dim3(KSEL / 32, DM / 32, BB), dim3(32, 8), 0, s1>>>(proj);
    cudaEventRecord(ev3, s1);
    k_compact<<<BB * SS / 8, 256>>>();
    cudaStreamWaitEvent(0, ev3, 0);

    k_gemm3t<<<dim3(DM / 128, SS / 128, BB), 256, GSMEM3>>>(out);
}

// round 15
// speedup vs baseline: 1.6251x; 1.0078x over previous
#include <cuda_runtime.h>
#include <cuda_bf16.h>
#include <cuda_fp16.h>

#define BB   8
#define SS   2048
#define KIN  512
#define NIN  2048
#define NP   4096
#define HID  4096
#define DM   1024
#define KSEL 256
#define NC   384
#define NCP  512

typedef unsigned long long ull;
typedef unsigned int u32;

// ---------------- scratch ----------------
__device__ __align__(256) __nv_bfloat16 g_Asp[(size_t)BB * 2 * SS * KIN];
__device__ __align__(256) __half        g_Ah16[(size_t)BB * SS * KIN];
__device__ __align__(256) __half        g_Bh [(size_t)BB * NP * KIN];
__device__ __align__(256) __nv_bfloat16 g_Bc [(size_t)BB * 2 * NC * KIN];
__device__ __align__(256) __half        g_PC [(size_t)BB * 2 * SS * NC];
__device__ __align__(256) __half        g_PA [(size_t)BB * 2 * SS * KSEL];
__device__ __align__(256) __half        g_Pr [(size_t)BB * DM * KSEL];
__device__ float    g_mask[BB * NIN];
__device__ float    g_h[BB * HID];
__device__ float    g_sig[BB * NP];
__device__ unsigned g_scoreEnc[BB * NP];
__device__ unsigned g_scoreEnc2[BB * NC];
__device__ int      g_pidx512[BB * NC];
__device__ int      g_pidx[BB * KSEL];
__device__ int      g_cmap[BB * KSEL];

// ---------------- helpers ----------------
__device__ __forceinline__ unsigned fenc(float f) {
    unsigned u = __float_as_uint(f);
    return (u & 0x80000000u) ? ~u : (u | 0x80000000u);
}
__device__ __forceinline__ float fdec(unsigned u) {
    return __uint_as_float((u & 0x80000000u) ? (u & 0x7fffffffu) : ~u);
}
__device__ __forceinline__ float gelu_f(float x) {
    return 0.5f * x * (1.0f + erff(x * 0.70710678118654752f));
}
__device__ __forceinline__ u32 smem_u32(const void* p) {
    u32 a; asm("{ .reg .u64 t; cvta.to.shared.u64 t, %1; cvt.u32.u64 %0, t; }" : "=r"(a) : "l"(p));
    return a;
}
__device__ __forceinline__ void split2(float a, __nv_bfloat16& h, __nv_bfloat16& m) {
    h = __float2bfloat16(a);
    m = __float2bfloat16(a - __bfloat162float(h));
}
__device__ __forceinline__ void split2h(float a, __half& h, __half& m) {
    h = __float2half(a);
    m = __float2half(a - __half2float(h));
}

// ---------------- mma.sync / ldmatrix / cp.async ----------------
__device__ __forceinline__ void mma16816(float* d, const u32* a, u32 b0, u32 b1) {
    asm volatile("mma.sync.aligned.m16n8k16.row.col.f32.bf16.bf16.f32 "
        "{%0,%1,%2,%3}, {%4,%5,%6,%7}, {%8,%9}, {%0,%1,%2,%3};"
        : "+f"(d[0]), "+f"(d[1]), "+f"(d[2]), "+f"(d[3])
        : "r"(a[0]), "r"(a[1]), "r"(a[2]), "r"(a[3]), "r"(b0), "r"(b1));
}
__device__ __forceinline__ void mma16816f(float* d, const u32* a, u32 b0, u32 b1) {
    asm volatile("mma.sync.aligned.m16n8k16.row.col.f32.f16.f16.f32 "
        "{%0,%1,%2,%3}, {%4,%5,%6,%7}, {%8,%9}, {%0,%1,%2,%3};"
        : "+f"(d[0]), "+f"(d[1]), "+f"(d[2]), "+f"(d[3])
        : "r"(a[0]), "r"(a[1]), "r"(a[2]), "r"(a[3]), "r"(b0), "r"(b1));
}
__device__ __forceinline__ void mma16816h(u32* d, const u32* a, u32 b0, u32 b1) {
    asm volatile("mma.sync.aligned.m16n8k16.row.col.f16.f16.f16.f16 "
        "{%0,%1}, {%2,%3,%4,%5}, {%6,%7}, {%0,%1};"
        : "+r"(d[0]), "+r"(d[1])
        : "r"(a[0]), "r"(a[1]), "r"(a[2]), "r"(a[3]), "r"(b0), "r"(b1));
}
__device__ __forceinline__ void ldsm4(u32* r, u32 addr) {
    asm volatile("ldmatrix.sync.aligned.m8n8.x4.shared.b16 {%0,%1,%2,%3}, [%4];"
        : "=r"(r[0]), "=r"(r[1]), "=r"(r[2]), "=r"(r[3]) : "r"(addr));
}
__device__ __forceinline__ void cpasync16(u32 dst, const void* src) {
    asm volatile("cp.async.cg.shared.global [%0], [%1], 16;" :: "r"(dst), "l"(src));
}
#define CP_COMMIT() asm volatile("cp.async.commit_group;" ::: "memory")
#define CP_WAIT(n)  asm volatile("cp.async.wait_group %0;" :: "n"(n) : "memory")

#define RPAD   80
#define PLANE  (128 * RPAD)          // 10240
#define BPLANE (256 * RPAD)          // 20480
#define STGB4  (4 * PLANE)
#define GSMEM4 (2 * STGB4)           // 81920 -> 2 CTAs/SM
#define STG1   (PLANE + BPLANE)      // gemm1a stage (A 128r + B 256r): 30720
#define GSMEM1 (2 * STG1)            // 61440 -> 2 CTAs/SM
#define STG3   (3 * PLANE)
#define GSMEM3 (2 * STG3)            // 61440

// ---------------- init kernels ----------------
__global__ void k_initMask() {
    int t = blockIdx.x * blockDim.x + threadIdx.x;
    if (t < BB * NIN) g_mask[t] = 0.0f;
}
__global__ void k_initScore() {
    int t = blockIdx.x * blockDim.x + threadIdx.x;
    if (t < BB * NP)  g_scoreEnc[t] = 0u;
    if (t < BB * NC)  g_scoreEnc2[t] = 0u;
}
__global__ void k_scatter(const int* __restrict__ sidx) {
    int t = blockIdx.x * blockDim.x + threadIdx.x;
    if (t < BB * KIN) {
        int b = t >> 9;
        g_mask[b * NIN + sidx[t]] = 1.0f;
    }
}

// ---------------- merged A split ----------------
union B4U { __nv_bfloat16 h[4]; ull u; };
union B2U { __nv_bfloat16 h[2]; u32 u; };
union H4U { __half h[4]; ull u; };
union H2U { __half h[2]; u32 u; };

__global__ void k_splitA(const float* __restrict__ act) {
    size_t t = (size_t)blockIdx.x * 256 + threadIdx.x;
    size_t bs = t >> 7;
    int k4 = (int)(t & 127);
    int b = (int)(bs >> 11), s = (int)(bs & 2047);
    float4 v = ((const float4*)act)[t];
    float vv[4] = { v.x, v.y, v.z, v.w };
    H4U f16; B4U hh, mm;
#pragma unroll
    for (int i = 0; i < 4; i++) {
        f16.h[i] = __float2half(vv[i]);
        hh.h[i] = __float2bfloat16(vv[i]);
        mm.h[i] = __float2bfloat16(vv[i] - __bfloat162float(hh.h[i]));
    }
    *(ull*)(g_Ah16 + t * 4) = f16.u;
    size_t base = ((size_t)(b * 2) * SS + s) * KIN + k4 * 4;
    const size_t PL = (size_t)SS * KIN;
    *(ull*)(g_Asp + base)      = hh.u;
    *(ull*)(g_Asp + base + PL) = mm.u;
}

// ---------------- gather B f16 (full 4096 rows) ----------------
__global__ void k_gatherBh(const float* __restrict__ cw, const int* __restrict__ sidx) {
    __shared__ float row[NIN];
    __shared__ int sidxS[BB * KIN];
    int p = blockIdx.x, tid = threadIdx.x;
    for (int i = tid; i < NIN; i += 256) row[i] = cw[(size_t)p * NIN + i];
    for (int i = tid; i < BB * KIN / 4; i += 256)
        ((int4*)sidxS)[i] = ((const int4*)sidx)[i];
    __syncthreads();
    int k = tid * 2;
#pragma unroll 1
    for (int b = 0; b < BB; b++) {
        int i0 = sidxS[b * KIN + k], i1 = sidxS[b * KIN + k + 1];
        H2U hh;
        hh.h[0] = __float2half(row[i0]);
        hh.h[1] = __float2half(row[i1]);
        *(u32*)(g_Bh + ((size_t)b * NP + p) * KIN + k) = hh.u;
    }
}

// ---------------- gather B splits for NC candidates ----------------
__global__ void k_gatherBc(const float* __restrict__ cw, const int* __restrict__ sidx) {
    __shared__ float row[NIN];
    int blk = blockIdx.x;
    int b = blk / NC, j = blk % NC;
    int tid = threadIdx.x;
    int p = g_pidx512[b * NC + j];
    for (int i = tid; i < NIN; i += 256) row[i] = cw[(size_t)p * NIN + i];
    __syncthreads();
    int k = tid * 2;
    int i0 = sidx[b * KIN + k], i1 = sidx[b * KIN + k + 1];
    B2U hh, mm;
    split2(row[i0], hh.h[0], mm.h[0]);
    split2(row[i1], hh.h[1], mm.h[1]);
    const size_t PL = (size_t)NC * KIN;
    size_t base = ((size_t)(b * 2) * NC + j) * KIN + k;
    *(u32*)(g_Bc + base)      = hh.u;
    *(u32*)(g_Bc + base + PL) = mm.u;
}

// ---------------- K1a: approx score GEMM, f16 acc, 128x256 tile, 2 CTAs/SM ----------------
__global__ __launch_bounds__(256, 2)
void k_gemm1a() {
    extern __shared__ char smem[];
    const u32 sbase = smem_u32(smem);
    const int tid = threadIdx.x;
    const int wid = tid >> 5, lid = tid & 31;
    const int wm = wid & 3, wn = wid >> 2;       // warp tile 32 x 128
    const int b  = blockIdx.z;
    const int p0 = blockIdx.x * 256;
    const int s0 = blockIdx.y * 128;

    u32 acc[2][16][2];
#pragma unroll
    for (int i = 0; i < 2; i++)
#pragma unroll
        for (int j = 0; j < 16; j++) { acc[i][j][0] = 0u; acc[i][j][1] = 0u; }

    auto load_stage = [&](int ks, int buf) {
        const int k0 = ks * 32;
        u32 sgA = sbase + buf * STG1;
        u32 sgB = sgA + PLANE;
#pragma unroll
        for (int i = 0; i < 2; i++) {            // A: 512 chunks (128 rows)
            int idx = tid + i * 256;
            int r = idx >> 2, c = idx & 3;
            const __half* g = g_Ah16 + ((size_t)b * SS + s0 + r) * KIN + k0 + c * 8;
            cpasync16(sgA + r * RPAD + c * 16, g);
        }
#pragma unroll
        for (int i = 0; i < 4; i++) {            // B: 1024 chunks (256 rows)
            int idx = tid + i * 256;
            int r = idx >> 2, c = idx & 3;
            const __half* g = g_Bh + ((size_t)b * NP + p0 + r) * KIN + k0 + c * 8;
            cpasync16(sgB + r * RPAD + c * 16, g);
        }
    };

    const u32 aoff = (u32)((wm * 32 + (lid & 15)) * RPAD + (lid >> 4) * 16);
    const u32 boff = (u32)((wn * 128 + (lid & 15)) * RPAD + (lid >> 4) * 16);

    load_stage(0, 0); CP_COMMIT();

#pragma unroll 1
    for (int ks = 0; ks < KIN / 32; ks++) {
        int buf = ks & 1;
        if (ks < KIN / 32 - 1) { load_stage(ks + 1, buf ^ 1); CP_COMMIT(); CP_WAIT(1); }
        else                   { CP_WAIT(0); }
        __syncthreads();
        u32 sA = sbase + buf * STG1;
        u32 sB = sA + PLANE;
#pragma unroll
        for (int kk = 0; kk < 2; kk++) {
            u32 ah[2][4];
#pragma unroll
            for (int mt = 0; mt < 2; mt++)
                ldsm4(ah[mt], sA + aoff + mt * (16 * RPAD) + kk * 32);
#pragma unroll
            for (int q4 = 0; q4 < 2; q4++) {     // B fragments in groups of 4 (live-range cap)
                u32 bh[4][4];
#pragma unroll
                for (int q = 0; q < 4; q++)
                    ldsm4(bh[q], sB + boff + (q4 * 4 + q) * (16 * RPAD) + kk * 32);
#pragma unroll
                for (int mt = 0; mt < 2; mt++)
#pragma unroll
                    for (int q = 0; q < 4; q++) {
                        int nt = q4 * 8 + 2 * q;
                        mma16816h(acc[mt][nt],     ah[mt], bh[q][0], bh[q][2]);
                        mma16816h(acc[mt][nt + 1], ah[mt], bh[q][1], bh[q][3]);
                    }
            }
        }
        __syncthreads();
    }

    u32* scol = (u32*)smem;
    if (tid < 256) scol[tid] = 0u;
    __syncthreads();
#pragma unroll
    for (int nt = 0; nt < 16; nt++) {
        float m0 = -1e30f, m1 = -1e30f;
#pragma unroll
        for (int mt = 0; mt < 2; mt++) {
            float2 lo = __half22float2(*(const __half2*)&acc[mt][nt][0]);
            float2 hi = __half22float2(*(const __half2*)&acc[mt][nt][1]);
            m0 = fmaxf(m0, fmaxf(lo.x, hi.x));
            m1 = fmaxf(m1, fmaxf(lo.y, hi.y));
        }
#pragma unroll
        for (int mk = 4; mk < 32; mk <<= 1) {
            m0 = fmaxf(m0, __shfl_xor_sync(0xffffffffu, m0, mk));
            m1 = fmaxf(m1, __shfl_xor_sync(0xffffffffu, m1, mk));
        }
        if (lid < 4) {
            atomicMax(&scol[wn * 128 + nt * 8 + 2 * lid],     fenc(m0));
            atomicMax(&scol[wn * 128 + nt * 8 + 2 * lid + 1], fenc(m1));
        }
    }
    __syncthreads();
    if (tid < 256) atomicMax(&g_scoreEnc[b * NP + p0 + tid], scol[tid]);
}

// ---------------- K2: hidden MLP ----------------
__global__ __launch_bounds__(256)
void k_hidden(const float* __restrict__ w1, const float* __restrict__ b1) {
    extern __shared__ float ms[];
    int tid = threadIdx.x, warp = tid >> 5, lane = tid & 31;
    for (int i = tid; i < BB * NIN / 4; i += 256)
        ((float4*)ms)[i] = ((const float4*)g_mask)[i];
    __syncthreads();
    int j = blockIdx.x * 8 + warp;
    const float4* wr = (const float4*)(w1 + (size_t)j * NIN);
    float acc[BB];
#pragma unroll
    for (int b = 0; b < BB; b++) acc[b] = 0.0f;
#pragma unroll
    for (int it = 0; it < NIN / 128; it++) {
        int q = lane + it * 32;
        float4 w = wr[q];
#pragma unroll
        for (int b = 0; b < BB; b++) {
            float4 m = ((const float4*)(ms + b * NIN))[q];
            acc[b] += w.x * m.x + w.y * m.y + w.z * m.z + w.w * m.w;
        }
    }
#pragma unroll
    for (int o = 16; o > 0; o >>= 1)
#pragma unroll
        for (int b = 0; b < BB; b++) acc[b] += __shfl_down_sync(0xffffffffu, acc[b], o);
    if (lane == 0) {
        float bj = b1[j];
#pragma unroll
        for (int b = 0; b < BB; b++) g_h[b * HID + j] = gelu_f(acc[b] + bj);
    }
}

// ---------------- K3a: relevance -> sigmoid (h staged in smem) ----------------
__global__ __launch_bounds__(256)
void k_relsig(const float* __restrict__ w2, const float* __restrict__ b2) {
    __shared__ float hs[BB][1024];
    int tid = threadIdx.x, warp = tid >> 5, lane = tid & 31;
    int pbase = blockIdx.x * 32;
    float acc[4][BB];
#pragma unroll
    for (int pp = 0; pp < 4; pp++)
#pragma unroll
        for (int b = 0; b < BB; b++) acc[pp][b] = 0.0f;

#pragma unroll 1
    for (int ch = 0; ch < HID / 1024; ch++) {
        int n0 = ch * 1024;
        for (int i = tid; i < BB * 1024 / 4; i += 256) {
            int b = i >> 8, q = i & 255;
            ((float4*)(hs[b]))[q] = ((const float4*)(g_h + b * HID + n0))[q];
        }
        __syncthreads();
#pragma unroll
        for (int pp = 0; pp < 4; pp++) {
            int p = pbase + warp * 4 + pp;
            const float4* wr = (const float4*)(w2 + (size_t)p * HID + n0);
#pragma unroll
            for (int it = 0; it < 8; it++) {
                int q = lane + it * 32;
                float4 w = wr[q];
#pragma unroll
                for (int b = 0; b < BB; b++) {
                    float4 h = ((const float4*)(hs[b]))[q];
                    acc[pp][b] += w.x * h.x + w.y * h.y + w.z * h.z + w.w * h.w;
                }
            }
        }
        __syncthreads();
    }
#pragma unroll
    for (int o = 16; o > 0; o >>= 1)
#pragma unroll
        for (int pp = 0; pp < 4; pp++)
#pragma unroll
            for (int b = 0; b < BB; b++)
                acc[pp][b] += __shfl_down_sync(0xffffffffu, acc[pp][b], o);
    if (lane == 0) {
#pragma unroll
        for (int pp = 0; pp < 4; pp++) {
            int p = pbase + warp * 4 + pp;
            float bp = b2[p];
#pragma unroll
            for (int b = 0; b < BB; b++) {
                float rel = acc[pp][b] + bp;
                g_sig[b * NP + p] = 1.0f / (1.0f + expf(-rel));
            }
        }
    }
}

// ---------------- K4: approx top-NC ----------------
__global__ void k_topkc() {
    __shared__ ull key[NP];
    int b = blockIdx.x, tid = threadIdx.x;
    for (int i = tid; i < NP; i += 1024) {
        float sc = gelu_f(fdec(g_scoreEnc[b * NP + i])) * g_sig[b * NP + i];
        key[i] = ((ull)fenc(sc) << 32) | (unsigned)i;
    }
    __syncthreads();
    for (int k = 2; k <= NP; k <<= 1) {
        for (int j = k >> 1; j > 0; j >>= 1) {
            for (int i = tid; i < NP; i += 1024) {
                int ix = i ^ j;
                if (ix > i) {
                    ull x = key[i], y = key[ix];
                    bool desc = ((i & k) == 0);
                    if (desc ? (x < y) : (x > y)) { key[i] = y; key[ix] = x; }
                }
            }
            __syncthreads();
        }
    }
    if (tid < NC) g_pidx512[b * NC + tid] = (int)(key[tid] & 0xffffffffu);
}

// ---------------- K5: refine — exact 3-pass bf16 z for NC cands ----------------
__global__ __launch_bounds__(256)
void k_refine() {
    extern __shared__ char smem[];
    const u32 sbase = smem_u32(smem);
    const int tid = threadIdx.x;
    const int wid = tid >> 5, lid = tid & 31;
    const int wm = wid & 3, wn = wid >> 2;
    const int b  = blockIdx.z;
    const int n0 = blockIdx.x * 128;
    const int s0 = blockIdx.y * 128;

    float acc[2][8][4];
#pragma unroll
    for (int i = 0; i < 2; i++)
#pragma unroll
        for (int j = 0; j < 8; j++)
#pragma unroll
            for (int r = 0; r < 4; r++) acc[i][j][r] = 0.0f;

    auto load_stage = [&](int ks, int buf) {
        const int k0 = ks * 32;
        u32 sg = sbase + buf * STGB4;
#pragma unroll
        for (int i = 0; i < 4; i++) {
            int idx = tid + i * 256;
            int sp = idx >> 9, rem = idx & 511;
            int r = rem >> 2, c = rem & 3;
            const __nv_bfloat16* g = g_Asp + ((size_t)(b * 2 + sp) * SS + s0 + r) * KIN + k0 + c * 8;
            cpasync16(sg + sp * PLANE + r * RPAD + c * 16, g);
        }
#pragma unroll
        for (int i = 0; i < 4; i++) {
            int idx = tid + i * 256;
            int sp = idx >> 9, rem = idx & 511;
            int r = rem >> 2, c = rem & 3;
            const __nv_bfloat16* g = g_Bc + ((size_t)(b * 2 + sp) * NC + n0 + r) * KIN + k0 + c * 8;
            cpasync16(sg + 2 * PLANE + sp * PLANE + r * RPAD + c * 16, g);
        }
    };

    const u32 aoff = (u32)((wm * 32 + (lid & 15)) * RPAD + (lid >> 4) * 16);
    const u32 boff = (u32)((wn * 64 + (lid & 15)) * RPAD + (lid >> 4) * 16);

    load_stage(0, 0); CP_COMMIT();

#pragma unroll 1
    for (int ks = 0; ks < KIN / 32; ks++) {
        int buf = ks & 1;
        if (ks < KIN / 32 - 1) { load_stage(ks + 1, buf ^ 1); CP_COMMIT(); CP_WAIT(1); }
        else                   { CP_WAIT(0); }
        __syncthreads();
        u32 sA = sbase + buf * STGB4;
        u32 sB = sA + 2 * PLANE;
#pragma unroll
        for (int kk = 0; kk < 2; kk++) {
            u32 ah[2][4], am[2][4];
#pragma unroll
            for (int mt = 0; mt < 2; mt++) {
                ldsm4(ah[mt], sA + aoff + mt * (16 * RPAD) + kk * 32);
                ldsm4(am[mt], sA + PLANE + aoff + mt * (16 * RPAD) + kk * 32);
            }
            u32 bh[4][4], bm[4][4];
#pragma unroll
            for (int nt2 = 0; nt2 < 4; nt2++) {
                ldsm4(bh[nt2], sB + boff + nt2 * (16 * RPAD) + kk * 32);
                ldsm4(bm[nt2], sB + PLANE + boff + nt2 * (16 * RPAD) + kk * 32);
            }
#pragma unroll
            for (int mt = 0; mt < 2; mt++)
#pragma unroll
                for (int nt2 = 0; nt2 < 4; nt2++) {
                    mma16816(acc[mt][2 * nt2],     ah[mt], bh[nt2][0], bh[nt2][2]);
                    mma16816(acc[mt][2 * nt2 + 1], ah[mt], bh[nt2][1], bh[nt2][3]);
                    mma16816(acc[mt][2 * nt2],     ah[mt], bm[nt2][0], bm[nt2][2]);
                    mma16816(acc[mt][2 * nt2 + 1], ah[mt], bm[nt2][1], bm[nt2][3]);
                    mma16816(acc[mt][2 * nt2],     am[mt], bh[nt2][0], bh[nt2][2]);
                    mma16816(acc[mt][2 * nt2 + 1], am[mt], bh[nt2][1], bh[nt2][3]);
                }
        }
        __syncthreads();
    }

    u32* scol = (u32*)smem;
    if (tid < 128) scol[tid] = 0u;
    __syncthreads();

    const size_t PL = (size_t)SS * NC;
#pragma unroll
    for (int mt = 0; mt < 2; mt++)
#pragma unroll
        for (int nt = 0; nt < 8; nt++) {
            int row = s0 + wm * 32 + mt * 16 + (lid >> 2);
            int col = n0 + wn * 64 + nt * 8 + 2 * (lid & 3);
            float g0 = gelu_f(acc[mt][nt][0]), g1 = gelu_f(acc[mt][nt][1]);
            float g2 = gelu_f(acc[mt][nt][2]), g3 = gelu_f(acc[mt][nt][3]);
            H2U h01, m01, h23, m23;
            split2h(g0, h01.h[0], m01.h[0]); split2h(g1, h01.h[1], m01.h[1]);
            split2h(g2, h23.h[0], m23.h[0]); split2h(g3, h23.h[1], m23.h[1]);
            size_t base = ((size_t)(b * 2) * SS + row) * NC + col;
            *(u32*)(g_PC + base)               = h01.u;
            *(u32*)(g_PC + base + PL)          = m01.u;
            *(u32*)(g_PC + base + 8 * NC)      = h23.u;
            *(u32*)(g_PC + base + PL + 8 * NC) = m23.u;
        }
#pragma unroll
    for (int nt = 0; nt < 8; nt++) {
        float m0 = fmaxf(fmaxf(acc[0][nt][0], acc[0][nt][2]), fmaxf(acc[1][nt][0], acc[1][nt][2]));
        float m1 = fmaxf(fmaxf(acc[0][nt][1], acc[0][nt][3]), fmaxf(acc[1][nt][1], acc[1][nt][3]));
#pragma unroll
        for (int mk = 4; mk < 32; mk <<= 1) {
            m0 = fmaxf(m0, __shfl_xor_sync(0xffffffffu, m0, mk));
            m1 = fmaxf(m1, __shfl_xor_sync(0xffffffffu, m1, mk));
        }
        if (lid < 4) {
            atomicMax(&scol[wn * 64 + nt * 8 + 2 * lid],     fenc(m0));
            atomicMax(&scol[wn * 64 + nt * 8 + 2 * lid + 1], fenc(m1));
        }
    }
    __syncthreads();
    if (tid < 128) atomicMax(&g_scoreEnc2[b * NC + n0 + tid], scol[tid]);
}

// ---------------- K6: exact rescore + top-256 ----------------
__global__ void k_rescore() {
    __shared__ ull key[NCP];
    int b = blockIdx.x, tid = threadIdx.x;
    if (tid < NC) {
        float z = fdec(g_scoreEnc2[b * NC + tid]);
        int p = g_pidx512[b * NC + tid];
        float sc = gelu_f(z) * g_sig[b * NP + p];
        key[tid] = ((ull)fenc(sc) << 32) | (unsigned)tid;
    } else {
        key[tid] = 0ULL;
    }
    __syncthreads();
    for (int k = 2; k <= NCP; k <<= 1) {
        for (int j = k >> 1; j > 0; j >>= 1) {
            int i = tid;
            int ix = i ^ j;
            if (ix > i) {
                ull x = key[i], y = key[ix];
                bool desc = ((i & k) == 0);
                if (desc ? (x < y) : (x > y)) { key[i] = y; key[ix] = x; }
            }
            __syncthreads();
        }
    }
    if (tid < KSEL) {
        int slot = (int)(key[tid] & 0xffffffffu);
        g_cmap[b * KSEL + tid] = slot;
        g_pidx[b * KSEL + tid] = g_pidx512[b * NC + slot];
    }
}

// ---------------- K7: compact via smem staging ----------------
__global__ void k_compact() {
    __shared__ __half st[2][8][NC];
    __shared__ int cm[KSEL];
    int blk = blockIdx.x;
    int b = blk / (SS / 8);
    int s8 = (blk % (SS / 8)) * 8;
    int tid = threadIdx.x;
    if (tid < KSEL) cm[tid] = g_cmap[b * KSEL + tid];
    const int4* src0 = (const int4*)(g_PC + ((size_t)(b * 2)     * SS + s8) * NC);
    const int4* src1 = (const int4*)(g_PC + ((size_t)(b * 2 + 1) * SS + s8) * NC);
    int4* d0 = (int4*)&st[0][0][0];
    int4* d1 = (int4*)&st[1][0][0];
    const int NI4 = 8 * NC / 8;
    for (int idx = tid; idx < NI4; idx += 256) {
        d0[idx] = src0[idx];
        d1[idx] = src1[idx];
    }
    __syncthreads();
    int j = tid;
    int c = cm[j];
    const size_t PLa = (size_t)SS * KSEL;
#pragma unroll
    for (int r = 0; r < 8; r++) {
        size_t dst = ((size_t)(b * 2) * SS + s8 + r) * KSEL + j;
        g_PA[dst]       = st[0][r][c];
        g_PA[dst + PLa] = st[1][r][c];
    }
}

// ---------------- K8: gather + transpose proj rows -> f16 single plane ----------------
__global__ void k_projsplit(const float* __restrict__ proj) {
    __shared__ float t[32][33];
    __shared__ int pj[32];
    int j0 = blockIdx.x * 32, d0 = blockIdx.y * 32, b = blockIdx.z;
    int tx = threadIdx.x, ty = threadIdx.y;
    if (ty == 0) pj[tx] = g_pidx[b * KSEL + j0 + tx];
    __syncthreads();
#pragma unroll
    for (int i = 0; i < 32; i += 8) {
        int p = pj[ty + i];
        t[ty + i][tx] = proj[(size_t)p * DM + d0 + tx];
    }
    __syncthreads();
#pragma unroll
    for (int i = 0; i < 32; i += 8) {
        float v = t[tx][ty + i];
        g_Pr[((size_t)b * DM + d0 + ty + i) * KSEL + j0 + tx] = __float2half(v);
    }
}

// ---------------- K9: final GEMM (f16 2-pass) ----------------
__global__ __launch_bounds__(256)
void k_gemm3t(float* __restrict__ out) {
    extern __shared__ char smem[];
    const u32 sbase = smem_u32(smem);
    const int tid = threadIdx.x;
    const int wid = tid >> 5, lid = tid & 31;
    const int wm = wid & 3, wn = wid >> 2;
    const int b  = blockIdx.z;
    const int d0 = blockIdx.x * 128;
    const int s0 = blockIdx.y * 128;

    float acc[2][8][4];
#pragma unroll
    for (int i = 0; i < 2; i++)
#pragma unroll
        for (int j = 0; j < 8; j++)
#pragma unroll
            for (int r = 0; r < 4; r++) acc[i][j][r] = 0.0f;

    auto load_stage = [&](int ks, int buf) {
        const int k0 = ks * 32;
        u32 sg = sbase + buf * STG3;
#pragma unroll
        for (int i = 0; i < 4; i++) {
            int idx = tid + i * 256;
            int sp = idx >> 9, rem = idx & 511;
            int r = rem >> 2, c = rem & 3;
            const __half* g = g_PA + ((size_t)(b * 2 + sp) * SS + s0 + r) * KSEL + k0 + c * 8;
            cpasync16(sg + sp * PLANE + r * RPAD + c * 16, g);
        }
#pragma unroll
        for (int i = 0; i < 2; i++) {
            int idx = tid + i * 256;
            int r = idx >> 2, c = idx & 3;
            const __half* g = g_Pr + ((size_t)b * DM + d0 + r) * KSEL + k0 + c * 8;
            cpasync16(sg + 2 * PLANE + r * RPAD + c * 16, g);
        }
    };

    const u32 aoff = (u32)((wm * 32 + (lid & 15)) * RPAD + (lid >> 4) * 16);
    const u32 boff = (u32)((wn * 64 + (lid & 15)) * RPAD + (lid >> 4) * 16);

    load_stage(0, 0); CP_COMMIT();

#pragma unroll 1
    for (int ks = 0; ks < KSEL / 32; ks++) {
        int buf = ks & 1;
        if (ks < KSEL / 32 - 1) { load_stage(ks + 1, buf ^ 1); CP_COMMIT(); CP_WAIT(1); }
        else                    { CP_WAIT(0); }
        __syncthreads();
        u32 sA = sbase + buf * STG3;
        u32 sB = sA + 2 * PLANE;
#pragma unroll
        for (int kk = 0; kk < 2; kk++) {
            u32 ah[2][4], am[2][4];
#pragma unroll
            for (int mt = 0; mt < 2; mt++) {
                ldsm4(ah[mt], sA + aoff + mt * (16 * RPAD) + kk * 32);
                ldsm4(am[mt], sA + PLANE + aoff + mt * (16 * RPAD) + kk * 32);
            }
            u32 bh[4][4];
#pragma unroll
            for (int nt2 = 0; nt2 < 4; nt2++)
                ldsm4(bh[nt2], sB + boff + nt2 * (16 * RPAD) + kk * 32);
#pragma unroll
            for (int mt = 0; mt < 2; mt++)
#pragma unroll
                for (int nt2 = 0; nt2 < 4; nt2++) {
                    mma16816f(acc[mt][2 * nt2],     ah[mt], bh[nt2][0], bh[nt2][2]);
                    mma16816f(acc[mt][2 * nt2 + 1], ah[mt], bh[nt2][1], bh[nt2][3]);
                    mma16816f(acc[mt][2 * nt2],     am[mt], bh[nt2][0], bh[nt2][2]);
                    mma16816f(acc[mt][2 * nt2 + 1], am[mt], bh[nt2][1], bh[nt2][3]);
                }
        }
        __syncthreads();
    }
#pragma unroll
    for (int mt = 0; mt < 2; mt++)
#pragma unroll
        for (int nt = 0; nt < 8; nt++) {
            int row = s0 + wm * 32 + mt * 16 + (lid >> 2);
            int col = d0 + wn * 64 + nt * 8 + 2 * (lid & 3);
            float* po = out + ((size_t)b * SS + row) * DM + col;
            *(float2*)po            = make_float2(acc[mt][nt][0], acc[mt][nt][1]);
            *(float2*)(po + 8 * DM) = make_float2(acc[mt][nt][2], acc[mt][nt][3]);
        }
}

// ---------------- entry (multi-stream fork/join) ----------------
extern "C" void kernel_launch(void* const* d_in, const int* in_sizes, int n_in,
                              void* d_out, int out_size) {
    const float* act  = (const float*)d_in[0];
    const int*   sidx = (const int*)d_in[1];
    int o = (n_in >= 9 && in_sizes[2] == 1) ? 3 : 2;
    const float* cw   = (const float*)d_in[o + 0];
    const float* proj = (const float*)d_in[o + 1];
    const float* w1   = (const float*)d_in[o + 2];
    const float* b1   = (const float*)d_in[o + 3];
    const float* w2   = (const float*)d_in[o + 4];
    const float* b2   = (const float*)d_in[o + 5];
    float* out = (float*)d_out;

    static cudaStream_t s1 = nullptr;
    static cudaEvent_t ev0 = nullptr, evA = nullptr, ev1 = nullptr, ev2 = nullptr, ev3 = nullptr;
    if (s1 == nullptr) {
        cudaStreamCreateWithFlags(&s1, cudaStreamNonBlocking);
        cudaEventCreateWithFlags(&ev0, cudaEventDisableTiming);
        cudaEventCreateWithFlags(&evA, cudaEventDisableTiming);
        cudaEventCreateWithFlags(&ev1, cudaEventDisableTiming);
        cudaEventCreateWithFlags(&ev2, cudaEventDisableTiming);
        cudaEventCreateWithFlags(&ev3, cudaEventDisableTiming);
        cudaFuncSetAttribute(k_gemm1a, cudaFuncAttributeMaxDynamicSharedMemorySize, GSMEM1);
        cudaFuncSetAttribute(k_refine, cudaFuncAttributeMaxDynamicSharedMemorySize, GSMEM4);
        cudaFuncSetAttribute(k_gemm3t, cudaFuncAttributeMaxDynamicSharedMemorySize, GSMEM3);
        cudaFuncSetAttribute(k_hidden, cudaFuncAttributeMaxDynamicSharedMemorySize, BB * NIN * 4);
    }

    // fork: merged A split + MLP chain on s1
    cudaEventRecord(ev0, 0);
    cudaStreamWaitEvent(s1, ev0, 0);
    k_splitA<<<(BB * SS * KIN / 4) / 256, 256, 0, s1>>>(act);
    cudaEventRecord(evA, s1);
    k_initMask<<<(BB * NIN + 255) / 256, 256, 0, s1>>>();
    k_scatter<<<(BB * KIN + 255) / 256, 256, 0, s1>>>(sidx);
    k_hidden<<<HID / 8, 256, BB * NIN * 4, s1>>>(w1, b1);
    k_relsig<<<NP / 32, 256, 0, s1>>>(w2, b2);
    cudaEventRecord(ev1, s1);

    // main chain
    k_initScore<<<(BB * NP + 255) / 256, 256>>>();
    k_gatherBh<<<NP, 256>>>(cw, sidx);
    cudaStreamWaitEvent(0, evA, 0);
    k_gemm1a<<<dim3(NP / 256, SS / 128, BB), 256, GSMEM1>>>();

    // join
    cudaStreamWaitEvent(0, ev1, 0);
    k_topkc<<<BB, 1024>>>();
    k_gatherBc<<<BB * NC, 256>>>(cw, sidx);
    k_refine<<<dim3(NC / 128, SS / 128, BB), 256, GSMEM4>>>();
    k_rescore<<<BB, NCP>>>();

    // fork: projsplit on s1, compact on main
    cudaEventRecord(ev2, 0);
    cudaStreamWaitEvent(s1, ev2, 0);
    k_projsplit<<<dim3(KSEL / 32, DM / 32, BB), dim3(32, 8), 0, s1>>>(proj);
    cudaEventRecord(ev3, s1);
    k_compact<<<BB * SS / 8, 256>>>();
    cudaStreamWaitEvent(0, ev3, 0);

    k_gemm3t<<<dim3(DM / 128, SS / 128, BB), 256, GSMEM3>>>(out);
}

// round 16
// speedup vs baseline: 1.6728x; 1.0293x over previous
#include <cuda_runtime.h>
#include <cuda_bf16.h>
#include <cuda_fp16.h>

#define BB   8
#define SS   2048
#define KIN  512
#define NIN  2048
#define NP   4096
#define HID  4096
#define DM   1024
#define KSEL 256
#define NC   384
#define NCP  512

typedef unsigned long long ull;
typedef unsigned int u32;

// ---------------- scratch ----------------
__device__ __align__(256) __nv_bfloat16 g_Asp[(size_t)BB * 2 * SS * KIN];
__device__ __align__(256) __half        g_Ah16[(size_t)BB * SS * KIN];
__device__ __align__(256) __half        g_Bh [(size_t)BB * NP * KIN];
__device__ __align__(256) __nv_bfloat16 g_Bc [(size_t)BB * 2 * NC * KIN];
__device__ __align__(256) __half        g_PC [(size_t)BB * 2 * SS * NC];
__device__ __align__(256) __half        g_PA [(size_t)BB * 2 * SS * KSEL];
__device__ __align__(256) __half        g_Pr [(size_t)BB * DM * KSEL];
__device__ float    g_mask[BB * NIN];
__device__ float    g_h[BB * HID];
__device__ float    g_sig[BB * NP];
__device__ unsigned g_scoreEnc[BB * NP];
__device__ unsigned g_scoreEnc2[BB * NC];
__device__ int      g_pidx512[BB * NC];
__device__ int      g_pidx[BB * KSEL];
__device__ int      g_cmap[BB * KSEL];

// ---------------- helpers ----------------
__device__ __forceinline__ unsigned fenc(float f) {
    unsigned u = __float_as_uint(f);
    return (u & 0x80000000u) ? ~u : (u | 0x80000000u);
}
__device__ __forceinline__ float fdec(unsigned u) {
    return __uint_as_float((u & 0x80000000u) ? (u & 0x7fffffffu) : ~u);
}
__device__ __forceinline__ float gelu_f(float x) {
    return 0.5f * x * (1.0f + erff(x * 0.70710678118654752f));
}
__device__ __forceinline__ u32 smem_u32(const void* p) {
    u32 a; asm("{ .reg .u64 t; cvta.to.shared.u64 t, %1; cvt.u32.u64 %0, t; }" : "=r"(a) : "l"(p));
    return a;
}
__device__ __forceinline__ void split2(float a, __nv_bfloat16& h, __nv_bfloat16& m) {
    h = __float2bfloat16(a);
    m = __float2bfloat16(a - __bfloat162float(h));
}
__device__ __forceinline__ void split2h(float a, __half& h, __half& m) {
    h = __float2half(a);
    m = __float2half(a - __half2float(h));
}

// ---------------- mma.sync / ldmatrix / cp.async ----------------
__device__ __forceinline__ void mma16816(float* d, const u32* a, u32 b0, u32 b1) {
    asm volatile("mma.sync.aligned.m16n8k16.row.col.f32.bf16.bf16.f32 "
        "{%0,%1,%2,%3}, {%4,%5,%6,%7}, {%8,%9}, {%0,%1,%2,%3};"
        : "+f"(d[0]), "+f"(d[1]), "+f"(d[2]), "+f"(d[3])
        : "r"(a[0]), "r"(a[1]), "r"(a[2]), "r"(a[3]), "r"(b0), "r"(b1));
}
__device__ __forceinline__ void mma16816f(float* d, const u32* a, u32 b0, u32 b1) {
    asm volatile("mma.sync.aligned.m16n8k16.row.col.f32.f16.f16.f32 "
        "{%0,%1,%2,%3}, {%4,%5,%6,%7}, {%8,%9}, {%0,%1,%2,%3};"
        : "+f"(d[0]), "+f"(d[1]), "+f"(d[2]), "+f"(d[3])
        : "r"(a[0]), "r"(a[1]), "r"(a[2]), "r"(a[3]), "r"(b0), "r"(b1));
}
__device__ __forceinline__ void mma16816h(u32* d, const u32* a, u32 b0, u32 b1) {
    asm volatile("mma.sync.aligned.m16n8k16.row.col.f16.f16.f16.f16 "
        "{%0,%1}, {%2,%3,%4,%5}, {%6,%7}, {%0,%1};"
        : "+r"(d[0]), "+r"(d[1])
        : "r"(a[0]), "r"(a[1]), "r"(a[2]), "r"(a[3]), "r"(b0), "r"(b1));
}
__device__ __forceinline__ void ldsm4(u32* r, u32 addr) {
    asm volatile("ldmatrix.sync.aligned.m8n8.x4.shared.b16 {%0,%1,%2,%3}, [%4];"
        : "=r"(r[0]), "=r"(r[1]), "=r"(r[2]), "=r"(r[3]) : "r"(addr));
}
__device__ __forceinline__ void cpasync16(u32 dst, const void* src) {
    asm volatile("cp.async.cg.shared.global [%0], [%1], 16;" :: "r"(dst), "l"(src));
}
#define CP_COMMIT() asm volatile("cp.async.commit_group;" ::: "memory")
#define CP_WAIT(n)  asm volatile("cp.async.wait_group %0;" :: "n"(n) : "memory")

#define RPAD   80
#define PLANE  (128 * RPAD)          // 10240
#define BPLANE (256 * RPAD)          // 20480
#define STGB4  (4 * PLANE)
#define GSMEM4 (2 * STGB4)           // 81920 -> 2 CTAs/SM
#define STG1   (PLANE + BPLANE)      // 30720
#define GSMEM1 (2 * STG1)            // 61440 -> 2 CTAs/SM
#define STG3   (3 * PLANE)
#define GSMEM3 (2 * STG3)            // 61440

// ---------------- init kernels ----------------
__global__ void k_initMask() {
    int t = blockIdx.x * blockDim.x + threadIdx.x;
    if (t < BB * NIN) g_mask[t] = 0.0f;
}
__global__ void k_scatter(const int* __restrict__ sidx) {
    int t = blockIdx.x * blockDim.x + threadIdx.x;
    if (t < BB * KIN) {
        int b = t >> 9;
        g_mask[b * NIN + sidx[t]] = 1.0f;
    }
}

// ---------------- merged A split (+ score-buffer init folded in) ----------------
union B4U { __nv_bfloat16 h[4]; ull u; };
union B2U { __nv_bfloat16 h[2]; u32 u; };
union H4U { __half h[4]; ull u; };
union H2U { __half h[2]; u32 u; };

__global__ void k_splitA(const float* __restrict__ act) {
    size_t t = (size_t)blockIdx.x * 256 + threadIdx.x;
    // fold score-buffer zeroing into this launch (completes before evA -> gemm1a)
    if (blockIdx.x < (BB * NP + 255) / 256) {
        int z = blockIdx.x * 256 + threadIdx.x;
        if (z < BB * NP) g_scoreEnc[z] = 0u;
        if (z < BB * NC) g_scoreEnc2[z] = 0u;
    }
    size_t bs = t >> 7;
    int k4 = (int)(t & 127);
    int b = (int)(bs >> 11), s = (int)(bs & 2047);
    float4 v = ((const float4*)act)[t];
    float vv[4] = { v.x, v.y, v.z, v.w };
    H4U f16; B4U hh, mm;
#pragma unroll
    for (int i = 0; i < 4; i++) {
        f16.h[i] = __float2half(vv[i]);
        hh.h[i] = __float2bfloat16(vv[i]);
        mm.h[i] = __float2bfloat16(vv[i] - __bfloat162float(hh.h[i]));
    }
    *(ull*)(g_Ah16 + t * 4) = f16.u;
    size_t base = ((size_t)(b * 2) * SS + s) * KIN + k4 * 4;
    const size_t PL = (size_t)SS * KIN;
    *(ull*)(g_Asp + base)      = hh.u;
    *(ull*)(g_Asp + base + PL) = mm.u;
}

// ---------------- gather B f16 (full 4096 rows) ----------------
__global__ void k_gatherBh(const float* __restrict__ cw, const int* __restrict__ sidx) {
    __shared__ float row[NIN];
    __shared__ int sidxS[BB * KIN];
    int p = blockIdx.x, tid = threadIdx.x;
    for (int i = tid; i < NIN; i += 256) row[i] = cw[(size_t)p * NIN + i];
    for (int i = tid; i < BB * KIN / 4; i += 256)
        ((int4*)sidxS)[i] = ((const int4*)sidx)[i];
    __syncthreads();
    int k = tid * 2;
#pragma unroll 1
    for (int b = 0; b < BB; b++) {
        int i0 = sidxS[b * KIN + k], i1 = sidxS[b * KIN + k + 1];
        H2U hh;
        hh.h[0] = __float2half(row[i0]);
        hh.h[1] = __float2half(row[i1]);
        *(u32*)(g_Bh + ((size_t)b * NP + p) * KIN + k) = hh.u;
    }
}

// ---------------- gather B splits for NC candidates ----------------
__global__ void k_gatherBc(const float* __restrict__ cw, const int* __restrict__ sidx) {
    __shared__ float row[NIN];
    int blk = blockIdx.x;
    int b = blk / NC, j = blk % NC;
    int tid = threadIdx.x;
    int p = g_pidx512[b * NC + j];
    for (int i = tid; i < NIN; i += 256) row[i] = cw[(size_t)p * NIN + i];
    __syncthreads();
    int k = tid * 2;
    int i0 = sidx[b * KIN + k], i1 = sidx[b * KIN + k + 1];
    B2U hh, mm;
    split2(row[i0], hh.h[0], mm.h[0]);
    split2(row[i1], hh.h[1], mm.h[1]);
    const size_t PL = (size_t)NC * KIN;
    size_t base = ((size_t)(b * 2) * NC + j) * KIN + k;
    *(u32*)(g_Bc + base)      = hh.u;
    *(u32*)(g_Bc + base + PL) = mm.u;
}

// ---------------- K1a: approx score GEMM, f16 acc, 128x256 tile ----------------
__global__ __launch_bounds__(256, 2)
void k_gemm1a() {
    extern __shared__ char smem[];
    const u32 sbase = smem_u32(smem);
    const int tid = threadIdx.x;
    const int wid = tid >> 5, lid = tid & 31;
    const int wm = wid & 3, wn = wid >> 2;
    const int b  = blockIdx.z;
    const int p0 = blockIdx.x * 256;
    const int s0 = blockIdx.y * 128;

    u32 acc[2][16][2];
#pragma unroll
    for (int i = 0; i < 2; i++)
#pragma unroll
        for (int j = 0; j < 16; j++) { acc[i][j][0] = 0u; acc[i][j][1] = 0u; }

    auto load_stage = [&](int ks, int buf) {
        const int k0 = ks * 32;
        u32 sgA = sbase + buf * STG1;
        u32 sgB = sgA + PLANE;
#pragma unroll
        for (int i = 0; i < 2; i++) {
            int idx = tid + i * 256;
            int r = idx >> 2, c = idx & 3;
            const __half* g = g_Ah16 + ((size_t)b * SS + s0 + r) * KIN + k0 + c * 8;
            cpasync16(sgA + r * RPAD + c * 16, g);
        }
#pragma unroll
        for (int i = 0; i < 4; i++) {
            int idx = tid + i * 256;
            int r = idx >> 2, c = idx & 3;
            const __half* g = g_Bh + ((size_t)b * NP + p0 + r) * KIN + k0 + c * 8;
            cpasync16(sgB + r * RPAD + c * 16, g);
        }
    };

    const u32 aoff = (u32)((wm * 32 + (lid & 15)) * RPAD + (lid >> 4) * 16);
    const u32 boff = (u32)((wn * 128 + (lid & 15)) * RPAD + (lid >> 4) * 16);

    load_stage(0, 0); CP_COMMIT();

#pragma unroll 1
    for (int ks = 0; ks < KIN / 32; ks++) {
        int buf = ks & 1;
        if (ks < KIN / 32 - 1) { load_stage(ks + 1, buf ^ 1); CP_COMMIT(); CP_WAIT(1); }
        else                   { CP_WAIT(0); }
        __syncthreads();
        u32 sA = sbase + buf * STG1;
        u32 sB = sA + PLANE;
#pragma unroll
        for (int kk = 0; kk < 2; kk++) {
            u32 ah[2][4];
#pragma unroll
            for (int mt = 0; mt < 2; mt++)
                ldsm4(ah[mt], sA + aoff + mt * (16 * RPAD) + kk * 32);
#pragma unroll
            for (int q4 = 0; q4 < 2; q4++) {
                u32 bh[4][4];
#pragma unroll
                for (int q = 0; q < 4; q++)
                    ldsm4(bh[q], sB + boff + (q4 * 4 + q) * (16 * RPAD) + kk * 32);
#pragma unroll
                for (int mt = 0; mt < 2; mt++)
#pragma unroll
                    for (int q = 0; q < 4; q++) {
                        int nt = q4 * 8 + 2 * q;
                        mma16816h(acc[mt][nt],     ah[mt], bh[q][0], bh[q][2]);
                        mma16816h(acc[mt][nt + 1], ah[mt], bh[q][1], bh[q][3]);
                    }
            }
        }
        __syncthreads();
    }

    u32* scol = (u32*)smem;
    if (tid < 256) scol[tid] = 0u;
    __syncthreads();
#pragma unroll
    for (int nt = 0; nt < 16; nt++) {
        float m0 = -1e30f, m1 = -1e30f;
#pragma unroll
        for (int mt = 0; mt < 2; mt++) {
            float2 lo = __half22float2(*(const __half2*)&acc[mt][nt][0]);
            float2 hi = __half22float2(*(const __half2*)&acc[mt][nt][1]);
            m0 = fmaxf(m0, fmaxf(lo.x, hi.x));
            m1 = fmaxf(m1, fmaxf(lo.y, hi.y));
        }
#pragma unroll
        for (int mk = 4; mk < 32; mk <<= 1) {
            m0 = fmaxf(m0, __shfl_xor_sync(0xffffffffu, m0, mk));
            m1 = fmaxf(m1, __shfl_xor_sync(0xffffffffu, m1, mk));
        }
        if (lid < 4) {
            atomicMax(&scol[wn * 128 + nt * 8 + 2 * lid],     fenc(m0));
            atomicMax(&scol[wn * 128 + nt * 8 + 2 * lid + 1], fenc(m1));
        }
    }
    __syncthreads();
    if (tid < 256) atomicMax(&g_scoreEnc[b * NP + p0 + tid], scol[tid]);
}

// ---------------- K2: hidden MLP ----------------
__global__ __launch_bounds__(256)
void k_hidden(const float* __restrict__ w1, const float* __restrict__ b1) {
    extern __shared__ float ms[];
    int tid = threadIdx.x, warp = tid >> 5, lane = tid & 31;
    for (int i = tid; i < BB * NIN / 4; i += 256)
        ((float4*)ms)[i] = ((const float4*)g_mask)[i];
    __syncthreads();
    int j = blockIdx.x * 8 + warp;
    const float4* wr = (const float4*)(w1 + (size_t)j * NIN);
    float acc[BB];
#pragma unroll
    for (int b = 0; b < BB; b++) acc[b] = 0.0f;
#pragma unroll
    for (int it = 0; it < NIN / 128; it++) {
        int q = lane + it * 32;
        float4 w = wr[q];
#pragma unroll
        for (int b = 0; b < BB; b++) {
            float4 m = ((const float4*)(ms + b * NIN))[q];
            acc[b] += w.x * m.x + w.y * m.y + w.z * m.z + w.w * m.w;
        }
    }
#pragma unroll
    for (int o = 16; o > 0; o >>= 1)
#pragma unroll
        for (int b = 0; b < BB; b++) acc[b] += __shfl_down_sync(0xffffffffu, acc[b], o);
    if (lane == 0) {
        float bj = b1[j];
#pragma unroll
        for (int b = 0; b < BB; b++) g_h[b * HID + j] = gelu_f(acc[b] + bj);
    }
}

// ---------------- K3a: relevance -> sigmoid ----------------
__global__ __launch_bounds__(256)
void k_relsig(const float* __restrict__ w2, const float* __restrict__ b2) {
    __shared__ float hs[BB][1024];
    int tid = threadIdx.x, warp = tid >> 5, lane = tid & 31;
    int pbase = blockIdx.x * 32;
    float acc[4][BB];
#pragma unroll
    for (int pp = 0; pp < 4; pp++)
#pragma unroll
        for (int b = 0; b < BB; b++) acc[pp][b] = 0.0f;

#pragma unroll 1
    for (int ch = 0; ch < HID / 1024; ch++) {
        int n0 = ch * 1024;
        for (int i = tid; i < BB * 1024 / 4; i += 256) {
            int b = i >> 8, q = i & 255;
            ((float4*)(hs[b]))[q] = ((const float4*)(g_h + b * HID + n0))[q];
        }
        __syncthreads();
#pragma unroll
        for (int pp = 0; pp < 4; pp++) {
            int p = pbase + warp * 4 + pp;
            const float4* wr = (const float4*)(w2 + (size_t)p * HID + n0);
#pragma unroll
            for (int it = 0; it < 8; it++) {
                int q = lane + it * 32;
                float4 w = wr[q];
#pragma unroll
                for (int b = 0; b < BB; b++) {
                    float4 h = ((const float4*)(hs[b]))[q];
                    acc[pp][b] += w.x * h.x + w.y * h.y + w.z * h.z + w.w * h.w;
                }
            }
        }
        __syncthreads();
    }
#pragma unroll
    for (int o = 16; o > 0; o >>= 1)
#pragma unroll
        for (int pp = 0; pp < 4; pp++)
#pragma unroll
            for (int b = 0; b < BB; b++)
                acc[pp][b] += __shfl_down_sync(0xffffffffu, acc[pp][b], o);
    if (lane == 0) {
#pragma unroll
        for (int pp = 0; pp < 4; pp++) {
            int p = pbase + warp * 4 + pp;
            float bp = b2[p];
#pragma unroll
            for (int b = 0; b < BB; b++) {
                float rel = acc[pp][b] + bp;
                g_sig[b * NP + p] = 1.0f / (1.0f + expf(-rel));
            }
        }
    }
}

// ---------------- K4: approx top-NC ----------------
__global__ void k_topkc() {
    __shared__ ull key[NP];
    int b = blockIdx.x, tid = threadIdx.x;
    for (int i = tid; i < NP; i += 1024) {
        float sc = gelu_f(fdec(g_scoreEnc[b * NP + i])) * g_sig[b * NP + i];
        key[i] = ((ull)fenc(sc) << 32) | (unsigned)i;
    }
    __syncthreads();
    for (int k = 2; k <= NP; k <<= 1) {
        for (int j = k >> 1; j > 0; j >>= 1) {
            for (int i = tid; i < NP; i += 1024) {
                int ix = i ^ j;
                if (ix > i) {
                    ull x = key[i], y = key[ix];
                    bool desc = ((i & k) == 0);
                    if (desc ? (x < y) : (x > y)) { key[i] = y; key[ix] = x; }
                }
            }
            __syncthreads();
        }
    }
    if (tid < NC) g_pidx512[b * NC + tid] = (int)(key[tid] & 0xffffffffu);
}

// ---------------- K5: refine — exact 3-pass bf16 z, forced 2 CTAs/SM ----------------
__global__ __launch_bounds__(256, 2)
void k_refine() {
    extern __shared__ char smem[];
    const u32 sbase = smem_u32(smem);
    const int tid = threadIdx.x;
    const int wid = tid >> 5, lid = tid & 31;
    const int wm = wid & 3, wn = wid >> 2;
    const int b  = blockIdx.z;
    const int n0 = blockIdx.x * 128;
    const int s0 = blockIdx.y * 128;

    float acc[2][8][4];
#pragma unroll
    for (int i = 0; i < 2; i++)
#pragma unroll
        for (int j = 0; j < 8; j++)
#pragma unroll
            for (int r = 0; r < 4; r++) acc[i][j][r] = 0.0f;

    auto load_stage = [&](int ks, int buf) {
        const int k0 = ks * 32;
        u32 sg = sbase + buf * STGB4;
#pragma unroll
        for (int i = 0; i < 4; i++) {
            int idx = tid + i * 256;
            int sp = idx >> 9, rem = idx & 511;
            int r = rem >> 2, c = rem & 3;
            const __nv_bfloat16* g = g_Asp + ((size_t)(b * 2 + sp) * SS + s0 + r) * KIN + k0 + c * 8;
            cpasync16(sg + sp * PLANE + r * RPAD + c * 16, g);
        }
#pragma unroll
        for (int i = 0; i < 4; i++) {
            int idx = tid + i * 256;
            int sp = idx >> 9, rem = idx & 511;
            int r = rem >> 2, c = rem & 3;
            const __nv_bfloat16* g = g_Bc + ((size_t)(b * 2 + sp) * NC + n0 + r) * KIN + k0 + c * 8;
            cpasync16(sg + 2 * PLANE + sp * PLANE + r * RPAD + c * 16, g);
        }
    };

    const u32 aoff = (u32)((wm * 32 + (lid & 15)) * RPAD + (lid >> 4) * 16);
    const u32 boff = (u32)((wn * 64 + (lid & 15)) * RPAD + (lid >> 4) * 16);

    load_stage(0, 0); CP_COMMIT();

#pragma unroll 1
    for (int ks = 0; ks < KIN / 32; ks++) {
        int buf = ks & 1;
        if (ks < KIN / 32 - 1) { load_stage(ks + 1, buf ^ 1); CP_COMMIT(); CP_WAIT(1); }
        else                   { CP_WAIT(0); }
        __syncthreads();
        u32 sA = sbase + buf * STGB4;
        u32 sB = sA + 2 * PLANE;
#pragma unroll
        for (int kk = 0; kk < 2; kk++) {
            u32 ah[2][4], am[2][4];
#pragma unroll
            for (int mt = 0; mt < 2; mt++) {
                ldsm4(ah[mt], sA + aoff + mt * (16 * RPAD) + kk * 32);
                ldsm4(am[mt], sA + PLANE + aoff + mt * (16 * RPAD) + kk * 32);
            }
            u32 bh[4][4], bm[4][4];
#pragma unroll
            for (int nt2 = 0; nt2 < 4; nt2++) {
                ldsm4(bh[nt2], sB + boff + nt2 * (16 * RPAD) + kk * 32);
                ldsm4(bm[nt2], sB + PLANE + boff + nt2 * (16 * RPAD) + kk * 32);
            }
#pragma unroll
            for (int mt = 0; mt < 2; mt++)
#pragma unroll
                for (int nt2 = 0; nt2 < 4; nt2++) {
                    mma16816(acc[mt][2 * nt2],     ah[mt], bh[nt2][0], bh[nt2][2]);
                    mma16816(acc[mt][2 * nt2 + 1], ah[mt], bh[nt2][1], bh[nt2][3]);
                    mma16816(acc[mt][2 * nt2],     ah[mt], bm[nt2][0], bm[nt2][2]);
                    mma16816(acc[mt][2 * nt2 + 1], ah[mt], bm[nt2][1], bm[nt2][3]);
                    mma16816(acc[mt][2 * nt2],     am[mt], bh[nt2][0], bh[nt2][2]);
                    mma16816(acc[mt][2 * nt2 + 1], am[mt], bh[nt2][1], bh[nt2][3]);
                }
        }
        __syncthreads();
    }

    u32* scol = (u32*)smem;
    if (tid < 128) scol[tid] = 0u;
    __syncthreads();

    const size_t PL = (size_t)SS * NC;
#pragma unroll
    for (int mt = 0; mt < 2; mt++)
#pragma unroll
        for (int nt = 0; nt < 8; nt++) {
            int row = s0 + wm * 32 + mt * 16 + (lid >> 2);
            int col = n0 + wn * 64 + nt * 8 + 2 * (lid & 3);
            float g0 = gelu_f(acc[mt][nt][0]), g1 = gelu_f(acc[mt][nt][1]);
            float g2 = gelu_f(acc[mt][nt][2]), g3 = gelu_f(acc[mt][nt][3]);
            H2U h01, m01, h23, m23;
            split2h(g0, h01.h[0], m01.h[0]); split2h(g1, h01.h[1], m01.h[1]);
            split2h(g2, h23.h[0], m23.h[0]); split2h(g3, h23.h[1], m23.h[1]);
            size_t base = ((size_t)(b * 2) * SS + row) * NC + col;
            *(u32*)(g_PC + base)               = h01.u;
            *(u32*)(g_PC + base + PL)          = m01.u;
            *(u32*)(g_PC + base + 8 * NC)      = h23.u;
            *(u32*)(g_PC + base + PL + 8 * NC) = m23.u;
        }
#pragma unroll
    for (int nt = 0; nt < 8; nt++) {
        float m0 = fmaxf(fmaxf(acc[0][nt][0], acc[0][nt][2]), fmaxf(acc[1][nt][0], acc[1][nt][2]));
        float m1 = fmaxf(fmaxf(acc[0][nt][1], acc[0][nt][3]), fmaxf(acc[1][nt][1], acc[1][nt][3]));
#pragma unroll
        for (int mk = 4; mk < 32; mk <<= 1) {
            m0 = fmaxf(m0, __shfl_xor_sync(0xffffffffu, m0, mk));
            m1 = fmaxf(m1, __shfl_xor_sync(0xffffffffu, m1, mk));
        }
        if (lid < 4) {
            atomicMax(&scol[wn * 64 + nt * 8 + 2 * lid],     fenc(m0));
            atomicMax(&scol[wn * 64 + nt * 8 + 2 * lid + 1], fenc(m1));
        }
    }
    __syncthreads();
    if (tid < 128) atomicMax(&g_scoreEnc2[b * NC + n0 + tid], scol[tid]);
}

// ---------------- K6: exact rescore + top-256 ----------------
__global__ void k_rescore() {
    __shared__ ull key[NCP];
    int b = blockIdx.x, tid = threadIdx.x;
    if (tid < NC) {
        float z = fdec(g_scoreEnc2[b * NC + tid]);
        int p = g_pidx512[b * NC + tid];
        float sc = gelu_f(z) * g_sig[b * NP + p];
        key[tid] = ((ull)fenc(sc) << 32) | (unsigned)tid;
    } else {
        key[tid] = 0ULL;
    }
    __syncthreads();
    for (int k = 2; k <= NCP; k <<= 1) {
        for (int j = k >> 1; j > 0; j >>= 1) {
            int i = tid;
            int ix = i ^ j;
            if (ix > i) {
                ull x = key[i], y = key[ix];
                bool desc = ((i & k) == 0);
                if (desc ? (x < y) : (x > y)) { key[i] = y; key[ix] = x; }
            }
            __syncthreads();
        }
    }
    if (tid < KSEL) {
        int slot = (int)(key[tid] & 0xffffffffu);
        g_cmap[b * KSEL + tid] = slot;
        g_pidx[b * KSEL + tid] = g_pidx512[b * NC + slot];
    }
}

// ---------------- K7: compact via smem staging ----------------
__global__ void k_compact() {
    __shared__ __half st[2][8][NC];
    __shared__ int cm[KSEL];
    int blk = blockIdx.x;
    int b = blk / (SS / 8);
    int s8 = (blk % (SS / 8)) * 8;
    int tid = threadIdx.x;
    if (tid < KSEL) cm[tid] = g_cmap[b * KSEL + tid];
    const int4* src0 = (const int4*)(g_PC + ((size_t)(b * 2)     * SS + s8) * NC);
    const int4* src1 = (const int4*)(g_PC + ((size_t)(b * 2 + 1) * SS + s8) * NC);
    int4* d0 = (int4*)&st[0][0][0];
    int4* d1 = (int4*)&st[1][0][0];
    const int NI4 = 8 * NC / 8;
    for (int idx = tid; idx < NI4; idx += 256) {
        d0[idx] = src0[idx];
        d1[idx] = src1[idx];
    }
    __syncthreads();
    int j = tid;
    int c = cm[j];
    const size_t PLa = (size_t)SS * KSEL;
#pragma unroll
    for (int r = 0; r < 8; r++) {
        size_t dst = ((size_t)(b * 2) * SS + s8 + r) * KSEL + j;
        g_PA[dst]       = st[0][r][c];
        g_PA[dst + PLa] = st[1][r][c];
    }
}

// ---------------- K8: gather + transpose proj rows -> f16 single plane ----------------
__global__ void k_projsplit(const float* __restrict__ proj) {
    __shared__ float t[32][33];
    __shared__ int pj[32];
    int j0 = blockIdx.x * 32, d0 = blockIdx.y * 32, b = blockIdx.z;
    int tx = threadIdx.x, ty = threadIdx.y;
    if (ty == 0) pj[tx] = g_pidx[b * KSEL + j0 + tx];
    __syncthreads();
#pragma unroll
    for (int i = 0; i < 32; i += 8) {
        int p = pj[ty + i];
        t[ty + i][tx] = proj[(size_t)p * DM + d0 + tx];
    }
    __syncthreads();
#pragma unroll
    for (int i = 0; i < 32; i += 8) {
        float v = t[tx][ty + i];
        g_Pr[((size_t)b * DM + d0 + ty + i) * KSEL + j0 + tx] = __float2half(v);
    }
}

// ---------------- K9: final GEMM (f16 2-pass), forced 2 CTAs/SM ----------------
__global__ __launch_bounds__(256, 2)
void k_gemm3t(float* __restrict__ out) {
    extern __shared__ char smem[];
    const u32 sbase = smem_u32(smem);
    const int tid = threadIdx.x;
    const int wid = tid >> 5, lid = tid & 31;
    const int wm = wid & 3, wn = wid >> 2;
    const int b  = blockIdx.z;
    const int d0 = blockIdx.x * 128;
    const int s0 = blockIdx.y * 128;

    float acc[2][8][4];
#pragma unroll
    for (int i = 0; i < 2; i++)
#pragma unroll
        for (int j = 0; j < 8; j++)
#pragma unroll
            for (int r = 0; r < 4; r++) acc[i][j][r] = 0.0f;

    auto load_stage = [&](int ks, int buf) {
        const int k0 = ks * 32;
        u32 sg = sbase + buf * STG3;
#pragma unroll
        for (int i = 0; i < 4; i++) {
            int idx = tid + i * 256;
            int sp = idx >> 9, rem = idx & 511;
            int r = rem >> 2, c = rem & 3;
            const __half* g = g_PA + ((size_t)(b * 2 + sp) * SS + s0 + r) * KSEL + k0 + c * 8;
            cpasync16(sg + sp * PLANE + r * RPAD + c * 16, g);
        }
#pragma unroll
        for (int i = 0; i < 2; i++) {
            int idx = tid + i * 256;
            int r = idx >> 2, c = idx & 3;
            const __half* g = g_Pr + ((size_t)b * DM + d0 + r) * KSEL + k0 + c * 8;
            cpasync16(sg + 2 * PLANE + r * RPAD + c * 16, g);
        }
    };

    const u32 aoff = (u32)((wm * 32 + (lid & 15)) * RPAD + (lid >> 4) * 16);
    const u32 boff = (u32)((wn * 64 + (lid & 15)) * RPAD + (lid >> 4) * 16);

    load_stage(0, 0); CP_COMMIT();

#pragma unroll 1
    for (int ks = 0; ks < KSEL / 32; ks++) {
        int buf = ks & 1;
        if (ks < KSEL / 32 - 1) { load_stage(ks + 1, buf ^ 1); CP_COMMIT(); CP_WAIT(1); }
        else                    { CP_WAIT(0); }
        __syncthreads();
        u32 sA = sbase + buf * STG3;
        u32 sB = sA + 2 * PLANE;
#pragma unroll
        for (int kk = 0; kk < 2; kk++) {
            u32 ah[2][4], am[2][4];
#pragma unroll
            for (int mt = 0; mt < 2; mt++) {
                ldsm4(ah[mt], sA + aoff + mt * (16 * RPAD) + kk * 32);
                ldsm4(am[mt], sA + PLANE + aoff + mt * (16 * RPAD) + kk * 32);
            }
            u32 bh[4][4];
#pragma unroll
            for (int nt2 = 0; nt2 < 4; nt2++)
                ldsm4(bh[nt2], sB + boff + nt2 * (16 * RPAD) + kk * 32);
#pragma unroll
            for (int mt = 0; mt < 2; mt++)
#pragma unroll
                for (int nt2 = 0; nt2 < 4; nt2++) {
                    mma16816f(acc[mt][2 * nt2],     ah[mt], bh[nt2][0], bh[nt2][2]);
                    mma16816f(acc[mt][2 * nt2 + 1], ah[mt], bh[nt2][1], bh[nt2][3]);
                    mma16816f(acc[mt][2 * nt2],     am[mt], bh[nt2][0], bh[nt2][2]);
                    mma16816f(acc[mt][2 * nt2 + 1], am[mt], bh[nt2][1], bh[nt2][3]);
                }
        }
        __syncthreads();
    }
#pragma unroll
    for (int mt = 0; mt < 2; mt++)
#pragma unroll
        for (int nt = 0; nt < 8; nt++) {
            int row = s0 + wm * 32 + mt * 16 + (lid >> 2);
            int col = d0 + wn * 64 + nt * 8 + 2 * (lid & 3);
            float* po = out + ((size_t)b * SS + row) * DM + col;
            *(float2*)po            = make_float2(acc[mt][nt][0], acc[mt][nt][1]);
            *(float2*)(po + 8 * DM) = make_float2(acc[mt][nt][2], acc[mt][nt][3]);
        }
}

// ---------------- entry (multi-stream fork/join) ----------------
extern "C" void kernel_launch(void* const* d_in, const int* in_sizes, int n_in,
                              void* d_out, int out_size) {
    const float* act  = (const float*)d_in[0];
    const int*   sidx = (const int*)d_in[1];
    int o = (n_in >= 9 && in_sizes[2] == 1) ? 3 : 2;
    const float* cw   = (const float*)d_in[o + 0];
    const float* proj = (const float*)d_in[o + 1];
    const float* w1   = (const float*)d_in[o + 2];
    const float* b1   = (const float*)d_in[o + 3];
    const float* w2   = (const float*)d_in[o + 4];
    const float* b2   = (const float*)d_in[o + 5];
    float* out = (float*)d_out;

    static cudaStream_t s1 = nullptr;
    static cudaEvent_t ev0 = nullptr, evA = nullptr, ev1 = nullptr, ev2 = nullptr, ev3 = nullptr;
    if (s1 == nullptr) {
        cudaStreamCreateWithFlags(&s1, cudaStreamNonBlocking);
        cudaEventCreateWithFlags(&ev0, cudaEventDisableTiming);
        cudaEventCreateWithFlags(&evA, cudaEventDisableTiming);
        cudaEventCreateWithFlags(&ev1, cudaEventDisableTiming);
        cudaEventCreateWithFlags(&ev2, cudaEventDisableTiming);
        cudaEventCreateWithFlags(&ev3, cudaEventDisableTiming);
        cudaFuncSetAttribute(k_gemm1a, cudaFuncAttributeMaxDynamicSharedMemorySize, GSMEM1);
        cudaFuncSetAttribute(k_refine, cudaFuncAttributeMaxDynamicSharedMemorySize, GSMEM4);
        cudaFuncSetAttribute(k_gemm3t, cudaFuncAttributeMaxDynamicSharedMemorySize, GSMEM3);
        cudaFuncSetAttribute(k_hidden, cudaFuncAttributeMaxDynamicSharedMemorySize, BB * NIN * 4);
    }

    // fork: merged A split (+score init) + MLP chain on s1
    cudaEventRecord(ev0, 0);
    cudaStreamWaitEvent(s1, ev0, 0);
    k_splitA<<<(BB * SS * KIN / 4) / 256, 256, 0, s1>>>(act);
    cudaEventRecord(evA, s1);
    k_initMask<<<(BB * NIN + 255) / 256, 256, 0, s1>>>();
    k_scatter<<<(BB * KIN + 255) / 256, 256, 0, s1>>>(sidx);
    k_hidden<<<HID / 8, 256, BB * NIN * 4, s1>>>(w1, b1);
    k_relsig<<<NP / 32, 256, 0, s1>>>(w2, b2);
    cudaEventRecord(ev1, s1);

    // main chain
    k_gatherBh<<<NP, 256>>>(cw, sidx);
    cudaStreamWaitEvent(0, evA, 0);
    k_gemm1a<<<dim3(NP / 256, SS / 128, BB), 256, GSMEM1>>>();

    // join
    cudaStreamWaitEvent(0, ev1, 0);
    k_topkc<<<BB, 1024>>>();
    k_gatherBc<<<BB * NC, 256>>>(cw, sidx);
    k_refine<<<dim3(NC / 128, SS / 128, BB), 256, GSMEM4>>>();
    k_rescore<<<BB, NCP>>>();

    // fork: projsplit on s1, compact on main
    cudaEventRecord(ev2, 0);
    cudaStreamWaitEvent(s1, ev2, 0);
    k_projsplit<<<dim3(KSEL / 32, DM / 32, BB), dim3(32, 8), 0, s1>>>(proj);
    cudaEventRecord(ev3, s1);
    k_compact<<<BB * SS / 8, 256>>>();
    cudaStreamWaitEvent(0, ev3, 0);

    k_gemm3t<<<dim3(DM / 128, SS / 128, BB), 256, GSMEM3>>>(out);
}

// round 17
// speedup vs baseline: 1.6775x; 1.0028x over previous
#include <cuda_runtime.h>
#include <cuda_bf16.h>
#include <cuda_fp16.h>

#define BB   8
#define SS   2048
#define KIN  512
#define NIN  2048
#define NP   4096
#define HID  4096
#define DM   1024
#define KSEL 256
#define NC   384
#define NCP  512

typedef unsigned long long ull;
typedef unsigned int u32;

// ---------------- scratch ----------------
__device__ __align__(256) __nv_bfloat16 g_Asp[(size_t)BB * 2 * SS * KIN];
__device__ __align__(256) __half        g_Ah16[(size_t)BB * SS * KIN];
__device__ __align__(256) __half        g_Bh [(size_t)BB * NP * KIN];
__device__ __align__(256) __nv_bfloat16 g_Bc [(size_t)BB * 2 * NC * KIN];
__device__ __align__(256) __half        g_PC [(size_t)BB * 2 * SS * NC];
__device__ __align__(256) __half        g_PA [(size_t)BB * 2 * SS * KSEL];
__device__ __align__(256) __half        g_Pr [(size_t)BB * DM * KSEL];
__device__ float    g_mask[BB * NIN];
__device__ float    g_h[BB * HID];
__device__ float    g_sig[BB * NP];
__device__ unsigned g_scoreEnc[BB * NP];
__device__ unsigned g_scoreEnc2[BB * NC];
__device__ int      g_pidx512[BB * NC];
__device__ int      g_pidx[BB * KSEL];
__device__ int      g_cmap[BB * KSEL];

// ---------------- helpers ----------------
__device__ __forceinline__ unsigned fenc(float f) {
    unsigned u = __float_as_uint(f);
    return (u & 0x80000000u) ? ~u : (u | 0x80000000u);
}
__device__ __forceinline__ float fdec(unsigned u) {
    return __uint_as_float((u & 0x80000000u) ? (u & 0x7fffffffu) : ~u);
}
__device__ __forceinline__ float gelu_f(float x) {
    return 0.5f * x * (1.0f + erff(x * 0.70710678118654752f));
}
__device__ __forceinline__ u32 smem_u32(const void* p) {
    u32 a; asm("{ .reg .u64 t; cvta.to.shared.u64 t, %1; cvt.u32.u64 %0, t; }" : "=r"(a) : "l"(p));
    return a;
}
__device__ __forceinline__ void split2(float a, __nv_bfloat16& h, __nv_bfloat16& m) {
    h = __float2bfloat16(a);
    m = __float2bfloat16(a - __bfloat162float(h));
}
__device__ __forceinline__ void split2h(float a, __half& h, __half& m) {
    h = __float2half(a);
    m = __float2half(a - __half2float(h));
}

// ---------------- mma.sync / ldmatrix / cp.async ----------------
__device__ __forceinline__ void mma16816(float* d, const u32* a, u32 b0, u32 b1) {
    asm volatile("mma.sync.aligned.m16n8k16.row.col.f32.bf16.bf16.f32 "
        "{%0,%1,%2,%3}, {%4,%5,%6,%7}, {%8,%9}, {%0,%1,%2,%3};"
        : "+f"(d[0]), "+f"(d[1]), "+f"(d[2]), "+f"(d[3])
        : "r"(a[0]), "r"(a[1]), "r"(a[2]), "r"(a[3]), "r"(b0), "r"(b1));
}
__device__ __forceinline__ void mma16816f(float* d, const u32* a, u32 b0, u32 b1) {
    asm volatile("mma.sync.aligned.m16n8k16.row.col.f32.f16.f16.f32 "
        "{%0,%1,%2,%3}, {%4,%5,%6,%7}, {%8,%9}, {%0,%1,%2,%3};"
        : "+f"(d[0]), "+f"(d[1]), "+f"(d[2]), "+f"(d[3])
        : "r"(a[0]), "r"(a[1]), "r"(a[2]), "r"(a[3]), "r"(b0), "r"(b1));
}
__device__ __forceinline__ void mma16816h(u32* d, const u32* a, u32 b0, u32 b1) {
    asm volatile("mma.sync.aligned.m16n8k16.row.col.f16.f16.f16.f16 "
        "{%0,%1}, {%2,%3,%4,%5}, {%6,%7}, {%0,%1};"
        : "+r"(d[0]), "+r"(d[1])
        : "r"(a[0]), "r"(a[1]), "r"(a[2]), "r"(a[3]), "r"(b0), "r"(b1));
}
__device__ __forceinline__ void ldsm4(u32* r, u32 addr) {
    asm volatile("ldmatrix.sync.aligned.m8n8.x4.shared.b16 {%0,%1,%2,%3}, [%4];"
        : "=r"(r[0]), "=r"(r[1]), "=r"(r[2]), "=r"(r[3]) : "r"(addr));
}
__device__ __forceinline__ void cpasync16(u32 dst, const void* src) {
    asm volatile("cp.async.cg.shared.global [%0], [%1], 16;" :: "r"(dst), "l"(src));
}
#define CP_COMMIT() asm volatile("cp.async.commit_group;" ::: "memory")
#define CP_WAIT(n)  asm volatile("cp.async.wait_group %0;" :: "n"(n) : "memory")

#define RPAD   80
#define PLANE  (128 * RPAD)          // 10240
#define STGB4  (4 * PLANE)
#define GSMEM4 (2 * STGB4)           // 81920 -> 2 CTAs/SM
#define STG1   (2 * PLANE)           // gemm1a stage (A 128r + B 128r): 20480
#define GSMEM1 (2 * STG1)            // 40960 -> 3 CTAs/SM by smem
#define STG3   (3 * PLANE)
#define GSMEM3 (2 * STG3)            // 61440

// ---------------- init kernels ----------------
__global__ void k_initMask() {
    int t = blockIdx.x * blockDim.x + threadIdx.x;
    if (t < BB * NIN) g_mask[t] = 0.0f;
}
__global__ void k_scatter(const int* __restrict__ sidx) {
    int t = blockIdx.x * blockDim.x + threadIdx.x;
    if (t < BB * KIN) {
        int b = t >> 9;
        g_mask[b * NIN + sidx[t]] = 1.0f;
    }
}

// ---------------- merged A split (+ score-buffer init folded in) ----------------
union B4U { __nv_bfloat16 h[4]; ull u; };
union B2U { __nv_bfloat16 h[2]; u32 u; };
union H4U { __half h[4]; ull u; };
union H2U { __half h[2]; u32 u; };

__global__ void k_splitA(const float* __restrict__ act) {
    size_t t = (size_t)blockIdx.x * 256 + threadIdx.x;
    if (blockIdx.x < (BB * NP + 255) / 256) {
        int z = blockIdx.x * 256 + threadIdx.x;
        if (z < BB * NP) g_scoreEnc[z] = 0u;
        if (z < BB * NC) g_scoreEnc2[z] = 0u;
    }
    size_t bs = t >> 7;
    int k4 = (int)(t & 127);
    int b = (int)(bs >> 11), s = (int)(bs & 2047);
    float4 v = ((const float4*)act)[t];
    float vv[4] = { v.x, v.y, v.z, v.w };
    H4U f16; B4U hh, mm;
#pragma unroll
    for (int i = 0; i < 4; i++) {
        f16.h[i] = __float2half(vv[i]);
        hh.h[i] = __float2bfloat16(vv[i]);
        mm.h[i] = __float2bfloat16(vv[i] - __bfloat162float(hh.h[i]));
    }
    *(ull*)(g_Ah16 + t * 4) = f16.u;
    size_t base = ((size_t)(b * 2) * SS + s) * KIN + k4 * 4;
    const size_t PL = (size_t)SS * KIN;
    *(ull*)(g_Asp + base)      = hh.u;
    *(ull*)(g_Asp + base + PL) = mm.u;
}

// ---------------- gather B f16 (full 4096 rows) ----------------
__global__ void k_gatherBh(const float* __restrict__ cw, const int* __restrict__ sidx) {
    __shared__ float row[NIN];
    __shared__ int sidxS[BB * KIN];
    int p = blockIdx.x, tid = threadIdx.x;
    for (int i = tid; i < NIN; i += 256) row[i] = cw[(size_t)p * NIN + i];
    for (int i = tid; i < BB * KIN / 4; i += 256)
        ((int4*)sidxS)[i] = ((const int4*)sidx)[i];
    __syncthreads();
    int k = tid * 2;
#pragma unroll 1
    for (int b = 0; b < BB; b++) {
        int i0 = sidxS[b * KIN + k], i1 = sidxS[b * KIN + k + 1];
        H2U hh;
        hh.h[0] = __float2half(row[i0]);
        hh.h[1] = __float2half(row[i1]);
        *(u32*)(g_Bh + ((size_t)b * NP + p) * KIN + k) = hh.u;
    }
}

// ---------------- gather B splits for NC candidates ----------------
__global__ void k_gatherBc(const float* __restrict__ cw, const int* __restrict__ sidx) {
    __shared__ float row[NIN];
    int blk = blockIdx.x;
    int b = blk / NC, j = blk % NC;
    int tid = threadIdx.x;
    int p = g_pidx512[b * NC + j];
    for (int i = tid; i < NIN; i += 256) row[i] = cw[(size_t)p * NIN + i];
    __syncthreads();
    int k = tid * 2;
    int i0 = sidx[b * KIN + k], i1 = sidx[b * KIN + k + 1];
    B2U hh, mm;
    split2(row[i0], hh.h[0], mm.h[0]);
    split2(row[i1], hh.h[1], mm.h[1]);
    const size_t PL = (size_t)NC * KIN;
    size_t base = ((size_t)(b * 2) * NC + j) * KIN + k;
    *(u32*)(g_Bc + base)      = hh.u;
    *(u32*)(g_Bc + base + PL) = mm.u;
}

// ---------------- K1a: approx score GEMM, f16 acc, 128x128 tile, 3 CTAs/SM ----------------
__global__ __launch_bounds__(256, 3)
void k_gemm1a() {
    extern __shared__ char smem[];
    const u32 sbase = smem_u32(smem);
    const int tid = threadIdx.x;
    const int wid = tid >> 5, lid = tid & 31;
    const int wm = wid & 3, wn = wid >> 2;       // warp tile 32 x 64
    const int b  = blockIdx.z;
    const int p0 = blockIdx.x * 128;
    const int s0 = blockIdx.y * 128;

    u32 acc[2][8][2];
#pragma unroll
    for (int i = 0; i < 2; i++)
#pragma unroll
        for (int j = 0; j < 8; j++) { acc[i][j][0] = 0u; acc[i][j][1] = 0u; }

    auto load_stage = [&](int ks, int buf) {
        const int k0 = ks * 32;
        u32 sgA = sbase + buf * STG1;
        u32 sgB = sgA + PLANE;
#pragma unroll
        for (int i = 0; i < 2; i++) {
            int idx = tid + i * 256;
            int r = idx >> 2, c = idx & 3;
            const __half* g = g_Ah16 + ((size_t)b * SS + s0 + r) * KIN + k0 + c * 8;
            cpasync16(sgA + r * RPAD + c * 16, g);
        }
#pragma unroll
        for (int i = 0; i < 2; i++) {
            int idx = tid + i * 256;
            int r = idx >> 2, c = idx & 3;
            const __half* g = g_Bh + ((size_t)b * NP + p0 + r) * KIN + k0 + c * 8;
            cpasync16(sgB + r * RPAD + c * 16, g);
        }
    };

    const u32 aoff = (u32)((wm * 32 + (lid & 15)) * RPAD + (lid >> 4) * 16);
    const u32 boff = (u32)((wn * 64 + (lid & 15)) * RPAD + (lid >> 4) * 16);

    load_stage(0, 0); CP_COMMIT();

#pragma unroll 1
    for (int ks = 0; ks < KIN / 32; ks++) {
        int buf = ks & 1;
        if (ks < KIN / 32 - 1) { load_stage(ks + 1, buf ^ 1); CP_COMMIT(); CP_WAIT(1); }
        else                   { CP_WAIT(0); }
        __syncthreads();
        u32 sA = sbase + buf * STG1;
        u32 sB = sA + PLANE;
#pragma unroll
        for (int kk = 0; kk < 2; kk++) {
            u32 ah[2][4];
#pragma unroll
            for (int mt = 0; mt < 2; mt++)
                ldsm4(ah[mt], sA + aoff + mt * (16 * RPAD) + kk * 32);
            u32 bh[4][4];
#pragma unroll
            for (int q = 0; q < 4; q++)
                ldsm4(bh[q], sB + boff + q * (16 * RPAD) + kk * 32);
#pragma unroll
            for (int mt = 0; mt < 2; mt++)
#pragma unroll
                for (int q = 0; q < 4; q++) {
                    mma16816h(acc[mt][2 * q],     ah[mt], bh[q][0], bh[q][2]);
                    mma16816h(acc[mt][2 * q + 1], ah[mt], bh[q][1], bh[q][3]);
                }
        }
        __syncthreads();
    }

    u32* scol = (u32*)smem;
    if (tid < 128) scol[tid] = 0u;
    __syncthreads();
#pragma unroll
    for (int nt = 0; nt < 8; nt++) {
        float m0 = -1e30f, m1 = -1e30f;
#pragma unroll
        for (int mt = 0; mt < 2; mt++) {
            float2 lo = __half22float2(*(const __half2*)&acc[mt][nt][0]);
            float2 hi = __half22float2(*(const __half2*)&acc[mt][nt][1]);
            m0 = fmaxf(m0, fmaxf(lo.x, hi.x));
            m1 = fmaxf(m1, fmaxf(lo.y, hi.y));
        }
#pragma unroll
        for (int mk = 4; mk < 32; mk <<= 1) {
            m0 = fmaxf(m0, __shfl_xor_sync(0xffffffffu, m0, mk));
            m1 = fmaxf(m1, __shfl_xor_sync(0xffffffffu, m1, mk));
        }
        if (lid < 4) {
            atomicMax(&scol[wn * 64 + nt * 8 + 2 * lid],     fenc(m0));
            atomicMax(&scol[wn * 64 + nt * 8 + 2 * lid + 1], fenc(m1));
        }
    }
    __syncthreads();
    if (tid < 128) atomicMax(&g_scoreEnc[b * NP + p0 + tid], scol[tid]);
}

// ---------------- K2: hidden MLP ----------------
__global__ __launch_bounds__(256)
void k_hidden(const float* __restrict__ w1, const float* __restrict__ b1) {
    extern __shared__ float ms[];
    int tid = threadIdx.x, warp = tid >> 5, lane = tid & 31;
    for (int i = tid; i < BB * NIN / 4; i += 256)
        ((float4*)ms)[i] = ((const float4*)g_mask)[i];
    __syncthreads();
    int j = blockIdx.x * 8 + warp;
    const float4* wr = (const float4*)(w1 + (size_t)j * NIN);
    float acc[BB];
#pragma unroll
    for (int b = 0; b < BB; b++) acc[b] = 0.0f;
#pragma unroll
    for (int it = 0; it < NIN / 128; it++) {
        int q = lane + it * 32;
        float4 w = wr[q];
#pragma unroll
        for (int b = 0; b < BB; b++) {
            float4 m = ((const float4*)(ms + b * NIN))[q];
            acc[b] += w.x * m.x + w.y * m.y + w.z * m.z + w.w * m.w;
        }
    }
#pragma unroll
    for (int o = 16; o > 0; o >>= 1)
#pragma unroll
        for (int b = 0; b < BB; b++) acc[b] += __shfl_down_sync(0xffffffffu, acc[b], o);
    if (lane == 0) {
        float bj = b1[j];
#pragma unroll
        for (int b = 0; b < BB; b++) g_h[b * HID + j] = gelu_f(acc[b] + bj);
    }
}

// ---------------- K3a: relevance -> sigmoid ----------------
__global__ __launch_bounds__(256)
void k_relsig(const float* __restrict__ w2, const float* __restrict__ b2) {
    __shared__ float hs[BB][1024];
    int tid = threadIdx.x, warp = tid >> 5, lane = tid & 31;
    int pbase = blockIdx.x * 32;
    float acc[4][BB];
#pragma unroll
    for (int pp = 0; pp < 4; pp++)
#pragma unroll
        for (int b = 0; b < BB; b++) acc[pp][b] = 0.0f;

#pragma unroll 1
    for (int ch = 0; ch < HID / 1024; ch++) {
        int n0 = ch * 1024;
        for (int i = tid; i < BB * 1024 / 4; i += 256) {
            int b = i >> 8, q = i & 255;
            ((float4*)(hs[b]))[q] = ((const float4*)(g_h + b * HID + n0))[q];
        }
        __syncthreads();
#pragma unroll
        for (int pp = 0; pp < 4; pp++) {
            int p = pbase + warp * 4 + pp;
            const float4* wr = (const float4*)(w2 + (size_t)p * HID + n0);
#pragma unroll
            for (int it = 0; it < 8; it++) {
                int q = lane + it * 32;
                float4 w = wr[q];
#pragma unroll
                for (int b = 0; b < BB; b++) {
                    float4 h = ((const float4*)(hs[b]))[q];
                    acc[pp][b] += w.x * h.x + w.y * h.y + w.z * h.z + w.w * h.w;
                }
            }
        }
        __syncthreads();
    }
#pragma unroll
    for (int o = 16; o > 0; o >>= 1)
#pragma unroll
        for (int pp = 0; pp < 4; pp++)
#pragma unroll
            for (int b = 0; b < BB; b++)
                acc[pp][b] += __shfl_down_sync(0xffffffffu, acc[pp][b], o);
    if (lane == 0) {
#pragma unroll
        for (int pp = 0; pp < 4; pp++) {
            int p = pbase + warp * 4 + pp;
            float bp = b2[p];
#pragma unroll
            for (int b = 0; b < BB; b++) {
                float rel = acc[pp][b] + bp;
                g_sig[b * NP + p] = 1.0f / (1.0f + expf(-rel));
            }
        }
    }
}

// ---------------- K4: approx top-NC ----------------
__global__ void k_topkc() {
    __shared__ ull key[NP];
    int b = blockIdx.x, tid = threadIdx.x;
    for (int i = tid; i < NP; i += 1024) {
        float sc = gelu_f(fdec(g_scoreEnc[b * NP + i])) * g_sig[b * NP + i];
        key[i] = ((ull)fenc(sc) << 32) | (unsigned)i;
    }
    __syncthreads();
    for (int k = 2; k <= NP; k <<= 1) {
        for (int j = k >> 1; j > 0; j >>= 1) {
            for (int i = tid; i < NP; i += 1024) {
                int ix = i ^ j;
                if (ix > i) {
                    ull x = key[i], y = key[ix];
                    bool desc = ((i & k) == 0);
                    if (desc ? (x < y) : (x > y)) { key[i] = y; key[ix] = x; }
                }
            }
            __syncthreads();
        }
    }
    if (tid < NC) g_pidx512[b * NC + tid] = (int)(key[tid] & 0xffffffffu);
}

// ---------------- K5: refine — exact 3-pass bf16 z, 2 CTAs/SM ----------------
__global__ __launch_bounds__(256, 2)
void k_refine() {
    extern __shared__ char smem[];
    const u32 sbase = smem_u32(smem);
    const int tid = threadIdx.x;
    const int wid = tid >> 5, lid = tid & 31;
    const int wm = wid & 3, wn = wid >> 2;
    const int b  = blockIdx.z;
    const int n0 = blockIdx.x * 128;
    const int s0 = blockIdx.y * 128;

    float acc[2][8][4];
#pragma unroll
    for (int i = 0; i < 2; i++)
#pragma unroll
        for (int j = 0; j < 8; j++)
#pragma unroll
            for (int r = 0; r < 4; r++) acc[i][j][r] = 0.0f;

    auto load_stage = [&](int ks, int buf) {
        const int k0 = ks * 32;
        u32 sg = sbase + buf * STGB4;
#pragma unroll
        for (int i = 0; i < 4; i++) {
            int idx = tid + i * 256;
            int sp = idx >> 9, rem = idx & 511;
            int r = rem >> 2, c = rem & 3;
            const __nv_bfloat16* g = g_Asp + ((size_t)(b * 2 + sp) * SS + s0 + r) * KIN + k0 + c * 8;
            cpasync16(sg + sp * PLANE + r * RPAD + c * 16, g);
        }
#pragma unroll
        for (int i = 0; i < 4; i++) {
            int idx = tid + i * 256;
            int sp = idx >> 9, rem = idx & 511;
            int r = rem >> 2, c = rem & 3;
            const __nv_bfloat16* g = g_Bc + ((size_t)(b * 2 + sp) * NC + n0 + r) * KIN + k0 + c * 8;
            cpasync16(sg + 2 * PLANE + sp * PLANE + r * RPAD + c * 16, g);
        }
    };

    const u32 aoff = (u32)((wm * 32 + (lid & 15)) * RPAD + (lid >> 4) * 16);
    const u32 boff = (u32)((wn * 64 + (lid & 15)) * RPAD + (lid >> 4) * 16);

    load_stage(0, 0); CP_COMMIT();

#pragma unroll 1
    for (int ks = 0; ks < KIN / 32; ks++) {
        int buf = ks & 1;
        if (ks < KIN / 32 - 1) { load_stage(ks + 1, buf ^ 1); CP_COMMIT(); CP_WAIT(1); }
        else                   { CP_WAIT(0); }
        __syncthreads();
        u32 sA = sbase + buf * STGB4;
        u32 sB = sA + 2 * PLANE;
#pragma unroll
        for (int kk = 0; kk < 2; kk++) {
            u32 ah[2][4], am[2][4];
#pragma unroll
            for (int mt = 0; mt < 2; mt++) {
                ldsm4(ah[mt], sA + aoff + mt * (16 * RPAD) + kk * 32);
                ldsm4(am[mt], sA + PLANE + aoff + mt * (16 * RPAD) + kk * 32);
            }
            u32 bh[4][4], bm[4][4];
#pragma unroll
            for (int nt2 = 0; nt2 < 4; nt2++) {
                ldsm4(bh[nt2], sB + boff + nt2 * (16 * RPAD) + kk * 32);
                ldsm4(bm[nt2], sB + PLANE + boff + nt2 * (16 * RPAD) + kk * 32);
            }
#pragma unroll
            for (int mt = 0; mt < 2; mt++)
#pragma unroll
                for (int nt2 = 0; nt2 < 4; nt2++) {
                    mma16816(acc[mt][2 * nt2],     ah[mt], bh[nt2][0], bh[nt2][2]);
                    mma16816(acc[mt][2 * nt2 + 1], ah[mt], bh[nt2][1], bh[nt2][3]);
                    mma16816(acc[mt][2 * nt2],     ah[mt], bm[nt2][0], bm[nt2][2]);
                    mma16816(acc[mt][2 * nt2 + 1], ah[mt], bm[nt2][1], bm[nt2][3]);
                    mma16816(acc[mt][2 * nt2],     am[mt], bh[nt2][0], bh[nt2][2]);
                    mma16816(acc[mt][2 * nt2 + 1], am[mt], bh[nt2][1], bh[nt2][3]);
                }
        }
        __syncthreads();
    }

    u32* scol = (u32*)smem;
    if (tid < 128) scol[tid] = 0u;
    __syncthreads();

    const size_t PL = (size_t)SS * NC;
#pragma unroll
    for (int mt = 0; mt < 2; mt++)
#pragma unroll
        for (int nt = 0; nt < 8; nt++) {
            int row = s0 + wm * 32 + mt * 16 + (lid >> 2);
            int col = n0 + wn * 64 + nt * 8 + 2 * (lid & 3);
            float g0 = gelu_f(acc[mt][nt][0]), g1 = gelu_f(acc[mt][nt][1]);
            float g2 = gelu_f(acc[mt][nt][2]), g3 = gelu_f(acc[mt][nt][3]);
            H2U h01, m01, h23, m23;
            split2h(g0, h01.h[0], m01.h[0]); split2h(g1, h01.h[1], m01.h[1]);
            split2h(g2, h23.h[0], m23.h[0]); split2h(g3, h23.h[1], m23.h[1]);
            size_t base = ((size_t)(b * 2) * SS + row) * NC + col;
            *(u32*)(g_PC + base)               = h01.u;
            *(u32*)(g_PC + base + PL)          = m01.u;
            *(u32*)(g_PC + base + 8 * NC)      = h23.u;
            *(u32*)(g_PC + base + PL + 8 * NC) = m23.u;
        }
#pragma unroll
    for (int nt = 0; nt < 8; nt++) {
        float m0 = fmaxf(fmaxf(acc[0][nt][0], acc[0][nt][2]), fmaxf(acc[1][nt][0], acc[1][nt][2]));
        float m1 = fmaxf(fmaxf(acc[0][nt][1], acc[0][nt][3]), fmaxf(acc[1][nt][1], acc[1][nt][3]));
#pragma unroll
        for (int mk = 4; mk < 32; mk <<= 1) {
            m0 = fmaxf(m0, __shfl_xor_sync(0xffffffffu, m0, mk));
            m1 = fmaxf(m1, __shfl_xor_sync(0xffffffffu, m1, mk));
        }
        if (lid < 4) {
            atomicMax(&scol[wn * 64 + nt * 8 + 2 * lid],     fenc(m0));
            atomicMax(&scol[wn * 64 + nt * 8 + 2 * lid + 1], fenc(m1));
        }
    }
    __syncthreads();
    if (tid < 128) atomicMax(&g_scoreEnc2[b * NC + n0 + tid], scol[tid]);
}

// ---------------- K6: exact rescore + top-256 ----------------
__global__ void k_rescore() {
    __shared__ ull key[NCP];
    int b = blockIdx.x, tid = threadIdx.x;
    if (tid < NC) {
        float z = fdec(g_scoreEnc2[b * NC + tid]);
        int p = g_pidx512[b * NC + tid];
        float sc = gelu_f(z) * g_sig[b * NP + p];
        key[tid] = ((ull)fenc(sc) << 32) | (unsigned)tid;
    } else {
        key[tid] = 0ULL;
    }
    __syncthreads();
    for (int k = 2; k <= NCP; k <<= 1) {
        for (int j = k >> 1; j > 0; j >>= 1) {
            int i = tid;
            int ix = i ^ j;
            if (ix > i) {
                ull x = key[i], y = key[ix];
                bool desc = ((i & k) == 0);
                if (desc ? (x < y) : (x > y)) { key[i] = y; key[ix] = x; }
            }
            __syncthreads();
        }
    }
    if (tid < KSEL) {
        int slot = (int)(key[tid] & 0xffffffffu);
        g_cmap[b * KSEL + tid] = slot;
        g_pidx[b * KSEL + tid] = g_pidx512[b * NC + slot];
    }
}

// ---------------- K7: compact via smem staging ----------------
__global__ void k_compact() {
    __shared__ __half st[2][8][NC];
    __shared__ int cm[KSEL];
    int blk = blockIdx.x;
    int b = blk / (SS / 8);
    int s8 = (blk % (SS / 8)) * 8;
    int tid = threadIdx.x;
    if (tid < KSEL) cm[tid] = g_cmap[b * KSEL + tid];
    const int4* src0 = (const int4*)(g_PC + ((size_t)(b * 2)     * SS + s8) * NC);
    const int4* src1 = (const int4*)(g_PC + ((size_t)(b * 2 + 1) * SS + s8) * NC);
    int4* d0 = (int4*)&st[0][0][0];
    int4* d1 = (int4*)&st[1][0][0];
    const int NI4 = 8 * NC / 8;
    for (int idx = tid; idx < NI4; idx += 256) {
        d0[idx] = src0[idx];
        d1[idx] = src1[idx];
    }
    __syncthreads();
    int j = tid;
    int c = cm[j];
    const size_t PLa = (size_t)SS * KSEL;
#pragma unroll
    for (int r = 0; r < 8; r++) {
        size_t dst = ((size_t)(b * 2) * SS + s8 + r) * KSEL + j;
        g_PA[dst]       = st[0][r][c];
        g_PA[dst + PLa] = st[1][r][c];
    }
}

// ---------------- K8: gather + transpose proj rows -> f16 single plane ----------------
__global__ void k_projsplit(const float* __restrict__ proj) {
    __shared__ float t[32][33];
    __shared__ int pj[32];
    int j0 = blockIdx.x * 32, d0 = blockIdx.y * 32, b = blockIdx.z;
    int tx = threadIdx.x, ty = threadIdx.y;
    if (ty == 0) pj[tx] = g_pidx[b * KSEL + j0 + tx];
    __syncthreads();
#pragma unroll
    for (int i = 0; i < 32; i += 8) {
        int p = pj[ty + i];
        t[ty + i][tx] = proj[(size_t)p * DM + d0 + tx];
    }
    __syncthreads();
#pragma unroll
    for (int i = 0; i < 32; i += 8) {
        float v = t[tx][ty + i];
        g_Pr[((size_t)b * DM + d0 + ty + i) * KSEL + j0 + tx] = __float2half(v);
    }
}

// ---------------- K9: final GEMM (f16 2-pass), 2 CTAs/SM ----------------
__global__ __launch_bounds__(256, 2)
void k_gemm3t(float* __restrict__ out) {
    extern __shared__ char smem[];
    const u32 sbase = smem_u32(smem);
    const int tid = threadIdx.x;
    const int wid = tid >> 5, lid = tid & 31;
    const int wm = wid & 3, wn = wid >> 2;
    const int b  = blockIdx.z;
    const int d0 = blockIdx.x * 128;
    const int s0 = blockIdx.y * 128;

    float acc[2][8][4];
#pragma unroll
    for (int i = 0; i < 2; i++)
#pragma unroll
        for (int j = 0; j < 8; j++)
#pragma unroll
            for (int r = 0; r < 4; r++) acc[i][j][r] = 0.0f;

    auto load_stage = [&](int ks, int buf) {
        const int k0 = ks * 32;
        u32 sg = sbase + buf * STG3;
#pragma unroll
        for (int i = 0; i < 4; i++) {
            int idx = tid + i * 256;
            int sp = idx >> 9, rem = idx & 511;
            int r = rem >> 2, c = rem & 3;
            const __half* g = g_PA + ((size_t)(b * 2 + sp) * SS + s0 + r) * KSEL + k0 + c * 8;
            cpasync16(sg + sp * PLANE + r * RPAD + c * 16, g);
        }
#pragma unroll
        for (int i = 0; i < 2; i++) {
            int idx = tid + i * 256;
            int r = idx >> 2, c = idx & 3;
            const __half* g = g_Pr + ((size_t)b * DM + d0 + r) * KSEL + k0 + c * 8;
            cpasync16(sg + 2 * PLANE + r * RPAD + c * 16, g);
        }
    };

    const u32 aoff = (u32)((wm * 32 + (lid & 15)) * RPAD + (lid >> 4) * 16);
    const u32 boff = (u32)((wn * 64 + (lid & 15)) * RPAD + (lid >> 4) * 16);

    load_stage(0, 0); CP_COMMIT();

#pragma unroll 1
    for (int ks = 0; ks < KSEL / 32; ks++) {
        int buf = ks & 1;
        if (ks < KSEL / 32 - 1) { load_stage(ks + 1, buf ^ 1); CP_COMMIT(); CP_WAIT(1); }
        else                    { CP_WAIT(0); }
        __syncthreads();
        u32 sA = sbase + buf * STG3;
        u32 sB = sA + 2 * PLANE;
#pragma unroll
        for (int kk = 0; kk < 2; kk++) {
            u32 ah[2][4], am[2][4];
#pragma unroll
            for (int mt = 0; mt < 2; mt++) {
                ldsm4(ah[mt], sA + aoff + mt * (16 * RPAD) + kk * 32);
                ldsm4(am[mt], sA + PLANE + aoff + mt * (16 * RPAD) + kk * 32);
            }
            u32 bh[4][4];
#pragma unroll
            for (int nt2 = 0; nt2 < 4; nt2++)
                ldsm4(bh[nt2], sB + boff + nt2 * (16 * RPAD) + kk * 32);
#pragma unroll
            for (int mt = 0; mt < 2; mt++)
#pragma unroll
                for (int nt2 = 0; nt2 < 4; nt2++) {
                    mma16816f(acc[mt][2 * nt2],     ah[mt], bh[nt2][0], bh[nt2][2]);
                    mma16816f(acc[mt][2 * nt2 + 1], ah[mt], bh[nt2][1], bh[nt2][3]);
                    mma16816f(acc[mt][2 * nt2],     am[mt], bh[nt2][0], bh[nt2][2]);
                    mma16816f(acc[mt][2 * nt2 + 1], am[mt], bh[nt2][1], bh[nt2][3]);
                }
        }
        __syncthreads();
    }
#pragma unroll
    for (int mt = 0; mt < 2; mt++)
#pragma unroll
        for (int nt = 0; nt < 8; nt++) {
            int row = s0 + wm * 32 + mt * 16 + (lid >> 2);
            int col = d0 + wn * 64 + nt * 8 + 2 * (lid & 3);
            float* po = out + ((size_t)b * SS + row) * DM + col;
            *(float2*)po            = make_float2(acc[mt][nt][0], acc[mt][nt][1]);
            *(float2*)(po + 8 * DM) = make_float2(acc[mt][nt][2], acc[mt][nt][3]);
        }
}

// ---------------- entry (multi-stream fork/join) ----------------
extern "C" void kernel_launch(void* const* d_in, const int* in_sizes, int n_in,
                              void* d_out, int out_size) {
    const float* act  = (const float*)d_in[0];
    const int*   sidx = (const int*)d_in[1];
    int o = (n_in >= 9 && in_sizes[2] == 1) ? 3 : 2;
    const float* cw   = (const float*)d_in[o + 0];
    const float* proj = (const float*)d_in[o + 1];
    const float* w1   = (const float*)d_in[o + 2];
    const float* b1   = (const float*)d_in[o + 3];
    const float* w2   = (const float*)d_in[o + 4];
    const float* b2   = (const float*)d_in[o + 5];
    float* out = (float*)d_out;

    static cudaStream_t s1 = nullptr;
    static cudaEvent_t ev0 = nullptr, evA = nullptr, ev1 = nullptr, ev2 = nullptr, ev3 = nullptr;
    if (s1 == nullptr) {
        cudaStreamCreateWithFlags(&s1, cudaStreamNonBlocking);
        cudaEventCreateWithFlags(&ev0, cudaEventDisableTiming);
        cudaEventCreateWithFlags(&evA, cudaEventDisableTiming);
        cudaEventCreateWithFlags(&ev1, cudaEventDisableTiming);
        cudaEventCreateWithFlags(&ev2, cudaEventDisableTiming);
        cudaEventCreateWithFlags(&ev3, cudaEventDisableTiming);
        cudaFuncSetAttribute(k_gemm1a, cudaFuncAttributeMaxDynamicSharedMemorySize, GSMEM1);
        cudaFuncSetAttribute(k_refine, cudaFuncAttributeMaxDynamicSharedMemorySize, GSMEM4);
        cudaFuncSetAttribute(k_gemm3t, cudaFuncAttributeMaxDynamicSharedMemorySize, GSMEM3);
        cudaFuncSetAttribute(k_hidden, cudaFuncAttributeMaxDynamicSharedMemorySize, BB * NIN * 4);
    }

    // fork: merged A split (+score init) + MLP chain on s1
    cudaEventRecord(ev0, 0);
    cudaStreamWaitEvent(s1, ev0, 0);
    k_splitA<<<(BB * SS * KIN / 4) / 256, 256, 0, s1>>>(act);
    cudaEventRecord(evA, s1);
    k_initMask<<<(BB * NIN + 255) / 256, 256, 0, s1>>>();
    k_scatter<<<(BB * KIN + 255) / 256, 256, 0, s1>>>(sidx);
    k_hidden<<<HID / 8, 256, BB * NIN * 4, s1>>>(w1, b1);
    k_relsig<<<NP / 32, 256, 0, s1>>>(w2, b2);
    cudaEventRecord(ev1, s1);

    // main chain
    k_gatherBh<<<NP, 256>>>(cw, sidx);
    cudaStreamWaitEvent(0, evA, 0);
    k_gemm1a<<<dim3(NP / 128, SS / 128, BB), 256, GSMEM1>>>();

    // join
    cudaStreamWaitEvent(0, ev1, 0);
    k_topkc<<<BB, 1024>>>();
    k_gatherBc<<<BB * NC, 256>>>(cw, sidx);
    k_refine<<<dim3(NC / 128, SS / 128, BB), 256, GSMEM4>>>();
    k_rescore<<<BB, NCP>>>();

    // fork: projsplit on s1, compact on main
    cudaEventRecord(ev2, 0);
    cudaStreamWaitEvent(s1, ev2, 0);
    k_projsplit<<<dim3(KSEL / 32, DM / 32, BB), dim3(32, 8), 0, s1>>>(proj);
    cudaEventRecord(ev3, s1);
    k_compact<<<BB * SS / 8, 256>>>();
    cudaStreamWaitEvent(0, ev3, 0);

    k_gemm3t<<<dim3(DM / 128, SS / 128, BB), 256, GSMEM3>>>(out);
}